// round 1
// baseline (speedup 1.0000x reference)
#include <cuda_runtime.h>

// ---------------------------------------------------------------------------
// SEMMBlock: spiking-router MoE transformer block, fp32 baseline.
// B=4 S=1024 D=512 E=8 F=2048 H=4 dh=128. All experts run densely.
// ---------------------------------------------------------------------------

#define B_  4
#define S_  1024
#define D_  512
#define E_  8
#define F_  2048
#define H_  4
#define DH_ 128
#define N_  (B_ * S_)          // 4096 tokens
#define LN_EPS 1e-5f

// ------------------------- scratch (device globals) ------------------------
__device__ float g_rw[N_ * E_];
__device__ float g_q[N_ * D_];
__device__ float g_k[N_ * D_];
__device__ float g_v[N_ * D_];
__device__ float g_att[(size_t)B_ * H_ * S_ * S_];   // 64 MB
__device__ float g_o[N_ * D_];
__device__ float g_tmp[N_ * D_];                     // o-proj out, then FFN2 out
__device__ float g_h[N_ * D_];
__device__ float g_f1[N_ * F_];                      // 32 MB

// ------------------------------- router -------------------------------------
// one warp per token: logits = x @ gate_w + gate_b; top-2; relu; scale&fire.
__global__ void router_kernel(const float* __restrict__ x,
                              const float* __restrict__ gw,
                              const float* __restrict__ gb,
                              float* __restrict__ logits,
                              float* __restrict__ rw)
{
    int warp = (blockIdx.x * blockDim.x + threadIdx.x) >> 5;
    int lane = threadIdx.x & 31;
    if (warp >= N_) return;
    const float* xr = x + (size_t)warp * D_;
    float acc[E_];
#pragma unroll
    for (int e = 0; e < E_; e++) acc[e] = 0.f;
    for (int i = lane; i < D_; i += 32) {
        float xv = xr[i];
        const float* g = gw + i * E_;
#pragma unroll
        for (int e = 0; e < E_; e++) acc[e] += xv * g[e];
    }
#pragma unroll
    for (int e = 0; e < E_; e++) {
#pragma unroll
        for (int o = 16; o > 0; o >>= 1)
            acc[e] += __shfl_down_sync(0xffffffffu, acc[e], o);
    }
    if (lane == 0) {
        float lg[E_];
#pragma unroll
        for (int e = 0; e < E_; e++) {
            lg[e] = acc[e] + gb[e];
            logits[warp * E_ + e] = lg[e];
        }
        int i1 = 0;
#pragma unroll
        for (int e = 1; e < E_; e++) if (lg[e] > lg[i1]) i1 = e;
        int i2 = -1;
#pragma unroll
        for (int e = 0; e < E_; e++) {
            if (e == i1) continue;
            if (i2 < 0 || lg[e] > lg[i2]) i2 = e;
        }
#pragma unroll
        for (int e = 0; e < E_; e++) {
            float r = 0.f;
            if (e == i1 || e == i2) {
                float mem = lg[e] > 0.f ? lg[e] : 0.f;
#pragma unroll
                for (int lvl = 0; lvl < 4; lvl++) {
                    float thr = 4.0f / (float)(1 << lvl);
                    if (mem >= thr) { r += thr; mem -= thr; }
                }
            }
            rw[warp * E_ + e] = r;
        }
    }
}

// ------------------------------- SGEMM --------------------------------------
// C = alpha*(A @ B) (+bias) (relu), 128x128x8 tiles, 256 threads, 8x8/thread.
// TRANSB=1: B is [N,K] row-major (C = A @ B^T).
// Batched via blockIdx.z with (outer, inner) stride decomposition z=(zo*nh+zi).
template <bool TRANSB, bool RELU>
__global__ __launch_bounds__(256) void sgemm_kernel(
    const float* __restrict__ A, const float* __restrict__ Bp,
    float* __restrict__ C, const float* __restrict__ bias,
    int K, int lda, int ldb, int ldc,
    int nh, long long sAo, long long sAi, long long sBo, long long sBi,
    long long sCo, long long sCi, float alpha)
{
    int z  = blockIdx.z;
    int zo = z / nh, zi = z - zo * nh;
    A  += zo * sAo + zi * sAi;
    Bp += zo * sBo + zi * sBi;
    C  += zo * sCo + zi * sCi;

    __shared__ __align__(16) float As[8][128];
    __shared__ __align__(16) float Bs[8][128];

    const int tid  = threadIdx.x;
    const int bm   = blockIdx.y * 128;
    const int bn   = blockIdx.x * 128;
    const int aRow = tid >> 1;
    const int aCol = (tid & 1) << 2;
    const int bRow = tid >> 5;
    const int bCol = (tid & 31) << 2;
    const int tx   = (tid & 15) << 3;
    const int ty   = (tid >> 4) << 3;

    float acc[8][8];
#pragma unroll
    for (int i = 0; i < 8; i++)
#pragma unroll
        for (int j = 0; j < 8; j++) acc[i][j] = 0.f;

    for (int k0 = 0; k0 < K; k0 += 8) {
        float4 a4 = *(const float4*)(A + (long long)(bm + aRow) * lda + (k0 + aCol));
        As[aCol + 0][aRow] = a4.x;
        As[aCol + 1][aRow] = a4.y;
        As[aCol + 2][aRow] = a4.z;
        As[aCol + 3][aRow] = a4.w;
        if (TRANSB) {
            float4 b4 = *(const float4*)(Bp + (long long)(bn + aRow) * ldb + (k0 + aCol));
            Bs[aCol + 0][aRow] = b4.x;
            Bs[aCol + 1][aRow] = b4.y;
            Bs[aCol + 2][aRow] = b4.z;
            Bs[aCol + 3][aRow] = b4.w;
        } else {
            float4 b4 = *(const float4*)(Bp + (long long)(k0 + bRow) * ldb + (bn + bCol));
            *(float4*)&Bs[bRow][bCol] = b4;
        }
        __syncthreads();
#pragma unroll
        for (int kk = 0; kk < 8; kk++) {
            float ar[8], br[8];
            *(float4*)(ar)     = *(const float4*)&As[kk][ty];
            *(float4*)(ar + 4) = *(const float4*)&As[kk][ty + 4];
            *(float4*)(br)     = *(const float4*)&Bs[kk][tx];
            *(float4*)(br + 4) = *(const float4*)&Bs[kk][tx + 4];
#pragma unroll
            for (int i = 0; i < 8; i++)
#pragma unroll
                for (int j = 0; j < 8; j++)
                    acc[i][j] += ar[i] * br[j];
        }
        __syncthreads();
    }

#pragma unroll
    for (int i = 0; i < 8; i++) {
        long long m = bm + ty + i;
        float4 o0, o1;
        float* oc[8] = {&o0.x, &o0.y, &o0.z, &o0.w, &o1.x, &o1.y, &o1.z, &o1.w};
#pragma unroll
        for (int j = 0; j < 8; j++) {
            float v2 = acc[i][j] * alpha;
            if (bias) v2 += bias[bn + tx + j];
            if (RELU) v2 = fmaxf(v2, 0.f);
            *oc[j] = v2;
        }
        *(float4*)(C + m * ldc + bn + tx)     = o0;
        *(float4*)(C + m * ldc + bn + tx + 4) = o1;
    }
}

// ------------------------------- softmax ------------------------------------
__global__ void softmax_kernel(float* __restrict__ att, int L)
{
    long long row = blockIdx.x;
    float* p = att + row * L;
    int t = threadIdx.x;
    __shared__ float red[256];
    float m = -1e30f;
    for (int i = t; i < L; i += 256) m = fmaxf(m, p[i]);
    red[t] = m; __syncthreads();
    for (int o = 128; o > 0; o >>= 1) { if (t < o) red[t] = fmaxf(red[t], red[t + o]); __syncthreads(); }
    m = red[0]; __syncthreads();
    float s = 0.f;
    for (int i = t; i < L; i += 256) {
        float ev = __expf(p[i] - m);
        p[i] = ev;
        s += ev;
    }
    red[t] = s; __syncthreads();
    for (int o = 128; o > 0; o >>= 1) { if (t < o) red[t] += red[t + o]; __syncthreads(); }
    float inv = 1.f / red[0];
    for (int i = t; i < L; i += 256) p[i] *= inv;
}

// --------------------------- LayerNorm kernels ------------------------------
// out = LN(a + b_in) * s + b  (128 threads per row, 4 elems/thread)
__global__ void ln_add_kernel(const float* __restrict__ a, const float* __restrict__ bsrc,
                              const float* __restrict__ s, const float* __restrict__ bias,
                              float* __restrict__ out)
{
    int row = blockIdx.x;
    int t = threadIdx.x;
    __shared__ float red[128];
    float v[4];
#pragma unroll
    for (int i = 0; i < 4; i++) {
        int d = t + i * 128;
        v[i] = a[(size_t)row * D_ + d] + bsrc[(size_t)row * D_ + d];
    }
    float sum = v[0] + v[1] + v[2] + v[3];
    red[t] = sum; __syncthreads();
    for (int o = 64; o > 0; o >>= 1) { if (t < o) red[t] += red[t + o]; __syncthreads(); }
    float mu = red[0] * (1.f / D_); __syncthreads();
    float sq = 0.f;
#pragma unroll
    for (int i = 0; i < 4; i++) { float d2 = v[i] - mu; sq += d2 * d2; }
    red[t] = sq; __syncthreads();
    for (int o = 64; o > 0; o >>= 1) { if (t < o) red[t] += red[t + o]; __syncthreads(); }
    float inv = rsqrtf(red[0] * (1.f / D_) + LN_EPS);
#pragma unroll
    for (int i = 0; i < 4; i++) {
        int d = t + i * 128;
        out[(size_t)row * D_ + d] = (v[i] - mu) * inv * s[d] + bias[d];
    }
}

// final += rw[row][e] * (LN(h + f2) * s + b)
__global__ void ln_add_acc_kernel(const float* __restrict__ h, const float* __restrict__ f2,
                                  const float* __restrict__ s, const float* __restrict__ bias,
                                  const float* __restrict__ rw, int e,
                                  float* __restrict__ finalOut)
{
    int row = blockIdx.x;
    int t = threadIdx.x;
    __shared__ float red[128];
    float v[4];
#pragma unroll
    for (int i = 0; i < 4; i++) {
        int d = t + i * 128;
        v[i] = h[(size_t)row * D_ + d] + f2[(size_t)row * D_ + d];
    }
    float sum = v[0] + v[1] + v[2] + v[3];
    red[t] = sum; __syncthreads();
    for (int o = 64; o > 0; o >>= 1) { if (t < o) red[t] += red[t + o]; __syncthreads(); }
    float mu = red[0] * (1.f / D_); __syncthreads();
    float sq = 0.f;
#pragma unroll
    for (int i = 0; i < 4; i++) { float d2 = v[i] - mu; sq += d2 * d2; }
    red[t] = sq; __syncthreads();
    for (int o = 64; o > 0; o >>= 1) { if (t < o) red[t] += red[t + o]; __syncthreads(); }
    float inv = rsqrtf(red[0] * (1.f / D_) + LN_EPS);
    float w = rw[row * E_ + e];
#pragma unroll
    for (int i = 0; i < 4; i++) {
        int d = t + i * 128;
        float y = (v[i] - mu) * inv * s[d] + bias[d];
        finalOut[(size_t)row * D_ + d] += w * y;
    }
}

// ------------------------------ host glue -----------------------------------
static void launch_gemm(bool transb, bool relu,
                        const float* A, const float* Bp, float* C, const float* bias,
                        int M, int N, int K, int lda, int ldb, int ldc,
                        int batches, int nh,
                        long long sAo, long long sAi, long long sBo, long long sBi,
                        long long sCo, long long sCi, float alpha)
{
    dim3 grid(N / 128, M / 128, batches);
    if (transb)
        sgemm_kernel<true, false><<<grid, 256>>>(A, Bp, C, bias, K, lda, ldb, ldc,
                                                 nh, sAo, sAi, sBo, sBi, sCo, sCi, alpha);
    else if (relu)
        sgemm_kernel<false, true><<<grid, 256>>>(A, Bp, C, bias, K, lda, ldb, ldc,
                                                 nh, sAo, sAi, sBo, sBi, sCo, sCi, alpha);
    else
        sgemm_kernel<false, false><<<grid, 256>>>(A, Bp, C, bias, K, lda, ldb, ldc,
                                                  nh, sAo, sAi, sBo, sBi, sCo, sCi, alpha);
}

extern "C" void kernel_launch(void* const* d_in, const int* in_sizes, int n_in,
                              void* d_out, int out_size)
{
    const float* x      = (const float*)d_in[0];
    const float* gate_w = (const float*)d_in[1];
    const float* gate_b = (const float*)d_in[2];
    const float* ln1_s  = (const float*)d_in[3];
    const float* ln1_b  = (const float*)d_in[4];
    const float* ln2_s  = (const float*)d_in[5];
    const float* ln2_b  = (const float*)d_in[6];
    const float* wq     = (const float*)d_in[7];
    const float* wk     = (const float*)d_in[8];
    const float* wv     = (const float*)d_in[9];
    const float* wo     = (const float*)d_in[10];
    const float* bq     = (const float*)d_in[11];
    const float* bk     = (const float*)d_in[12];
    const float* bv     = (const float*)d_in[13];
    const float* bo     = (const float*)d_in[14];
    const float* w1     = (const float*)d_in[15];
    const float* b1     = (const float*)d_in[16];
    const float* w2     = (const float*)d_in[17];
    const float* b2     = (const float*)d_in[18];

    float* out_final  = (float*)d_out;
    float* out_logits = out_final + (size_t)N_ * D_;

    float *q, *k, *v, *att, *o, *tmp, *h, *f1, *rw;
    cudaGetSymbolAddress((void**)&q,   g_q);
    cudaGetSymbolAddress((void**)&k,   g_k);
    cudaGetSymbolAddress((void**)&v,   g_v);
    cudaGetSymbolAddress((void**)&att, g_att);
    cudaGetSymbolAddress((void**)&o,   g_o);
    cudaGetSymbolAddress((void**)&tmp, g_tmp);
    cudaGetSymbolAddress((void**)&h,   g_h);
    cudaGetSymbolAddress((void**)&f1,  g_f1);
    cudaGetSymbolAddress((void**)&rw,  g_rw);

    cudaMemsetAsync(out_final, 0, (size_t)N_ * D_ * sizeof(float));

    router_kernel<<<N_ / 8, 256>>>(x, gate_w, gate_b, out_logits, rw);

    const float attn_scale = 0.08838834764831845f;  // 1/sqrt(128)
    const long long SD  = (long long)S_ * D_;
    const long long SS  = (long long)S_ * S_;

    for (int e = 0; e < E_; e++) {
        const float* Wq = wq + (long long)e * D_ * D_;
        const float* Wk = wk + (long long)e * D_ * D_;
        const float* Wv = wv + (long long)e * D_ * D_;
        const float* Wo = wo + (long long)e * D_ * D_;
        const float* W1 = w1 + (long long)e * D_ * F_;
        const float* W2 = w2 + (long long)e * F_ * D_;
        const float* Bq = bq + (long long)e * D_;
        const float* Bk = bk + (long long)e * D_;
        const float* Bv = bv + (long long)e * D_;
        const float* Bo = bo + (long long)e * D_;
        const float* B1 = b1 + (long long)e * F_;
        const float* B2 = b2 + (long long)e * D_;

        // QKV projections: [N_, D_] = x @ W + b
        launch_gemm(false, false, x, Wq, q, Bq, N_, D_, D_, D_, D_, D_,
                    1, 1, 0, 0, 0, 0, 0, 0, 1.f);
        launch_gemm(false, false, x, Wk, k, Bk, N_, D_, D_, D_, D_, D_,
                    1, 1, 0, 0, 0, 0, 0, 0, 1.f);
        launch_gemm(false, false, x, Wv, v, Bv, N_, D_, D_, D_, D_, D_,
                    1, 1, 0, 0, 0, 0, 0, 0, 1.f);

        // scores[b,h] = q[b,:,h,:] @ k[b,:,h,:]^T / sqrt(dh)   (batched NT)
        launch_gemm(true, false, q, k, att, nullptr, S_, S_, DH_, D_, D_, S_,
                    B_ * H_, H_,
                    SD, DH_,        // A: q offsets per (b, h)
                    SD, DH_,        // B: k offsets per (b, h)
                    (long long)H_ * SS, SS,  // C: att offsets
                    attn_scale);

        softmax_kernel<<<B_ * H_ * S_, 256>>>(att, S_);

        // o[b,:,h,:] = att[b,h] @ v[b,:,h,:]   (batched NN)
        launch_gemm(false, false, att, v, o, nullptr, S_, DH_, S_, S_, D_, D_,
                    B_ * H_, H_,
                    (long long)H_ * SS, SS,
                    SD, DH_,
                    SD, DH_,
                    1.f);

        // o projection
        launch_gemm(false, false, o, Wo, tmp, Bo, N_, D_, D_, D_, D_, D_,
                    1, 1, 0, 0, 0, 0, 0, 0, 1.f);

        // h = LN1(x + oproj)
        ln_add_kernel<<<N_, 128>>>(x, tmp, ln1_s + (long long)e * D_, ln1_b + (long long)e * D_, h);

        // FFN1: f1 = relu(h @ W1 + b1)
        launch_gemm(false, true, h, W1, f1, B1, N_, F_, D_, D_, F_, F_,
                    1, 1, 0, 0, 0, 0, 0, 0, 1.f);

        // FFN2: tmp = f1 @ W2 + b2
        launch_gemm(false, false, f1, W2, tmp, B2, N_, D_, F_, F_, D_, D_,
                    1, 1, 0, 0, 0, 0, 0, 0, 1.f);

        // final += rw_e * LN2(h + tmp)
        ln_add_acc_kernel<<<N_, 128>>>(h, tmp, ln2_s + (long long)e * D_, ln2_b + (long long)e * D_,
                                       rw, e, out_final);
    }
}

// round 2
// speedup vs baseline: 3.3966x; 3.3966x over previous
#include <cuda_runtime.h>

// ---------------------------------------------------------------------------
// SEMMBlock: spiking-router MoE transformer block.
// B=4 S=1024 D=512 E=8 F=2048 H=4 dh=128. All experts dense.
// Round 2: tf32 tensor-core GEMMs (mma.sync.m16n8k8), all-expert batching.
// ---------------------------------------------------------------------------

#define B_  4
#define S_  1024
#define D_  512
#define E_  8
#define F_  2048
#define H_  4
#define DH_ 128
#define N_  (B_ * S_)          // 4096 tokens
#define LN_EPS 1e-5f

#define DD_  (D_ * D_)
#define ND_  ((long long)N_ * D_)
#define SD_  ((long long)S_ * D_)
#define SS_  ((long long)S_ * S_)
#define NF_  ((long long)N_ * F_)

// ------------------------- scratch (device globals) ------------------------
__device__ float g_rw[N_ * E_];
__device__ float g_wqkv[E_ * 3 * DD_];             // packed [e][qkv][D][D]
__device__ float g_bqkv[E_ * 3 * D_];
__device__ float g_qkv[(size_t)E_ * 3 * N_ * D_];  // [e][qkv][n][d]  201MB
__device__ float g_att[(size_t)E_ * B_ * H_ * S_ * S_];  // 537MB
__device__ float g_o[(size_t)E_ * N_ * D_];
__device__ float g_t1[(size_t)E_ * N_ * D_];
__device__ float g_h[(size_t)E_ * N_ * D_];
__device__ float g_f1[(size_t)E_ * N_ * F_];       // 268MB
__device__ float g_f2[(size_t)E_ * N_ * D_];

// ------------------------------ helpers -------------------------------------
__device__ __forceinline__ float rna_tf32(float x) {
    float y;
    asm("cvt.rna.tf32.f32 %0, %1;" : "=f"(y) : "f"(x));
    return y;
}

// ------------------------------- router -------------------------------------
__global__ void router_kernel(const float* __restrict__ x,
                              const float* __restrict__ gw,
                              const float* __restrict__ gb,
                              float* __restrict__ logits,
                              float* __restrict__ rw)
{
    int warp = (blockIdx.x * blockDim.x + threadIdx.x) >> 5;
    int lane = threadIdx.x & 31;
    if (warp >= N_) return;
    const float* xr = x + (size_t)warp * D_;
    float acc[E_];
#pragma unroll
    for (int e = 0; e < E_; e++) acc[e] = 0.f;
    for (int i = lane; i < D_; i += 32) {
        float xv = xr[i];
        const float* g = gw + i * E_;
#pragma unroll
        for (int e = 0; e < E_; e++) acc[e] += xv * g[e];
    }
#pragma unroll
    for (int e = 0; e < E_; e++) {
#pragma unroll
        for (int o = 16; o > 0; o >>= 1)
            acc[e] += __shfl_down_sync(0xffffffffu, acc[e], o);
    }
    if (lane == 0) {
        float lg[E_];
#pragma unroll
        for (int e = 0; e < E_; e++) {
            lg[e] = acc[e] + gb[e];
            logits[warp * E_ + e] = lg[e];
        }
        int i1 = 0;
#pragma unroll
        for (int e = 1; e < E_; e++) if (lg[e] > lg[i1]) i1 = e;
        int i2 = -1;
#pragma unroll
        for (int e = 0; e < E_; e++) {
            if (e == i1) continue;
            if (i2 < 0 || lg[e] > lg[i2]) i2 = e;
        }
#pragma unroll
        for (int e = 0; e < E_; e++) {
            float r = 0.f;
            if (e == i1 || e == i2) {
                float mem = lg[e] > 0.f ? lg[e] : 0.f;
#pragma unroll
                for (int lvl = 0; lvl < 4; lvl++) {
                    float thr = 4.0f / (float)(1 << lvl);
                    if (mem >= thr) { r += thr; mem -= thr; }
                }
            }
            rw[warp * E_ + e] = r;
        }
    }
}

// ------------------------------ QKV pack ------------------------------------
__global__ void pack_qkv_kernel(const float* __restrict__ wq, const float* __restrict__ wk,
                                const float* __restrict__ wv,
                                const float* __restrict__ bq, const float* __restrict__ bk,
                                const float* __restrict__ bv)
{
    int idx = blockIdx.x * blockDim.x + threadIdx.x;
    const int totalW = E_ * 3 * DD_;
    if (idx < totalW) {
        int e = idx / (3 * DD_);
        int r = idx - e * 3 * DD_;
        int w = r / DD_;
        int o = r - w * DD_;
        const float* src = (w == 0) ? wq : (w == 1) ? wk : wv;
        g_wqkv[idx] = src[e * DD_ + o];
    }
    if (idx < E_ * 3 * D_) {
        int e = idx / (3 * D_);
        int r = idx - e * 3 * D_;
        int w = r / D_;
        int o = r - w * D_;
        const float* src = (w == 0) ? bq : (w == 1) ? bk : bv;
        g_bqkv[idx] = src[e * D_ + o];
    }
}

// --------------------------- tf32 tensor GEMM -------------------------------
// C = alpha * A @ B(^T) (+bias) (relu). BM=BN=128, BK=16. 256 threads, 8 warps
// of 64x32. mma.sync.m16n8k8.tf32. Batched z -> (z0, z1, z2) via div1/div2.
template <bool TRANSB, bool RELU>
__global__ __launch_bounds__(256) void tf32_gemm(
    const float* __restrict__ A, const float* __restrict__ Bp,
    float* __restrict__ C, const float* __restrict__ bias,
    int K, int lda, int ldb, int ldc,
    int div1, int div2,
    long long sA0, long long sA1, long long sA2,
    long long sB0, long long sB1, long long sB2,
    long long sC0, long long sC1, long long sC2,
    long long sb0, long long sb1,
    float alpha)
{
    int z = blockIdx.z;
    int z0 = z / div1; int r = z - z0 * div1;
    int z1 = r / div2; int z2 = r - z1 * div2;
    A  += z0 * sA0 + z1 * sA1 + z2 * sA2;
    Bp += z0 * sB0 + z1 * sB1 + z2 * sB2;
    C  += z0 * sC0 + z1 * sC1 + z2 * sC2;
    const float* biasp = bias ? (bias + z0 * sb0 + z1 * sb1) : nullptr;

    __shared__ float As[16][136];   // [k][m]: bank = 8k+m (conflict-free reads)
    __shared__ float Bs[16][136];   // [k][n]

    const int tid  = threadIdx.x;
    const int lane = tid & 31;
    const int wid  = tid >> 5;
    const int warpM = (wid >> 2) * 64;
    const int warpN = (wid & 3) * 32;
    const int bm = blockIdx.y * 128;
    const int bn = blockIdx.x * 128;

    // staging indices
    const int arow = tid >> 2;           // 0..63
    const int akc  = (tid & 3) << 2;     // 0,4,8,12
    const int bk_  = tid >> 5;           // 0..7 (NN)
    const int bnc  = (tid & 31) << 2;    // 0..124 (NN)

    float acc[4][4][4];
#pragma unroll
    for (int i = 0; i < 4; i++)
#pragma unroll
        for (int j = 0; j < 4; j++)
#pragma unroll
            for (int q = 0; q < 4; q++) acc[i][j][q] = 0.f;

    for (int k0 = 0; k0 < K; k0 += 16) {
        // global -> regs
        float4 va0 = *(const float4*)(A + (long long)(bm + arow) * lda + (k0 + akc));
        float4 va1 = *(const float4*)(A + (long long)(bm + arow + 64) * lda + (k0 + akc));
        float4 vb0, vb1;
        if (TRANSB) {
            vb0 = *(const float4*)(Bp + (long long)(bn + arow) * ldb + (k0 + akc));
            vb1 = *(const float4*)(Bp + (long long)(bn + arow + 64) * ldb + (k0 + akc));
        } else {
            vb0 = *(const float4*)(Bp + (long long)(k0 + bk_) * ldb + (bn + bnc));
            vb1 = *(const float4*)(Bp + (long long)(k0 + bk_ + 8) * ldb + (bn + bnc));
        }
        __syncthreads();
        // regs -> smem with round-to-nearest tf32
        As[akc + 0][arow] = rna_tf32(va0.x);
        As[akc + 1][arow] = rna_tf32(va0.y);
        As[akc + 2][arow] = rna_tf32(va0.z);
        As[akc + 3][arow] = rna_tf32(va0.w);
        As[akc + 0][arow + 64] = rna_tf32(va1.x);
        As[akc + 1][arow + 64] = rna_tf32(va1.y);
        As[akc + 2][arow + 64] = rna_tf32(va1.z);
        As[akc + 3][arow + 64] = rna_tf32(va1.w);
        if (TRANSB) {
            Bs[akc + 0][arow] = rna_tf32(vb0.x);
            Bs[akc + 1][arow] = rna_tf32(vb0.y);
            Bs[akc + 2][arow] = rna_tf32(vb0.z);
            Bs[akc + 3][arow] = rna_tf32(vb0.w);
            Bs[akc + 0][arow + 64] = rna_tf32(vb1.x);
            Bs[akc + 1][arow + 64] = rna_tf32(vb1.y);
            Bs[akc + 2][arow + 64] = rna_tf32(vb1.z);
            Bs[akc + 3][arow + 64] = rna_tf32(vb1.w);
        } else {
            float4 c0 = make_float4(rna_tf32(vb0.x), rna_tf32(vb0.y), rna_tf32(vb0.z), rna_tf32(vb0.w));
            float4 c1 = make_float4(rna_tf32(vb1.x), rna_tf32(vb1.y), rna_tf32(vb1.z), rna_tf32(vb1.w));
            *(float4*)&Bs[bk_][bnc]     = c0;
            *(float4*)&Bs[bk_ + 8][bnc] = c1;
        }
        __syncthreads();

#pragma unroll
        for (int ks = 0; ks < 2; ks++) {
            const int kb = ks * 8;
            unsigned af[4][4], bf[4][2];
            const int krow = kb + (lane & 3);
            const int mrow = warpM + (lane >> 2);
            const int ncol = warpN + (lane >> 2);
#pragma unroll
            for (int mi = 0; mi < 4; mi++) {
                int m = mrow + mi * 16;
                af[mi][0] = __float_as_uint(As[krow][m]);
                af[mi][1] = __float_as_uint(As[krow][m + 8]);
                af[mi][2] = __float_as_uint(As[krow + 4][m]);
                af[mi][3] = __float_as_uint(As[krow + 4][m + 8]);
            }
#pragma unroll
            for (int ni = 0; ni < 4; ni++) {
                int n = ncol + ni * 8;
                bf[ni][0] = __float_as_uint(Bs[krow][n]);
                bf[ni][1] = __float_as_uint(Bs[krow + 4][n]);
            }
#pragma unroll
            for (int mi = 0; mi < 4; mi++)
#pragma unroll
                for (int ni = 0; ni < 4; ni++) {
                    asm volatile(
                        "mma.sync.aligned.m16n8k8.row.col.f32.tf32.tf32.f32 "
                        "{%0,%1,%2,%3}, {%4,%5,%6,%7}, {%8,%9}, {%0,%1,%2,%3};\n"
                        : "+f"(acc[mi][ni][0]), "+f"(acc[mi][ni][1]),
                          "+f"(acc[mi][ni][2]), "+f"(acc[mi][ni][3])
                        : "r"(af[mi][0]), "r"(af[mi][1]), "r"(af[mi][2]), "r"(af[mi][3]),
                          "r"(bf[ni][0]), "r"(bf[ni][1]));
                }
        }
    }

    // epilogue
#pragma unroll
    for (int mi = 0; mi < 4; mi++) {
        int row0 = bm + warpM + mi * 16 + (lane >> 2);
#pragma unroll
        for (int ni = 0; ni < 4; ni++) {
            int col = bn + warpN + ni * 8 + ((lane & 3) << 1);
            float b0 = 0.f, b1 = 0.f;
            if (biasp) { b0 = biasp[col]; b1 = biasp[col + 1]; }
            float2 v0, v1;
            v0.x = acc[mi][ni][0] * alpha + b0;
            v0.y = acc[mi][ni][1] * alpha + b1;
            v1.x = acc[mi][ni][2] * alpha + b0;
            v1.y = acc[mi][ni][3] * alpha + b1;
            if (RELU) {
                v0.x = fmaxf(v0.x, 0.f); v0.y = fmaxf(v0.y, 0.f);
                v1.x = fmaxf(v1.x, 0.f); v1.y = fmaxf(v1.y, 0.f);
            }
            *(float2*)(C + (long long)row0 * ldc + col)      = v0;
            *(float2*)(C + (long long)(row0 + 8) * ldc + col) = v1;
        }
    }
}

// ------------------------------- softmax ------------------------------------
__global__ void softmax_kernel(float* __restrict__ att, int L)
{
    long long row = blockIdx.x;
    float* p = att + row * L;
    int t = threadIdx.x;
    __shared__ float red[256];
    float m = -1e30f;
    for (int i = t; i < L; i += 256) m = fmaxf(m, p[i]);
    red[t] = m; __syncthreads();
    for (int o = 128; o > 0; o >>= 1) { if (t < o) red[t] = fmaxf(red[t], red[t + o]); __syncthreads(); }
    m = red[0]; __syncthreads();
    float s = 0.f;
    for (int i = t; i < L; i += 256) {
        float ev = __expf(p[i] - m);
        p[i] = ev;
        s += ev;
    }
    red[t] = s; __syncthreads();
    for (int o = 128; o > 0; o >>= 1) { if (t < o) red[t] += red[t + o]; __syncthreads(); }
    float inv = 1.f / red[0];
    for (int i = t; i < L; i += 256) p[i] *= inv;
}

// --------------------------- LayerNorm kernels ------------------------------
// h[e] = LN(x + t1[e]) * s[e] + b[e];  grid = E*N rows
__global__ void ln1_kernel(const float* __restrict__ x, const float* __restrict__ t1,
                           const float* __restrict__ s_all, const float* __restrict__ b_all,
                           float* __restrict__ h)
{
    int row = blockIdx.x;
    int e = row >> 12;       // / N_
    int n = row & (N_ - 1);
    const float* a    = x  + (size_t)n * D_;
    const float* bsrc = t1 + ((size_t)e * N_ + n) * D_;
    const float* s    = s_all + (size_t)e * D_;
    const float* bb   = b_all + (size_t)e * D_;
    float* out        = h + ((size_t)e * N_ + n) * D_;
    int t = threadIdx.x;
    __shared__ float red[128];
    float v[4];
#pragma unroll
    for (int i = 0; i < 4; i++) {
        int d = t + i * 128;
        v[i] = a[d] + bsrc[d];
    }
    float sum = v[0] + v[1] + v[2] + v[3];
    red[t] = sum; __syncthreads();
    for (int o = 64; o > 0; o >>= 1) { if (t < o) red[t] += red[t + o]; __syncthreads(); }
    float mu = red[0] * (1.f / D_); __syncthreads();
    float sq = 0.f;
#pragma unroll
    for (int i = 0; i < 4; i++) { float d2 = v[i] - mu; sq += d2 * d2; }
    red[t] = sq; __syncthreads();
    for (int o = 64; o > 0; o >>= 1) { if (t < o) red[t] += red[t + o]; __syncthreads(); }
    float inv = rsqrtf(red[0] * (1.f / D_) + LN_EPS);
#pragma unroll
    for (int i = 0; i < 4; i++) {
        int d = t + i * 128;
        out[d] = (v[i] - mu) * inv * s[d] + bb[d];
    }
}

// final[n] = sum_e rw[n][e] * (LN(h[e][n] + f2[e][n]) * s2[e] + b2[e])
__global__ void ln2_acc_kernel(const float* __restrict__ h, const float* __restrict__ f2,
                               const float* __restrict__ s_all, const float* __restrict__ b_all,
                               const float* __restrict__ rw,
                               float* __restrict__ finalOut)
{
    int n = blockIdx.x;
    int t = threadIdx.x;
    __shared__ float red[128];
    float outv[4] = {0.f, 0.f, 0.f, 0.f};
    for (int e = 0; e < E_; e++) {
        float w = rw[n * E_ + e];
        if (w == 0.f) continue;            // block-uniform
        const float* hp = h  + ((size_t)e * N_ + n) * D_;
        const float* fp = f2 + ((size_t)e * N_ + n) * D_;
        const float* s  = s_all + (size_t)e * D_;
        const float* bb = b_all + (size_t)e * D_;
        float v[4];
#pragma unroll
        for (int i = 0; i < 4; i++) {
            int d = t + i * 128;
            v[i] = hp[d] + fp[d];
        }
        float sum = v[0] + v[1] + v[2] + v[3];
        __syncthreads();
        red[t] = sum; __syncthreads();
        for (int o = 64; o > 0; o >>= 1) { if (t < o) red[t] += red[t + o]; __syncthreads(); }
        float mu = red[0] * (1.f / D_); __syncthreads();
        float sq = 0.f;
#pragma unroll
        for (int i = 0; i < 4; i++) { float d2 = v[i] - mu; sq += d2 * d2; }
        red[t] = sq; __syncthreads();
        for (int o = 64; o > 0; o >>= 1) { if (t < o) red[t] += red[t + o]; __syncthreads(); }
        float inv = rsqrtf(red[0] * (1.f / D_) + LN_EPS);
#pragma unroll
        for (int i = 0; i < 4; i++) {
            int d = t + i * 128;
            outv[i] += w * ((v[i] - mu) * inv * s[d] + bb[d]);
        }
    }
#pragma unroll
    for (int i = 0; i < 4; i++)
        finalOut[(size_t)n * D_ + t + i * 128] = outv[i];
}

// ------------------------------ host glue -----------------------------------
extern "C" void kernel_launch(void* const* d_in, const int* in_sizes, int n_in,
                              void* d_out, int out_size)
{
    const float* x      = (const float*)d_in[0];
    const float* gate_w = (const float*)d_in[1];
    const float* gate_b = (const float*)d_in[2];
    const float* ln1_s  = (const float*)d_in[3];
    const float* ln1_b  = (const float*)d_in[4];
    const float* ln2_s  = (const float*)d_in[5];
    const float* ln2_b  = (const float*)d_in[6];
    const float* wq     = (const float*)d_in[7];
    const float* wk     = (const float*)d_in[8];
    const float* wv     = (const float*)d_in[9];
    const float* wo     = (const float*)d_in[10];
    const float* bq     = (const float*)d_in[11];
    const float* bk     = (const float*)d_in[12];
    const float* bv     = (const float*)d_in[13];
    const float* bo     = (const float*)d_in[14];
    const float* w1     = (const float*)d_in[15];
    const float* b1     = (const float*)d_in[16];
    const float* w2     = (const float*)d_in[17];
    const float* b2     = (const float*)d_in[18];

    float* out_final  = (float*)d_out;
    float* out_logits = out_final + (size_t)N_ * D_;

    float *qkv, *att, *o, *t1, *h, *f1, *f2, *rw, *wqkvP, *bqkvP;
    cudaGetSymbolAddress((void**)&qkv,   g_qkv);
    cudaGetSymbolAddress((void**)&att,   g_att);
    cudaGetSymbolAddress((void**)&o,     g_o);
    cudaGetSymbolAddress((void**)&t1,    g_t1);
    cudaGetSymbolAddress((void**)&h,     g_h);
    cudaGetSymbolAddress((void**)&f1,    g_f1);
    cudaGetSymbolAddress((void**)&f2,    g_f2);
    cudaGetSymbolAddress((void**)&rw,    g_rw);
    cudaGetSymbolAddress((void**)&wqkvP, g_wqkv);
    cudaGetSymbolAddress((void**)&bqkvP, g_bqkv);

    // pack QKV weights+biases
    {
        int total = E_ * 3 * DD_;
        pack_qkv_kernel<<<(total + 255) / 256, 256>>>(wq, wk, wv, bq, bk, bv);
    }

    router_kernel<<<N_ / 8, 256>>>(x, gate_w, gate_b, out_logits, rw);

    const float attn_scale = 0.08838834764831845f;  // 1/sqrt(128)

    // QKV: all experts, z = e*3 + w  (24 batches)
    {
        dim3 grid(D_ / 128, N_ / 128, E_ * 3);
        tf32_gemm<false, false><<<grid, 256>>>(
            x, wqkvP, qkv, bqkvP,
            D_, D_, D_, D_,
            3, 1,
            0, 0, 0,
            3LL * DD_, DD_, 0,
            3LL * ND_, ND_, 0,
            3LL * D_, D_,
            1.f);
    }

    // QK^T: z = e*16 + b*4 + h  (128 batches), NT
    {
        dim3 grid(S_ / 128, S_ / 128, E_ * B_ * H_);
        tf32_gemm<true, false><<<grid, 256>>>(
            qkv /*q*/, qkv + ND_ /*k*/, att, nullptr,
            DH_, D_, D_, S_,
            B_ * H_, H_,
            3LL * ND_, SD_, DH_,
            3LL * ND_, SD_, DH_,
            (long long)B_ * H_ * SS_, (long long)H_ * SS_, SS_,
            0, 0,
            attn_scale);
    }

    softmax_kernel<<<E_ * B_ * H_ * S_, 256>>>(att, S_);

    // att @ V: z = e*16 + b*4 + h, NN
    {
        dim3 grid(DH_ / 128, S_ / 128, E_ * B_ * H_);
        tf32_gemm<false, false><<<grid, 256>>>(
            att, qkv + 2 * ND_ /*v*/, o, nullptr,
            S_, S_, D_, D_,
            B_ * H_, H_,
            (long long)B_ * H_ * SS_, (long long)H_ * SS_, SS_,
            3LL * ND_, SD_, DH_,
            ND_, SD_, DH_,
            0, 0,
            1.f);
    }

    // O projection: z = e
    {
        dim3 grid(D_ / 128, N_ / 128, E_);
        tf32_gemm<false, false><<<grid, 256>>>(
            o, wo, t1, bo,
            D_, D_, D_, D_,
            1, 1,
            ND_, 0, 0,
            (long long)DD_, 0, 0,
            ND_, 0, 0,
            D_, 0,
            1.f);
    }

    // LN1: h[e] = LN(x + t1[e])
    ln1_kernel<<<E_ * N_, 128>>>(x, t1, ln1_s, ln1_b, h);

    // FFN1: f1 = relu(h @ w1 + b1), z = e
    {
        dim3 grid(F_ / 128, N_ / 128, E_);
        tf32_gemm<false, true><<<grid, 256>>>(
            h, w1, f1, b1,
            D_, D_, F_, F_,
            1, 1,
            ND_, 0, 0,
            (long long)D_ * F_, 0, 0,
            NF_, 0, 0,
            F_, 0,
            1.f);
    }

    // FFN2: f2 = f1 @ w2 + b2, z = e
    {
        dim3 grid(D_ / 128, N_ / 128, E_);
        tf32_gemm<false, false><<<grid, 256>>>(
            f1, w2, f2, b2,
            F_, F_, D_, D_,
            1, 1,
            NF_, 0, 0,
            (long long)F_ * D_, 0, 0,
            ND_, 0, 0,
            D_, 0,
            1.f);
    }

    // final = sum_e rw_e * LN2(h[e] + f2[e])
    ln2_acc_kernel<<<N_, 128>>>(h, f2, ln2_s, ln2_b, rw, out_final);
}

// round 3
// speedup vs baseline: 4.0151x; 1.1821x over previous
#include <cuda_runtime.h>
#include <cstdint>

// ---------------------------------------------------------------------------
// SEMMBlock: spiking-router MoE transformer block.
// B=4 S=1024 D=512 E=8 F=2048 H=4 dh=128. All experts dense.
// Round 3: cp.async double-buffered tf32 GEMM, 1-pass softmax.
// ---------------------------------------------------------------------------

#define B_  4
#define S_  1024
#define D_  512
#define E_  8
#define F_  2048
#define H_  4
#define DH_ 128
#define N_  (B_ * S_)          // 4096 tokens
#define LN_EPS 1e-5f

#define DD_  (D_ * D_)
#define ND_  ((long long)N_ * D_)
#define SD_  ((long long)S_ * D_)
#define SS_  ((long long)S_ * S_)
#define NF_  ((long long)N_ * F_)

// ------------------------- scratch (device globals) ------------------------
__device__ float g_rw[N_ * E_];
__device__ float g_wqkv[E_ * 3 * DD_];             // packed [e][qkv][D][D]
__device__ float g_bqkv[E_ * 3 * D_];
__device__ float g_qkv[(size_t)E_ * 3 * N_ * D_];
__device__ float g_att[(size_t)E_ * B_ * H_ * S_ * S_];  // 537MB
__device__ float g_o[(size_t)E_ * N_ * D_];
__device__ float g_t1[(size_t)E_ * N_ * D_];
__device__ float g_h[(size_t)E_ * N_ * D_];
__device__ float g_f1[(size_t)E_ * N_ * F_];
__device__ float g_f2[(size_t)E_ * N_ * D_];

// ------------------------------ helpers -------------------------------------
__device__ __forceinline__ void cp_async16(uint32_t smem, const void* gptr) {
    asm volatile("cp.async.cg.shared.global [%0], [%1], 16;\n" :: "r"(smem), "l"(gptr));
}
__device__ __forceinline__ void cp_commit() {
    asm volatile("cp.async.commit_group;\n");
}
__device__ __forceinline__ void cp_wait0() {
    asm volatile("cp.async.wait_group 0;\n");
}

// ------------------------------- router -------------------------------------
__global__ void router_kernel(const float* __restrict__ x,
                              const float* __restrict__ gw,
                              const float* __restrict__ gb,
                              float* __restrict__ logits,
                              float* __restrict__ rw)
{
    int warp = (blockIdx.x * blockDim.x + threadIdx.x) >> 5;
    int lane = threadIdx.x & 31;
    if (warp >= N_) return;
    const float* xr = x + (size_t)warp * D_;
    float acc[E_];
#pragma unroll
    for (int e = 0; e < E_; e++) acc[e] = 0.f;
    for (int i = lane; i < D_; i += 32) {
        float xv = xr[i];
        const float* g = gw + i * E_;
#pragma unroll
        for (int e = 0; e < E_; e++) acc[e] += xv * g[e];
    }
#pragma unroll
    for (int e = 0; e < E_; e++) {
#pragma unroll
        for (int o = 16; o > 0; o >>= 1)
            acc[e] += __shfl_down_sync(0xffffffffu, acc[e], o);
    }
    if (lane == 0) {
        float lg[E_];
#pragma unroll
        for (int e = 0; e < E_; e++) {
            lg[e] = acc[e] + gb[e];
            logits[warp * E_ + e] = lg[e];
        }
        int i1 = 0;
#pragma unroll
        for (int e = 1; e < E_; e++) if (lg[e] > lg[i1]) i1 = e;
        int i2 = -1;
#pragma unroll
        for (int e = 0; e < E_; e++) {
            if (e == i1) continue;
            if (i2 < 0 || lg[e] > lg[i2]) i2 = e;
        }
#pragma unroll
        for (int e = 0; e < E_; e++) {
            float r = 0.f;
            if (e == i1 || e == i2) {
                float mem = lg[e] > 0.f ? lg[e] : 0.f;
#pragma unroll
                for (int lvl = 0; lvl < 4; lvl++) {
                    float thr = 4.0f / (float)(1 << lvl);
                    if (mem >= thr) { r += thr; mem -= thr; }
                }
            }
            rw[warp * E_ + e] = r;
        }
    }
}

// ------------------------------ QKV pack ------------------------------------
__global__ void pack_qkv_kernel(const float* __restrict__ wq, const float* __restrict__ wk,
                                const float* __restrict__ wv,
                                const float* __restrict__ bq, const float* __restrict__ bk,
                                const float* __restrict__ bv)
{
    int idx = blockIdx.x * blockDim.x + threadIdx.x;
    const int totalW = E_ * 3 * DD_;
    if (idx < totalW) {
        int e = idx / (3 * DD_);
        int r = idx - e * 3 * DD_;
        int w = r / DD_;
        int o = r - w * DD_;
        const float* src = (w == 0) ? wq : (w == 1) ? wk : wv;
        g_wqkv[idx] = src[e * DD_ + o];
    }
    if (idx < E_ * 3 * D_) {
        int e = idx / (3 * D_);
        int r = idx - e * 3 * D_;
        int w = r / D_;
        int o = r - w * D_;
        const float* src = (w == 0) ? bq : (w == 1) ? bk : bv;
        g_bqkv[idx] = src[e * D_ + o];
    }
}

// --------------------------- tf32 tensor GEMM -------------------------------
// C = alpha * A @ B(^T) (+bias) (relu). BM=BN=128, BK=16, 256 thr, 8 warps of
// 64x32. cp.async double-buffered. mma.sync.m16n8k8.tf32 (HW truncation to
// tf32 -- error budget allows). Batched z -> (z0,z1,z2) via div1/div2.
#define ASTRIDE 20     // floats per A/B-NT smem row (conflict-free, 16B-aligned)
#define BSTRIDE 136    // floats per B-NN smem row

template <bool TRANSB, bool RELU>
__global__ __launch_bounds__(256, 2) void tf32_gemm(
    const float* __restrict__ A, const float* __restrict__ Bp,
    float* __restrict__ C, const float* __restrict__ bias,
    int K, int lda, int ldb, int ldc,
    int div1, int div2,
    long long sA0, long long sA1, long long sA2,
    long long sB0, long long sB1, long long sB2,
    long long sC0, long long sC1, long long sC2,
    long long sb0, long long sb1,
    float alpha)
{
    int z = blockIdx.z;
    int z0 = z / div1; int r = z - z0 * div1;
    int z1 = r / div2; int z2 = r - z1 * div2;
    A  += z0 * sA0 + z1 * sA1 + z2 * sA2;
    Bp += z0 * sB0 + z1 * sB1 + z2 * sB2;
    C  += z0 * sC0 + z1 * sC1 + z2 * sC2;
    const float* biasp = bias ? (bias + z0 * sb0 + z1 * sb1) : nullptr;

    __shared__ float As[2][128 * ASTRIDE];
    __shared__ float Bs[2][TRANSB ? 128 * ASTRIDE : 16 * BSTRIDE];

    const int tid  = threadIdx.x;
    const int lane = tid & 31;
    const int wid  = tid >> 5;
    const int warpM = (wid >> 2) * 64;
    const int warpN = (wid & 3) * 32;
    const int bm = blockIdx.y * 128;
    const int bn = blockIdx.x * 128;

    // staging indices
    const int srow = tid >> 1;            // 0..127
    const int sch  = (tid & 1) << 2;      // 0 or 4 (k offset; +8 for 2nd op)
    const int bkr  = tid >> 5;            // 0..7 (NN)
    const int bn4  = (tid & 31) << 2;     // 0..124 (NN)

    const float* gA = A + (long long)(bm + srow) * lda + sch;
    uint32_t sA = (uint32_t)__cvta_generic_to_shared(&As[0][srow * ASTRIDE + sch]);
    const float* gB;
    uint32_t sB;
    if (TRANSB) {
        gB = Bp + (long long)(bn + srow) * ldb + sch;
        sB = (uint32_t)__cvta_generic_to_shared(&Bs[0][srow * ASTRIDE + sch]);
    } else {
        gB = Bp + (long long)bkr * ldb + bn + bn4;
        sB = (uint32_t)__cvta_generic_to_shared(&Bs[0][bkr * BSTRIDE + bn4]);
    }
    const uint32_t stageA = sizeof(float) * 128 * ASTRIDE;
    const uint32_t stageB = TRANSB ? sizeof(float) * 128 * ASTRIDE
                                   : sizeof(float) * 16 * BSTRIDE;

    float acc[4][4][4];
#pragma unroll
    for (int i = 0; i < 4; i++)
#pragma unroll
        for (int j = 0; j < 4; j++)
#pragma unroll
            for (int q = 0; q < 4; q++) acc[i][j][q] = 0.f;

    // ---- prologue: prefetch k0 = 0 into stage 0 ----
    cp_async16(sA,          gA);
    cp_async16(sA + 32,     gA + 8);
    if (TRANSB) {
        cp_async16(sB,      gB);
        cp_async16(sB + 32, gB + 8);
    } else {
        cp_async16(sB,                      gB);
        cp_async16(sB + 8 * BSTRIDE * 4,    gB + (long long)8 * ldb);
    }
    cp_commit();

    int stage = 0;
    const int mrow = warpM + (lane >> 2);
    const int ncol = warpN + (lane >> 2);

    for (int k0 = 0; k0 < K; k0 += 16) {
        cp_wait0();
        __syncthreads();

        if (k0 + 16 < K) {
            int st = stage ^ 1;
            const float* gA2 = gA + k0 + 16;
            uint32_t sA2 = sA + st * stageA;
            cp_async16(sA2,      gA2);
            cp_async16(sA2 + 32, gA2 + 8);
            uint32_t sB2 = sB + st * stageB;
            if (TRANSB) {
                const float* gB2 = gB + k0 + 16;
                cp_async16(sB2,      gB2);
                cp_async16(sB2 + 32, gB2 + 8);
            } else {
                const float* gB2 = gB + (long long)(k0 + 16) * ldb;
                cp_async16(sB2,                   gB2);
                cp_async16(sB2 + 8 * BSTRIDE * 4, gB2 + (long long)8 * ldb);
            }
            cp_commit();
        }

        const float* As0 = &As[stage][0];
        const float* Bs0 = &Bs[stage][0];

#pragma unroll
        for (int ks = 0; ks < 2; ks++) {
            const int krow = ks * 8 + (lane & 3);
            unsigned af[4][4], bf[4][2];
#pragma unroll
            for (int mi = 0; mi < 4; mi++) {
                const float* pa = As0 + (mrow + mi * 16) * ASTRIDE + krow;
                af[mi][0] = __float_as_uint(pa[0]);
                af[mi][1] = __float_as_uint(pa[8 * ASTRIDE]);
                af[mi][2] = __float_as_uint(pa[4]);
                af[mi][3] = __float_as_uint(pa[8 * ASTRIDE + 4]);
            }
#pragma unroll
            for (int ni = 0; ni < 4; ni++) {
                if (TRANSB) {
                    const float* pb = Bs0 + (ncol + ni * 8) * ASTRIDE + krow;
                    bf[ni][0] = __float_as_uint(pb[0]);
                    bf[ni][1] = __float_as_uint(pb[4]);
                } else {
                    const float* pb = Bs0 + krow * BSTRIDE + ncol + ni * 8;
                    bf[ni][0] = __float_as_uint(pb[0]);
                    bf[ni][1] = __float_as_uint(pb[4 * BSTRIDE]);
                }
            }
#pragma unroll
            for (int mi = 0; mi < 4; mi++)
#pragma unroll
                for (int ni = 0; ni < 4; ni++) {
                    asm volatile(
                        "mma.sync.aligned.m16n8k8.row.col.f32.tf32.tf32.f32 "
                        "{%0,%1,%2,%3}, {%4,%5,%6,%7}, {%8,%9}, {%0,%1,%2,%3};\n"
                        : "+f"(acc[mi][ni][0]), "+f"(acc[mi][ni][1]),
                          "+f"(acc[mi][ni][2]), "+f"(acc[mi][ni][3])
                        : "r"(af[mi][0]), "r"(af[mi][1]), "r"(af[mi][2]), "r"(af[mi][3]),
                          "r"(bf[ni][0]), "r"(bf[ni][1]));
                }
        }
        stage ^= 1;
    }

    // epilogue
#pragma unroll
    for (int mi = 0; mi < 4; mi++) {
        int row0 = bm + warpM + mi * 16 + (lane >> 2);
#pragma unroll
        for (int ni = 0; ni < 4; ni++) {
            int col = bn + warpN + ni * 8 + ((lane & 3) << 1);
            float b0 = 0.f, b1 = 0.f;
            if (biasp) { b0 = biasp[col]; b1 = biasp[col + 1]; }
            float2 v0, v1;
            v0.x = acc[mi][ni][0] * alpha + b0;
            v0.y = acc[mi][ni][1] * alpha + b1;
            v1.x = acc[mi][ni][2] * alpha + b0;
            v1.y = acc[mi][ni][3] * alpha + b1;
            if (RELU) {
                v0.x = fmaxf(v0.x, 0.f); v0.y = fmaxf(v0.y, 0.f);
                v1.x = fmaxf(v1.x, 0.f); v1.y = fmaxf(v1.y, 0.f);
            }
            *(float2*)(C + (long long)row0 * ldc + col)       = v0;
            *(float2*)(C + (long long)(row0 + 8) * ldc + col) = v1;
        }
    }
}

// ------------------------------- softmax ------------------------------------
// one row of 1024 per block, 256 threads, registers only (1 read + 1 write)
__global__ __launch_bounds__(256) void softmax_kernel(float* __restrict__ att)
{
    float* p = att + (size_t)blockIdx.x * S_;
    const int t = threadIdx.x;
    const int lane = t & 31;
    const int warp = t >> 5;
    __shared__ float red[8];

    float4 v = *(float4*)(p + t * 4);
    float m = fmaxf(fmaxf(v.x, v.y), fmaxf(v.z, v.w));
#pragma unroll
    for (int o = 16; o > 0; o >>= 1) m = fmaxf(m, __shfl_xor_sync(0xffffffffu, m, o));
    if (lane == 0) red[warp] = m;
    __syncthreads();
    m = red[lane & 7];
#pragma unroll
    for (int o = 4; o > 0; o >>= 1) m = fmaxf(m, __shfl_xor_sync(0xffffffffu, m, o));

    v.x = __expf(v.x - m); v.y = __expf(v.y - m);
    v.z = __expf(v.z - m); v.w = __expf(v.w - m);
    float s = v.x + v.y + v.z + v.w;
#pragma unroll
    for (int o = 16; o > 0; o >>= 1) s += __shfl_xor_sync(0xffffffffu, s, o);
    __syncthreads();
    if (lane == 0) red[warp] = s;
    __syncthreads();
    s = red[lane & 7];
#pragma unroll
    for (int o = 4; o > 0; o >>= 1) s += __shfl_xor_sync(0xffffffffu, s, o);

    float inv = 1.f / s;
    v.x *= inv; v.y *= inv; v.z *= inv; v.w *= inv;
    *(float4*)(p + t * 4) = v;
}

// --------------------------- LayerNorm kernels ------------------------------
__global__ void ln1_kernel(const float* __restrict__ x, const float* __restrict__ t1,
                           const float* __restrict__ s_all, const float* __restrict__ b_all,
                           float* __restrict__ h)
{
    int row = blockIdx.x;
    int e = row >> 12;
    int n = row & (N_ - 1);
    const float* a    = x  + (size_t)n * D_;
    const float* bsrc = t1 + ((size_t)e * N_ + n) * D_;
    const float* s    = s_all + (size_t)e * D_;
    const float* bb   = b_all + (size_t)e * D_;
    float* out        = h + ((size_t)e * N_ + n) * D_;
    int t = threadIdx.x;
    __shared__ float red[128];
    float v[4];
#pragma unroll
    for (int i = 0; i < 4; i++) {
        int d = t + i * 128;
        v[i] = a[d] + bsrc[d];
    }
    float sum = v[0] + v[1] + v[2] + v[3];
    red[t] = sum; __syncthreads();
    for (int o = 64; o > 0; o >>= 1) { if (t < o) red[t] += red[t + o]; __syncthreads(); }
    float mu = red[0] * (1.f / D_); __syncthreads();
    float sq = 0.f;
#pragma unroll
    for (int i = 0; i < 4; i++) { float d2 = v[i] - mu; sq += d2 * d2; }
    red[t] = sq; __syncthreads();
    for (int o = 64; o > 0; o >>= 1) { if (t < o) red[t] += red[t + o]; __syncthreads(); }
    float inv = rsqrtf(red[0] * (1.f / D_) + LN_EPS);
#pragma unroll
    for (int i = 0; i < 4; i++) {
        int d = t + i * 128;
        out[d] = (v[i] - mu) * inv * s[d] + bb[d];
    }
}

__global__ void ln2_acc_kernel(const float* __restrict__ h, const float* __restrict__ f2,
                               const float* __restrict__ s_all, const float* __restrict__ b_all,
                               const float* __restrict__ rw,
                               float* __restrict__ finalOut)
{
    int n = blockIdx.x;
    int t = threadIdx.x;
    __shared__ float red[128];
    float outv[4] = {0.f, 0.f, 0.f, 0.f};
    for (int e = 0; e < E_; e++) {
        float w = rw[n * E_ + e];
        if (w == 0.f) continue;            // block-uniform
        const float* hp = h  + ((size_t)e * N_ + n) * D_;
        const float* fp = f2 + ((size_t)e * N_ + n) * D_;
        const float* s  = s_all + (size_t)e * D_;
        const float* bb = b_all + (size_t)e * D_;
        float v[4];
#pragma unroll
        for (int i = 0; i < 4; i++) {
            int d = t + i * 128;
            v[i] = hp[d] + fp[d];
        }
        float sum = v[0] + v[1] + v[2] + v[3];
        __syncthreads();
        red[t] = sum; __syncthreads();
        for (int o = 64; o > 0; o >>= 1) { if (t < o) red[t] += red[t + o]; __syncthreads(); }
        float mu = red[0] * (1.f / D_); __syncthreads();
        float sq = 0.f;
#pragma unroll
        for (int i = 0; i < 4; i++) { float d2 = v[i] - mu; sq += d2 * d2; }
        red[t] = sq; __syncthreads();
        for (int o = 64; o > 0; o >>= 1) { if (t < o) red[t] += red[t + o]; __syncthreads(); }
        float inv = rsqrtf(red[0] * (1.f / D_) + LN_EPS);
#pragma unroll
        for (int i = 0; i < 4; i++) {
            int d = t + i * 128;
            outv[i] += w * ((v[i] - mu) * inv * s[d] + bb[d]);
        }
    }
#pragma unroll
    for (int i = 0; i < 4; i++)
        finalOut[(size_t)n * D_ + t + i * 128] = outv[i];
}

// ------------------------------ host glue -----------------------------------
extern "C" void kernel_launch(void* const* d_in, const int* in_sizes, int n_in,
                              void* d_out, int out_size)
{
    const float* x      = (const float*)d_in[0];
    const float* gate_w = (const float*)d_in[1];
    const float* gate_b = (const float*)d_in[2];
    const float* ln1_s  = (const float*)d_in[3];
    const float* ln1_b  = (const float*)d_in[4];
    const float* ln2_s  = (const float*)d_in[5];
    const float* ln2_b  = (const float*)d_in[6];
    const float* wq     = (const float*)d_in[7];
    const float* wk     = (const float*)d_in[8];
    const float* wv     = (const float*)d_in[9];
    const float* wo     = (const float*)d_in[10];
    const float* bq     = (const float*)d_in[11];
    const float* bk     = (const float*)d_in[12];
    const float* bv     = (const float*)d_in[13];
    const float* bo     = (const float*)d_in[14];
    const float* w1     = (const float*)d_in[15];
    const float* b1     = (const float*)d_in[16];
    const float* w2     = (const float*)d_in[17];
    const float* b2     = (const float*)d_in[18];

    float* out_final  = (float*)d_out;
    float* out_logits = out_final + (size_t)N_ * D_;

    float *qkv, *att, *o, *t1, *h, *f1, *f2, *rw, *wqkvP, *bqkvP;
    cudaGetSymbolAddress((void**)&qkv,   g_qkv);
    cudaGetSymbolAddress((void**)&att,   g_att);
    cudaGetSymbolAddress((void**)&o,     g_o);
    cudaGetSymbolAddress((void**)&t1,    g_t1);
    cudaGetSymbolAddress((void**)&h,     g_h);
    cudaGetSymbolAddress((void**)&f1,    g_f1);
    cudaGetSymbolAddress((void**)&f2,    g_f2);
    cudaGetSymbolAddress((void**)&rw,    g_rw);
    cudaGetSymbolAddress((void**)&wqkvP, g_wqkv);
    cudaGetSymbolAddress((void**)&bqkvP, g_bqkv);

    {
        int total = E_ * 3 * DD_;
        pack_qkv_kernel<<<(total + 255) / 256, 256>>>(wq, wk, wv, bq, bk, bv);
    }

    router_kernel<<<N_ / 8, 256>>>(x, gate_w, gate_b, out_logits, rw);

    const float attn_scale = 0.08838834764831845f;  // 1/sqrt(128)

    // QKV: z = e*3 + w  (24 batches)
    {
        dim3 grid(D_ / 128, N_ / 128, E_ * 3);
        tf32_gemm<false, false><<<grid, 256>>>(
            x, wqkvP, qkv, bqkvP,
            D_, D_, D_, D_,
            3, 1,
            0, 0, 0,
            3LL * DD_, DD_, 0,
            3LL * ND_, ND_, 0,
            3LL * D_, D_,
            1.f);
    }

    // QK^T: z = e*16 + b*4 + h (128 batches), NT
    {
        dim3 grid(S_ / 128, S_ / 128, E_ * B_ * H_);
        tf32_gemm<true, false><<<grid, 256>>>(
            qkv /*q*/, qkv + ND_ /*k*/, att, nullptr,
            DH_, D_, D_, S_,
            B_ * H_, H_,
            3LL * ND_, SD_, DH_,
            3LL * ND_, SD_, DH_,
            (long long)B_ * H_ * SS_, (long long)H_ * SS_, SS_,
            0, 0,
            attn_scale);
    }

    softmax_kernel<<<E_ * B_ * H_ * S_, 256>>>(att);

    // att @ V: NN
    {
        dim3 grid(DH_ / 128, S_ / 128, E_ * B_ * H_);
        tf32_gemm<false, false><<<grid, 256>>>(
            att, qkv + 2 * ND_ /*v*/, o, nullptr,
            S_, S_, D_, D_,
            B_ * H_, H_,
            (long long)B_ * H_ * SS_, (long long)H_ * SS_, SS_,
            3LL * ND_, SD_, DH_,
            ND_, SD_, DH_,
            0, 0,
            1.f);
    }

    // O projection
    {
        dim3 grid(D_ / 128, N_ / 128, E_);
        tf32_gemm<false, false><<<grid, 256>>>(
            o, wo, t1, bo,
            D_, D_, D_, D_,
            1, 1,
            ND_, 0, 0,
            (long long)DD_, 0, 0,
            ND_, 0, 0,
            D_, 0,
            1.f);
    }

    ln1_kernel<<<E_ * N_, 128>>>(x, t1, ln1_s, ln1_b, h);

    // FFN1
    {
        dim3 grid(F_ / 128, N_ / 128, E_);
        tf32_gemm<false, true><<<grid, 256>>>(
            h, w1, f1, b1,
            D_, D_, F_, F_,
            1, 1,
            ND_, 0, 0,
            (long long)D_ * F_, 0, 0,
            NF_, 0, 0,
            F_, 0,
            1.f);
    }

    // FFN2
    {
        dim3 grid(D_ / 128, N_ / 128, E_);
        tf32_gemm<false, false><<<grid, 256>>>(
            f1, w2, f2, b2,
            F_, F_, D_, D_,
            1, 1,
            NF_, 0, 0,
            (long long)F_ * D_, 0, 0,
            ND_, 0, 0,
            D_, 0,
            1.f);
    }

    ln2_acc_kernel<<<N_, 128>>>(h, f2, ln2_s, ln2_b, rw, out_final);
}

// round 4
// speedup vs baseline: 4.3248x; 1.0771x over previous
#include <cuda_runtime.h>
#include <cstdint>

// ---------------------------------------------------------------------------
// SEMMBlock: spiking-router MoE transformer block.
// B=4 S=1024 D=512 E=8 F=2048 H=4 dh=128. All experts dense.
// Round 4: fused flash attention (no score buffer); tf32 GEMMs elsewhere.
// ---------------------------------------------------------------------------

#define B_  4
#define S_  1024
#define D_  512
#define E_  8
#define F_  2048
#define H_  4
#define DH_ 128
#define N_  (B_ * S_)          // 4096 tokens
#define LN_EPS 1e-5f

#define DD_  (D_ * D_)
#define ND_  ((long long)N_ * D_)
#define SD_  ((long long)S_ * D_)
#define NF_  ((long long)N_ * F_)

// ------------------------- scratch (device globals) ------------------------
__device__ float g_rw[N_ * E_];
__device__ float g_wqkv[E_ * 3 * DD_];             // packed [e][qkv][D][D]
__device__ float g_bqkv[E_ * 3 * D_];
__device__ float g_qkv[(size_t)E_ * 3 * N_ * D_];
__device__ float g_o[(size_t)E_ * N_ * D_];
__device__ float g_t1[(size_t)E_ * N_ * D_];
__device__ float g_h[(size_t)E_ * N_ * D_];
__device__ float g_f1[(size_t)E_ * N_ * F_];
__device__ float g_f2[(size_t)E_ * N_ * D_];

// ------------------------------ helpers -------------------------------------
__device__ __forceinline__ void cp_async16(uint32_t smem, const void* gptr) {
    asm volatile("cp.async.cg.shared.global [%0], [%1], 16;\n" :: "r"(smem), "l"(gptr));
}
__device__ __forceinline__ void cp_commit() {
    asm volatile("cp.async.commit_group;\n");
}
__device__ __forceinline__ void cp_wait0() {
    asm volatile("cp.async.wait_group 0;\n");
}
__device__ __forceinline__ void mma_tf32(float* c, unsigned a0, unsigned a1,
                                         unsigned a2, unsigned a3,
                                         unsigned b0, unsigned b1) {
    asm volatile(
        "mma.sync.aligned.m16n8k8.row.col.f32.tf32.tf32.f32 "
        "{%0,%1,%2,%3}, {%4,%5,%6,%7}, {%8,%9}, {%0,%1,%2,%3};\n"
        : "+f"(c[0]), "+f"(c[1]), "+f"(c[2]), "+f"(c[3])
        : "r"(a0), "r"(a1), "r"(a2), "r"(a3), "r"(b0), "r"(b1));
}

// ------------------------------- router -------------------------------------
__global__ void router_kernel(const float* __restrict__ x,
                              const float* __restrict__ gw,
                              const float* __restrict__ gb,
                              float* __restrict__ logits,
                              float* __restrict__ rw)
{
    int warp = (blockIdx.x * blockDim.x + threadIdx.x) >> 5;
    int lane = threadIdx.x & 31;
    if (warp >= N_) return;
    const float* xr = x + (size_t)warp * D_;
    float acc[E_];
#pragma unroll
    for (int e = 0; e < E_; e++) acc[e] = 0.f;
    for (int i = lane; i < D_; i += 32) {
        float xv = xr[i];
        const float* g = gw + i * E_;
#pragma unroll
        for (int e = 0; e < E_; e++) acc[e] += xv * g[e];
    }
#pragma unroll
    for (int e = 0; e < E_; e++) {
#pragma unroll
        for (int o = 16; o > 0; o >>= 1)
            acc[e] += __shfl_down_sync(0xffffffffu, acc[e], o);
    }
    if (lane == 0) {
        float lg[E_];
#pragma unroll
        for (int e = 0; e < E_; e++) {
            lg[e] = acc[e] + gb[e];
            logits[warp * E_ + e] = lg[e];
        }
        int i1 = 0;
#pragma unroll
        for (int e = 1; e < E_; e++) if (lg[e] > lg[i1]) i1 = e;
        int i2 = -1;
#pragma unroll
        for (int e = 0; e < E_; e++) {
            if (e == i1) continue;
            if (i2 < 0 || lg[e] > lg[i2]) i2 = e;
        }
#pragma unroll
        for (int e = 0; e < E_; e++) {
            float r = 0.f;
            if (e == i1 || e == i2) {
                float mem = lg[e] > 0.f ? lg[e] : 0.f;
#pragma unroll
                for (int lvl = 0; lvl < 4; lvl++) {
                    float thr = 4.0f / (float)(1 << lvl);
                    if (mem >= thr) { r += thr; mem -= thr; }
                }
            }
            rw[warp * E_ + e] = r;
        }
    }
}

// ------------------------------ QKV pack ------------------------------------
__global__ void pack_qkv_kernel(const float* __restrict__ wq, const float* __restrict__ wk,
                                const float* __restrict__ wv,
                                const float* __restrict__ bq, const float* __restrict__ bk,
                                const float* __restrict__ bv)
{
    int idx = blockIdx.x * blockDim.x + threadIdx.x;
    const int totalW = E_ * 3 * DD_;
    if (idx < totalW) {
        int e = idx / (3 * DD_);
        int r = idx - e * 3 * DD_;
        int w = r / DD_;
        int o = r - w * DD_;
        const float* src = (w == 0) ? wq : (w == 1) ? wk : wv;
        g_wqkv[idx] = src[e * DD_ + o];
    }
    if (idx < E_ * 3 * D_) {
        int e = idx / (3 * D_);
        int r = idx - e * 3 * D_;
        int w = r / D_;
        int o = r - w * D_;
        const float* src = (w == 0) ? bq : (w == 1) ? bk : bv;
        g_bqkv[idx] = src[e * D_ + o];
    }
}

// --------------------------- tf32 tensor GEMM -------------------------------
#define ASTRIDE 20     // floats per A/B-NT smem row
#define BSTRIDE 136    // floats per B-NN smem row

template <bool TRANSB, bool RELU>
__global__ __launch_bounds__(256, 2) void tf32_gemm(
    const float* __restrict__ A, const float* __restrict__ Bp,
    float* __restrict__ C, const float* __restrict__ bias,
    int K, int lda, int ldb, int ldc,
    int div1, int div2,
    long long sA0, long long sA1, long long sA2,
    long long sB0, long long sB1, long long sB2,
    long long sC0, long long sC1, long long sC2,
    long long sb0, long long sb1,
    float alpha)
{
    int z = blockIdx.z;
    int z0 = z / div1; int r = z - z0 * div1;
    int z1 = r / div2; int z2 = r - z1 * div2;
    A  += z0 * sA0 + z1 * sA1 + z2 * sA2;
    Bp += z0 * sB0 + z1 * sB1 + z2 * sB2;
    C  += z0 * sC0 + z1 * sC1 + z2 * sC2;
    const float* biasp = bias ? (bias + z0 * sb0 + z1 * sb1) : nullptr;

    __shared__ float As[2][128 * ASTRIDE];
    __shared__ float Bs[2][TRANSB ? 128 * ASTRIDE : 16 * BSTRIDE];

    const int tid  = threadIdx.x;
    const int lane = tid & 31;
    const int wid  = tid >> 5;
    const int warpM = (wid >> 2) * 64;
    const int warpN = (wid & 3) * 32;
    const int bm = blockIdx.y * 128;
    const int bn = blockIdx.x * 128;

    const int srow = tid >> 1;
    const int sch  = (tid & 1) << 2;
    const int bkr  = tid >> 5;
    const int bn4  = (tid & 31) << 2;

    const float* gA = A + (long long)(bm + srow) * lda + sch;
    uint32_t sA = (uint32_t)__cvta_generic_to_shared(&As[0][srow * ASTRIDE + sch]);
    const float* gB;
    uint32_t sB;
    if (TRANSB) {
        gB = Bp + (long long)(bn + srow) * ldb + sch;
        sB = (uint32_t)__cvta_generic_to_shared(&Bs[0][srow * ASTRIDE + sch]);
    } else {
        gB = Bp + (long long)bkr * ldb + bn + bn4;
        sB = (uint32_t)__cvta_generic_to_shared(&Bs[0][bkr * BSTRIDE + bn4]);
    }
    const uint32_t stageA = sizeof(float) * 128 * ASTRIDE;
    const uint32_t stageB = TRANSB ? sizeof(float) * 128 * ASTRIDE
                                   : sizeof(float) * 16 * BSTRIDE;

    float acc[4][4][4];
#pragma unroll
    for (int i = 0; i < 4; i++)
#pragma unroll
        for (int j = 0; j < 4; j++)
#pragma unroll
            for (int q = 0; q < 4; q++) acc[i][j][q] = 0.f;

    cp_async16(sA,          gA);
    cp_async16(sA + 32,     gA + 8);
    if (TRANSB) {
        cp_async16(sB,      gB);
        cp_async16(sB + 32, gB + 8);
    } else {
        cp_async16(sB,                      gB);
        cp_async16(sB + 8 * BSTRIDE * 4,    gB + (long long)8 * ldb);
    }
    cp_commit();

    int stage = 0;
    const int mrow = warpM + (lane >> 2);
    const int ncol = warpN + (lane >> 2);

    for (int k0 = 0; k0 < K; k0 += 16) {
        cp_wait0();
        __syncthreads();

        if (k0 + 16 < K) {
            int st = stage ^ 1;
            const float* gA2 = gA + k0 + 16;
            uint32_t sA2 = sA + st * stageA;
            cp_async16(sA2,      gA2);
            cp_async16(sA2 + 32, gA2 + 8);
            uint32_t sB2 = sB + st * stageB;
            if (TRANSB) {
                const float* gB2 = gB + k0 + 16;
                cp_async16(sB2,      gB2);
                cp_async16(sB2 + 32, gB2 + 8);
            } else {
                const float* gB2 = gB + (long long)(k0 + 16) * ldb;
                cp_async16(sB2,                   gB2);
                cp_async16(sB2 + 8 * BSTRIDE * 4, gB2 + (long long)8 * ldb);
            }
            cp_commit();
        }

        const float* As0 = &As[stage][0];
        const float* Bs0 = &Bs[stage][0];

#pragma unroll
        for (int ks = 0; ks < 2; ks++) {
            const int krow = ks * 8 + (lane & 3);
            unsigned af[4][4], bf[4][2];
#pragma unroll
            for (int mi = 0; mi < 4; mi++) {
                const float* pa = As0 + (mrow + mi * 16) * ASTRIDE + krow;
                af[mi][0] = __float_as_uint(pa[0]);
                af[mi][1] = __float_as_uint(pa[8 * ASTRIDE]);
                af[mi][2] = __float_as_uint(pa[4]);
                af[mi][3] = __float_as_uint(pa[8 * ASTRIDE + 4]);
            }
#pragma unroll
            for (int ni = 0; ni < 4; ni++) {
                if (TRANSB) {
                    const float* pb = Bs0 + (ncol + ni * 8) * ASTRIDE + krow;
                    bf[ni][0] = __float_as_uint(pb[0]);
                    bf[ni][1] = __float_as_uint(pb[4]);
                } else {
                    const float* pb = Bs0 + krow * BSTRIDE + ncol + ni * 8;
                    bf[ni][0] = __float_as_uint(pb[0]);
                    bf[ni][1] = __float_as_uint(pb[4 * BSTRIDE]);
                }
            }
#pragma unroll
            for (int mi = 0; mi < 4; mi++)
#pragma unroll
                for (int ni = 0; ni < 4; ni++)
                    mma_tf32(acc[mi][ni], af[mi][0], af[mi][1], af[mi][2], af[mi][3],
                             bf[ni][0], bf[ni][1]);
        }
        stage ^= 1;
    }

#pragma unroll
    for (int mi = 0; mi < 4; mi++) {
        int row0 = bm + warpM + mi * 16 + (lane >> 2);
#pragma unroll
        for (int ni = 0; ni < 4; ni++) {
            int col = bn + warpN + ni * 8 + ((lane & 3) << 1);
            float b0 = 0.f, b1 = 0.f;
            if (biasp) { b0 = biasp[col]; b1 = biasp[col + 1]; }
            float2 v0, v1;
            v0.x = acc[mi][ni][0] * alpha + b0;
            v0.y = acc[mi][ni][1] * alpha + b1;
            v1.x = acc[mi][ni][2] * alpha + b0;
            v1.y = acc[mi][ni][3] * alpha + b1;
            if (RELU) {
                v0.x = fmaxf(v0.x, 0.f); v0.y = fmaxf(v0.y, 0.f);
                v1.x = fmaxf(v1.x, 0.f); v1.y = fmaxf(v1.y, 0.f);
            }
            *(float2*)(C + (long long)row0 * ldc + col)       = v0;
            *(float2*)(C + (long long)(row0 + 8) * ldc + col) = v1;
        }
    }
}

// ------------------------- fused flash attention -----------------------------
// Block: one (e,b,h) x 128-row Q tile. 256 threads = 8 warps, 16 rows/warp.
// KV tiles of 64 rows, cp.async double-buffered. Online softmax in registers.
#define BC_   64
#define QSTR  132
#define KSTR  132
#define VSTR  136
#define FLASH_SMEM ((128*QSTR + 2*BC_*KSTR + 2*BC_*VSTR) * 4)

__global__ __launch_bounds__(256) void flash_kernel(const float* __restrict__ qkv,
                                                    float* __restrict__ o)
{
    extern __shared__ float fsm[];
    float* Qs = fsm;
    float* Ks = fsm + 128 * QSTR;
    float* Vs = Ks + 2 * BC_ * KSTR;

    const int tid  = threadIdx.x;
    const int lane = tid & 31;
    const int wid  = tid >> 5;
    const int qt = blockIdx.x;                 // Q tile 0..7
    const int z  = blockIdx.y;                 // e*16 + b*4 + h
    const int e  = z >> 4;
    const int b  = (z >> 2) & 3;
    const int h  = z & 3;
    const float scale = 0.08838834764831845f;  // 1/sqrt(128)

    const float* qbase = qkv + (long long)e * 3 * ND_ + (long long)(b * S_ + qt * 128) * D_ + h * DH_;
    const float* kbase = qkv + (long long)e * 3 * ND_ + ND_ + (long long)(b * S_) * D_ + h * DH_;
    const float* vbase = kbase + ND_;

    // ---- stage Q tile ----
    {
        int r = tid >> 1, c0 = (tid & 1) * 64;
        const float* g = qbase + (long long)r * D_ + c0;
        uint32_t s = (uint32_t)__cvta_generic_to_shared(&Qs[r * QSTR + c0]);
#pragma unroll
        for (int j = 0; j < 16; j++) cp_async16(s + j * 16, g + j * 4);
    }
    // ---- stage KV tile 0 ----
    {
        int r = tid >> 2, c0 = (tid & 3) * 32;
        const float* gk = kbase + (long long)r * D_ + c0;
        const float* gv = vbase + (long long)r * D_ + c0;
        uint32_t sk = (uint32_t)__cvta_generic_to_shared(&Ks[r * KSTR + c0]);
        uint32_t sv = (uint32_t)__cvta_generic_to_shared(&Vs[r * VSTR + c0]);
#pragma unroll
        for (int j = 0; j < 8; j++) {
            cp_async16(sk + j * 16, gk + j * 4);
            cp_async16(sv + j * 16, gv + j * 4);
        }
    }
    cp_commit();

    const int r0 = lane >> 2;
    const int qq = lane & 3;
    const int wrow = wid * 16;

    float oacc[16][4];
#pragma unroll
    for (int i = 0; i < 16; i++)
#pragma unroll
        for (int j = 0; j < 4; j++) oacc[i][j] = 0.f;
    float m0 = -1e30f, m1 = -1e30f, l0 = 0.f, l1 = 0.f;

    for (int t = 0; t < 16; t++) {
        const int st = t & 1;
        cp_wait0();
        __syncthreads();

        if (t < 15) {
            int r = tid >> 2, c0 = (tid & 3) * 32;
            int st2 = st ^ 1;
            const float* gk = kbase + (long long)((t + 1) * BC_ + r) * D_ + c0;
            const float* gv = vbase + (long long)((t + 1) * BC_ + r) * D_ + c0;
            uint32_t sk = (uint32_t)__cvta_generic_to_shared(&Ks[st2 * BC_ * KSTR + r * KSTR + c0]);
            uint32_t sv = (uint32_t)__cvta_generic_to_shared(&Vs[st2 * BC_ * VSTR + r * VSTR + c0]);
#pragma unroll
            for (int j = 0; j < 8; j++) {
                cp_async16(sk + j * 16, gk + j * 4);
                cp_async16(sv + j * 16, gv + j * 4);
            }
            cp_commit();
        }

        // ---- S = Q_w @ K^T ----
        float sacc[8][4];
#pragma unroll
        for (int i = 0; i < 8; i++)
#pragma unroll
            for (int j = 0; j < 4; j++) sacc[i][j] = 0.f;

        const float* Qw = Qs + wrow * QSTR;
        const float* Kt = Ks + st * BC_ * KSTR;
#pragma unroll
        for (int ks = 0; ks < 16; ks++) {
            const int kc = ks * 8 + qq;
            const float* pa = Qw + r0 * QSTR + kc;
            unsigned a0 = __float_as_uint(pa[0]);
            unsigned a1 = __float_as_uint(pa[8 * QSTR]);
            unsigned a2 = __float_as_uint(pa[4]);
            unsigned a3 = __float_as_uint(pa[8 * QSTR + 4]);
#pragma unroll
            for (int ni = 0; ni < 8; ni++) {
                const float* pb = Kt + (ni * 8 + r0) * KSTR + kc;
                mma_tf32(sacc[ni], a0, a1, a2, a3,
                         __float_as_uint(pb[0]), __float_as_uint(pb[4]));
            }
        }

        // ---- online softmax ----
        float rmax0 = -1e30f, rmax1 = -1e30f;
#pragma unroll
        for (int ni = 0; ni < 8; ni++) {
            sacc[ni][0] *= scale; sacc[ni][1] *= scale;
            sacc[ni][2] *= scale; sacc[ni][3] *= scale;
            rmax0 = fmaxf(rmax0, fmaxf(sacc[ni][0], sacc[ni][1]));
            rmax1 = fmaxf(rmax1, fmaxf(sacc[ni][2], sacc[ni][3]));
        }
        rmax0 = fmaxf(rmax0, __shfl_xor_sync(0xffffffffu, rmax0, 1));
        rmax0 = fmaxf(rmax0, __shfl_xor_sync(0xffffffffu, rmax0, 2));
        rmax1 = fmaxf(rmax1, __shfl_xor_sync(0xffffffffu, rmax1, 1));
        rmax1 = fmaxf(rmax1, __shfl_xor_sync(0xffffffffu, rmax1, 2));
        float mn0 = fmaxf(m0, rmax0), mn1 = fmaxf(m1, rmax1);
        float c0 = __expf(m0 - mn0), c1 = __expf(m1 - mn1);
        m0 = mn0; m1 = mn1;
        float rs0 = 0.f, rs1 = 0.f;
#pragma unroll
        for (int ni = 0; ni < 8; ni++) {
            sacc[ni][0] = __expf(sacc[ni][0] - m0);
            sacc[ni][1] = __expf(sacc[ni][1] - m0);
            sacc[ni][2] = __expf(sacc[ni][2] - m1);
            sacc[ni][3] = __expf(sacc[ni][3] - m1);
            rs0 += sacc[ni][0] + sacc[ni][1];
            rs1 += sacc[ni][2] + sacc[ni][3];
        }
        rs0 += __shfl_xor_sync(0xffffffffu, rs0, 1);
        rs0 += __shfl_xor_sync(0xffffffffu, rs0, 2);
        rs1 += __shfl_xor_sync(0xffffffffu, rs1, 1);
        rs1 += __shfl_xor_sync(0xffffffffu, rs1, 2);
        l0 = l0 * c0 + rs0;
        l1 = l1 * c1 + rs1;
#pragma unroll
        for (int ni = 0; ni < 16; ni++) {
            oacc[ni][0] *= c0; oacc[ni][1] *= c0;
            oacc[ni][2] *= c1; oacc[ni][3] *= c1;
        }

        // ---- O += P @ V ----
        const float* Vt = Vs + st * BC_ * VSTR;
        const int srcA = (lane & ~3) | (qq >> 1);
        const int srcB = srcA + 2;
#pragma unroll
        for (int ks = 0; ks < 8; ks++) {
            float x0 = __shfl_sync(0xffffffffu, sacc[ks][0], srcA);
            float x1 = __shfl_sync(0xffffffffu, sacc[ks][1], srcA);
            float a0f = (qq & 1) ? x1 : x0;
            float y0 = __shfl_sync(0xffffffffu, sacc[ks][0], srcB);
            float y1 = __shfl_sync(0xffffffffu, sacc[ks][1], srcB);
            float a2f = (qq & 1) ? y1 : y0;
            x0 = __shfl_sync(0xffffffffu, sacc[ks][2], srcA);
            x1 = __shfl_sync(0xffffffffu, sacc[ks][3], srcA);
            float a1f = (qq & 1) ? x1 : x0;
            y0 = __shfl_sync(0xffffffffu, sacc[ks][2], srcB);
            y1 = __shfl_sync(0xffffffffu, sacc[ks][3], srcB);
            float a3f = (qq & 1) ? y1 : y0;
            unsigned a0 = __float_as_uint(a0f), a1 = __float_as_uint(a1f);
            unsigned a2 = __float_as_uint(a2f), a3 = __float_as_uint(a3f);
#pragma unroll
            for (int ni = 0; ni < 16; ni++) {
                const float* pv = Vt + (ks * 8 + qq) * VSTR + ni * 8 + r0;
                mma_tf32(oacc[ni], a0, a1, a2, a3,
                         __float_as_uint(pv[0]), __float_as_uint(pv[4 * VSTR]));
            }
        }
    }

    // ---- epilogue ----
    float inv0 = 1.f / l0, inv1 = 1.f / l1;
    long long tok0 = (long long)(b * S_ + qt * 128 + wrow + r0);
    float* ob = o + (long long)e * ND_ + tok0 * D_ + h * DH_;
#pragma unroll
    for (int ni = 0; ni < 16; ni++) {
        int col = ni * 8 + 2 * qq;
        float2 v0 = make_float2(oacc[ni][0] * inv0, oacc[ni][1] * inv0);
        float2 v1 = make_float2(oacc[ni][2] * inv1, oacc[ni][3] * inv1);
        *(float2*)(ob + col)            = v0;
        *(float2*)(ob + 8LL * D_ + col) = v1;
    }
}

// --------------------------- LayerNorm kernels ------------------------------
__global__ void ln1_kernel(const float* __restrict__ x, const float* __restrict__ t1,
                           const float* __restrict__ s_all, const float* __restrict__ b_all,
                           float* __restrict__ h)
{
    int row = blockIdx.x;
    int e = row >> 12;
    int n = row & (N_ - 1);
    const float* a    = x  + (size_t)n * D_;
    const float* bsrc = t1 + ((size_t)e * N_ + n) * D_;
    const float* s    = s_all + (size_t)e * D_;
    const float* bb   = b_all + (size_t)e * D_;
    float* out        = h + ((size_t)e * N_ + n) * D_;
    int t = threadIdx.x;
    __shared__ float red[128];
    float v[4];
#pragma unroll
    for (int i = 0; i < 4; i++) {
        int d = t + i * 128;
        v[i] = a[d] + bsrc[d];
    }
    float sum = v[0] + v[1] + v[2] + v[3];
    red[t] = sum; __syncthreads();
    for (int o = 64; o > 0; o >>= 1) { if (t < o) red[t] += red[t + o]; __syncthreads(); }
    float mu = red[0] * (1.f / D_); __syncthreads();
    float sq = 0.f;
#pragma unroll
    for (int i = 0; i < 4; i++) { float d2 = v[i] - mu; sq += d2 * d2; }
    red[t] = sq; __syncthreads();
    for (int o = 64; o > 0; o >>= 1) { if (t < o) red[t] += red[t + o]; __syncthreads(); }
    float inv = rsqrtf(red[0] * (1.f / D_) + LN_EPS);
#pragma unroll
    for (int i = 0; i < 4; i++) {
        int d = t + i * 128;
        out[d] = (v[i] - mu) * inv * s[d] + bb[d];
    }
}

__global__ void ln2_acc_kernel(const float* __restrict__ h, const float* __restrict__ f2,
                               const float* __restrict__ s_all, const float* __restrict__ b_all,
                               const float* __restrict__ rw,
                               float* __restrict__ finalOut)
{
    int n = blockIdx.x;
    int t = threadIdx.x;
    __shared__ float red[128];
    float outv[4] = {0.f, 0.f, 0.f, 0.f};
    for (int e = 0; e < E_; e++) {
        float w = rw[n * E_ + e];
        if (w == 0.f) continue;
        const float* hp = h  + ((size_t)e * N_ + n) * D_;
        const float* fp = f2 + ((size_t)e * N_ + n) * D_;
        const float* s  = s_all + (size_t)e * D_;
        const float* bb = b_all + (size_t)e * D_;
        float v[4];
#pragma unroll
        for (int i = 0; i < 4; i++) {
            int d = t + i * 128;
            v[i] = hp[d] + fp[d];
        }
        float sum = v[0] + v[1] + v[2] + v[3];
        __syncthreads();
        red[t] = sum; __syncthreads();
        for (int o = 64; o > 0; o >>= 1) { if (t < o) red[t] += red[t + o]; __syncthreads(); }
        float mu = red[0] * (1.f / D_); __syncthreads();
        float sq = 0.f;
#pragma unroll
        for (int i = 0; i < 4; i++) { float d2 = v[i] - mu; sq += d2 * d2; }
        red[t] = sq; __syncthreads();
        for (int o = 64; o > 0; o >>= 1) { if (t < o) red[t] += red[t + o]; __syncthreads(); }
        float inv = rsqrtf(red[0] * (1.f / D_) + LN_EPS);
#pragma unroll
        for (int i = 0; i < 4; i++) {
            int d = t + i * 128;
            outv[i] += w * ((v[i] - mu) * inv * s[d] + bb[d]);
        }
    }
#pragma unroll
    for (int i = 0; i < 4; i++)
        finalOut[(size_t)n * D_ + t + i * 128] = outv[i];
}

// ------------------------------ host glue -----------------------------------
extern "C" void kernel_launch(void* const* d_in, const int* in_sizes, int n_in,
                              void* d_out, int out_size)
{
    const float* x      = (const float*)d_in[0];
    const float* gate_w = (const float*)d_in[1];
    const float* gate_b = (const float*)d_in[2];
    const float* ln1_s  = (const float*)d_in[3];
    const float* ln1_b  = (const float*)d_in[4];
    const float* ln2_s  = (const float*)d_in[5];
    const float* ln2_b  = (const float*)d_in[6];
    const float* wq     = (const float*)d_in[7];
    const float* wk     = (const float*)d_in[8];
    const float* wv     = (const float*)d_in[9];
    const float* wo     = (const float*)d_in[10];
    const float* bq     = (const float*)d_in[11];
    const float* bk     = (const float*)d_in[12];
    const float* bv     = (const float*)d_in[13];
    const float* bo     = (const float*)d_in[14];
    const float* w1     = (const float*)d_in[15];
    const float* b1     = (const float*)d_in[16];
    const float* w2     = (const float*)d_in[17];
    const float* b2     = (const float*)d_in[18];

    float* out_final  = (float*)d_out;
    float* out_logits = out_final + (size_t)N_ * D_;

    float *qkv, *o, *t1, *h, *f1, *f2, *rw, *wqkvP, *bqkvP;
    cudaGetSymbolAddress((void**)&qkv,   g_qkv);
    cudaGetSymbolAddress((void**)&o,     g_o);
    cudaGetSymbolAddress((void**)&t1,    g_t1);
    cudaGetSymbolAddress((void**)&h,     g_h);
    cudaGetSymbolAddress((void**)&f1,    g_f1);
    cudaGetSymbolAddress((void**)&f2,    g_f2);
    cudaGetSymbolAddress((void**)&rw,    g_rw);
    cudaGetSymbolAddress((void**)&wqkvP, g_wqkv);
    cudaGetSymbolAddress((void**)&bqkvP, g_bqkv);

    cudaFuncSetAttribute(flash_kernel,
                         cudaFuncAttributeMaxDynamicSharedMemorySize, FLASH_SMEM);

    {
        int total = E_ * 3 * DD_;
        pack_qkv_kernel<<<(total + 255) / 256, 256>>>(wq, wk, wv, bq, bk, bv);
    }

    router_kernel<<<N_ / 8, 256>>>(x, gate_w, gate_b, out_logits, rw);

    // QKV: z = e*3 + w  (24 batches)
    {
        dim3 grid(D_ / 128, N_ / 128, E_ * 3);
        tf32_gemm<false, false><<<grid, 256>>>(
            x, wqkvP, qkv, bqkvP,
            D_, D_, D_, D_,
            3, 1,
            0, 0, 0,
            3LL * DD_, DD_, 0,
            3LL * ND_, ND_, 0,
            3LL * D_, D_,
            1.f);
    }

    // fused attention: grid (Qtiles=8, ebh=128)
    {
        dim3 grid(S_ / 128, E_ * B_ * H_);
        flash_kernel<<<grid, 256, FLASH_SMEM>>>(qkv, o);
    }

    // O projection
    {
        dim3 grid(D_ / 128, N_ / 128, E_);
        tf32_gemm<false, false><<<grid, 256>>>(
            o, wo, t1, bo,
            D_, D_, D_, D_,
            1, 1,
            ND_, 0, 0,
            (long long)DD_, 0, 0,
            ND_, 0, 0,
            D_, 0,
            1.f);
    }

    ln1_kernel<<<E_ * N_, 128>>>(x, t1, ln1_s, ln1_b, h);

    // FFN1
    {
        dim3 grid(F_ / 128, N_ / 128, E_);
        tf32_gemm<false, true><<<grid, 256>>>(
            h, w1, f1, b1,
            D_, D_, F_, F_,
            1, 1,
            ND_, 0, 0,
            (long long)D_ * F_, 0, 0,
            NF_, 0, 0,
            F_, 0,
            1.f);
    }

    // FFN2
    {
        dim3 grid(D_ / 128, N_ / 128, E_);
        tf32_gemm<false, false><<<grid, 256>>>(
            f1, w2, f2, b2,
            F_, F_, D_, D_,
            1, 1,
            NF_, 0, 0,
            (long long)F_ * D_, 0, 0,
            ND_, 0, 0,
            D_, 0,
            1.f);
    }

    ln2_acc_kernel<<<N_, 128>>>(h, f2, ln2_s, ln2_b, rw, out_final);
}

// round 5
// speedup vs baseline: 10.3019x; 2.3821x over previous
#include <cuda_runtime.h>
#include <cstdint>

// ---------------------------------------------------------------------------
// SEMMBlock: spiking-router MoE transformer block.
// B=4 S=1024 D=512 E=8 F=2048 H=4 dh=128.
// Round 5: exploit router sparsity — only top-2 experts per token do
// Q/attention/O/FFN work. K/V projections stay dense. Gather-GEMMs with
// device-side early exit so the CUDA graph stays static.
// ---------------------------------------------------------------------------

#define B_  4
#define S_  1024
#define D_  512
#define E_  8
#define F_  2048
#define H_  4
#define DH_ 128
#define N_  (B_ * S_)          // 4096 tokens
#define SEGS (E_ * B_)         // 32 (expert, batch) segments
#define LN_EPS 1e-5f

#define DD_  (D_ * D_)
#define ND_  ((long long)N_ * D_)
#define SD_  ((long long)S_ * D_)
#define SF_  ((long long)S_ * F_)

// ------------------------- scratch (device globals) ------------------------
__device__ float g_rw[N_ * E_];
__device__ int   g_cnt[SEGS];
__device__ int   g_idx[SEGS * S_];          // token list per (e,b), zero-padded
__device__ int   g_pos[N_ * E_];            // inverse: token -> slot in segment
__device__ float g_kv[(size_t)E_ * 2 * N_ * D_];   // dense K,V  (134MB)
__device__ float g_qg[(size_t)SEGS * S_ * D_];     // gathered Q  (67MB)
__device__ float g_og[(size_t)SEGS * S_ * D_];
__device__ float g_t1[(size_t)SEGS * S_ * D_];
__device__ float g_hg[(size_t)SEGS * S_ * D_];
__device__ float g_f1[(size_t)SEGS * S_ * F_];     // 268MB
__device__ float g_f2[(size_t)SEGS * S_ * D_];

// ------------------------------ helpers -------------------------------------
__device__ __forceinline__ void cp_async16(uint32_t smem, const void* gptr) {
    asm volatile("cp.async.cg.shared.global [%0], [%1], 16;\n" :: "r"(smem), "l"(gptr));
}
__device__ __forceinline__ void cp_commit() {
    asm volatile("cp.async.commit_group;\n");
}
__device__ __forceinline__ void cp_wait0() {
    asm volatile("cp.async.wait_group 0;\n");
}
__device__ __forceinline__ void mma_tf32(float* c, unsigned a0, unsigned a1,
                                         unsigned a2, unsigned a3,
                                         unsigned b0, unsigned b1) {
    asm volatile(
        "mma.sync.aligned.m16n8k8.row.col.f32.tf32.tf32.f32 "
        "{%0,%1,%2,%3}, {%4,%5,%6,%7}, {%8,%9}, {%0,%1,%2,%3};\n"
        : "+f"(c[0]), "+f"(c[1]), "+f"(c[2]), "+f"(c[3])
        : "r"(a0), "r"(a1), "r"(a2), "r"(a3), "r"(b0), "r"(b1));
}

// ------------------------------- router -------------------------------------
__global__ void router_kernel(const float* __restrict__ x,
                              const float* __restrict__ gw,
                              const float* __restrict__ gb,
                              float* __restrict__ logits,
                              float* __restrict__ rw)
{
    int warp = (blockIdx.x * blockDim.x + threadIdx.x) >> 5;
    int lane = threadIdx.x & 31;
    if (warp >= N_) return;
    const float* xr = x + (size_t)warp * D_;
    float acc[E_];
#pragma unroll
    for (int e = 0; e < E_; e++) acc[e] = 0.f;
    for (int i = lane; i < D_; i += 32) {
        float xv = xr[i];
        const float* g = gw + i * E_;
#pragma unroll
        for (int e = 0; e < E_; e++) acc[e] += xv * g[e];
    }
#pragma unroll
    for (int e = 0; e < E_; e++) {
#pragma unroll
        for (int o = 16; o > 0; o >>= 1)
            acc[e] += __shfl_down_sync(0xffffffffu, acc[e], o);
    }
    if (lane == 0) {
        float lg[E_];
#pragma unroll
        for (int e = 0; e < E_; e++) {
            lg[e] = acc[e] + gb[e];
            logits[warp * E_ + e] = lg[e];
        }
        int i1 = 0;
#pragma unroll
        for (int e = 1; e < E_; e++) if (lg[e] > lg[i1]) i1 = e;
        int i2 = -1;
#pragma unroll
        for (int e = 0; e < E_; e++) {
            if (e == i1) continue;
            if (i2 < 0 || lg[e] > lg[i2]) i2 = e;
        }
#pragma unroll
        for (int e = 0; e < E_; e++) {
            float r = 0.f;
            if (e == i1 || e == i2) {
                float mem = lg[e] > 0.f ? lg[e] : 0.f;
#pragma unroll
                for (int lvl = 0; lvl < 4; lvl++) {
                    float thr = 4.0f / (float)(1 << lvl);
                    if (mem >= thr) { r += thr; mem -= thr; }
                }
            }
            rw[warp * E_ + e] = r;
        }
    }
}

// -------------------------- build gather lists -------------------------------
__global__ void build_lists_kernel(const float* __restrict__ rw)
{
    int n = blockIdx.x * blockDim.x + threadIdx.x;
    if (n >= N_) return;
    int b = n >> 10;
#pragma unroll
    for (int e = 0; e < E_; e++) {
        if (rw[n * E_ + e] != 0.f) {
            int seg = e * B_ + b;
            int i = atomicAdd(&g_cnt[seg], 1);
            g_idx[seg * S_ + i] = n;
            g_pos[n * E_ + e] = i;
        }
    }
}

// --------------------------- tf32 tensor GEMM (NN) ---------------------------
// C = A @ B + bias (relu). BM=BN=128, BK=16, 256 thr, 8 warps of 64x32.
// z -> (z0=z/div1, z1=z%div1). Optional A-row gather (gidx) and per-z
// row-count early exit (mlim).
#define ASTRIDE 20
#define BSTRIDE 136

template <bool RELU>
__global__ __launch_bounds__(256, 2) void tf32_gemm(
    const float* __restrict__ A, const float* __restrict__ Bp,
    float* __restrict__ C, const float* __restrict__ bias,
    int K, int lda, int ldb, int ldc,
    int div1,
    long long sA0, long long sA1,
    long long sB0, long long sB1,
    long long sC0, long long sC1,
    long long sb0,
    const int* __restrict__ mlim, const int* __restrict__ gidx)
{
    const int z  = blockIdx.z;
    const int bm = blockIdx.y * 128;
    if (mlim && bm >= mlim[z]) return;
    const int z0 = z / div1, z1 = z - z0 * div1;
    A  += z0 * sA0 + z1 * sA1;
    Bp += z0 * sB0 + z1 * sB1;
    C  += z0 * sC0 + z1 * sC1;
    const float* biasp = bias + z0 * sb0;

    __shared__ float As[2][128 * ASTRIDE];
    __shared__ float Bs[2][16 * BSTRIDE];

    const int tid  = threadIdx.x;
    const int lane = tid & 31;
    const int wid  = tid >> 5;
    const int warpM = (wid >> 2) * 64;
    const int warpN = (wid & 3) * 32;
    const int bn = blockIdx.x * 128;

    const int srow = tid >> 1;
    const int sch  = (tid & 1) << 2;
    const int bkr  = tid >> 5;
    const int bn4  = (tid & 31) << 2;

    long long arow = bm + srow;
    if (gidx) arow = gidx[(long long)z * S_ + arow];
    const float* gA = A + arow * lda + sch;
    uint32_t sA = (uint32_t)__cvta_generic_to_shared(&As[0][srow * ASTRIDE + sch]);
    const float* gB = Bp + (long long)bkr * ldb + bn + bn4;
    uint32_t sB = (uint32_t)__cvta_generic_to_shared(&Bs[0][bkr * BSTRIDE + bn4]);
    const uint32_t stageA = sizeof(float) * 128 * ASTRIDE;
    const uint32_t stageB = sizeof(float) * 16 * BSTRIDE;

    float acc[4][4][4];
#pragma unroll
    for (int i = 0; i < 4; i++)
#pragma unroll
        for (int j = 0; j < 4; j++)
#pragma unroll
            for (int q = 0; q < 4; q++) acc[i][j][q] = 0.f;

    cp_async16(sA,      gA);
    cp_async16(sA + 32, gA + 8);
    cp_async16(sB,                   gB);
    cp_async16(sB + 8 * BSTRIDE * 4, gB + (long long)8 * ldb);
    cp_commit();

    int stage = 0;
    const int mrow = warpM + (lane >> 2);
    const int ncol = warpN + (lane >> 2);

    for (int k0 = 0; k0 < K; k0 += 16) {
        cp_wait0();
        __syncthreads();

        if (k0 + 16 < K) {
            int st = stage ^ 1;
            const float* gA2 = gA + k0 + 16;
            uint32_t sA2 = sA + st * stageA;
            cp_async16(sA2,      gA2);
            cp_async16(sA2 + 32, gA2 + 8);
            uint32_t sB2 = sB + st * stageB;
            const float* gB2 = gB + (long long)(k0 + 16) * ldb;
            cp_async16(sB2,                   gB2);
            cp_async16(sB2 + 8 * BSTRIDE * 4, gB2 + (long long)8 * ldb);
            cp_commit();
        }

        const float* As0 = &As[stage][0];
        const float* Bs0 = &Bs[stage][0];

#pragma unroll
        for (int ks = 0; ks < 2; ks++) {
            const int krow = ks * 8 + (lane & 3);
            unsigned af[4][4], bf[4][2];
#pragma unroll
            for (int mi = 0; mi < 4; mi++) {
                const float* pa = As0 + (mrow + mi * 16) * ASTRIDE + krow;
                af[mi][0] = __float_as_uint(pa[0]);
                af[mi][1] = __float_as_uint(pa[8 * ASTRIDE]);
                af[mi][2] = __float_as_uint(pa[4]);
                af[mi][3] = __float_as_uint(pa[8 * ASTRIDE + 4]);
            }
#pragma unroll
            for (int ni = 0; ni < 4; ni++) {
                const float* pb = Bs0 + krow * BSTRIDE + ncol + ni * 8;
                bf[ni][0] = __float_as_uint(pb[0]);
                bf[ni][1] = __float_as_uint(pb[4 * BSTRIDE]);
            }
#pragma unroll
            for (int mi = 0; mi < 4; mi++)
#pragma unroll
                for (int ni = 0; ni < 4; ni++)
                    mma_tf32(acc[mi][ni], af[mi][0], af[mi][1], af[mi][2], af[mi][3],
                             bf[ni][0], bf[ni][1]);
        }
        stage ^= 1;
    }

#pragma unroll
    for (int mi = 0; mi < 4; mi++) {
        int row0 = bm + warpM + mi * 16 + (lane >> 2);
#pragma unroll
        for (int ni = 0; ni < 4; ni++) {
            int col = bn + warpN + ni * 8 + ((lane & 3) << 1);
            float b0 = biasp[col], b1 = biasp[col + 1];
            float2 v0, v1;
            v0.x = acc[mi][ni][0] + b0;
            v0.y = acc[mi][ni][1] + b1;
            v1.x = acc[mi][ni][2] + b0;
            v1.y = acc[mi][ni][3] + b1;
            if (RELU) {
                v0.x = fmaxf(v0.x, 0.f); v0.y = fmaxf(v0.y, 0.f);
                v1.x = fmaxf(v1.x, 0.f); v1.y = fmaxf(v1.y, 0.f);
            }
            *(float2*)(C + (long long)row0 * ldc + col)       = v0;
            *(float2*)(C + (long long)(row0 + 8) * ldc + col) = v1;
        }
    }
}

// ------------------------- fused flash attention -----------------------------
// Block: 128 gathered Q rows of one (seg=e*4+b, h). Full dense K/V loop.
#define BC_   64
#define QSTR  132
#define KSTR  132
#define VSTR  136
#define FLASH_SMEM ((128*QSTR + 2*BC_*KSTR + 2*BC_*VSTR) * 4)

__global__ __launch_bounds__(256) void flash_kernel(const float* __restrict__ qg,
                                                    const float* __restrict__ kv,
                                                    const int* __restrict__ cnt,
                                                    float* __restrict__ og)
{
    const int qt  = blockIdx.x;                // Q tile 0..7
    const int seg = blockIdx.y >> 2;           // e*4+b
    const int h   = blockIdx.y & 3;
    if (qt * 128 >= cnt[seg]) return;
    const int e = seg >> 2;
    const int b = seg & 3;

    extern __shared__ float fsm[];
    float* Qs = fsm;
    float* Ks = fsm + 128 * QSTR;
    float* Vs = Ks + 2 * BC_ * KSTR;

    const int tid  = threadIdx.x;
    const int lane = tid & 31;
    const int wid  = tid >> 5;
    const float scale = 0.08838834764831845f;  // 1/sqrt(128)

    const float* qbase = qg + (long long)seg * SD_ + (long long)(qt * 128) * D_ + h * DH_;
    const float* kbase = kv + (long long)e * 2 * ND_ + (long long)(b * S_) * D_ + h * DH_;
    const float* vbase = kbase + ND_;

    // ---- stage Q tile ----
    {
        int r = tid >> 1, c0 = (tid & 1) * 64;
        const float* g = qbase + (long long)r * D_ + c0;
        uint32_t s = (uint32_t)__cvta_generic_to_shared(&Qs[r * QSTR + c0]);
#pragma unroll
        for (int j = 0; j < 16; j++) cp_async16(s + j * 16, g + j * 4);
    }
    // ---- stage KV tile 0 ----
    {
        int r = tid >> 2, c0 = (tid & 3) * 32;
        const float* gk = kbase + (long long)r * D_ + c0;
        const float* gv = vbase + (long long)r * D_ + c0;
        uint32_t sk = (uint32_t)__cvta_generic_to_shared(&Ks[r * KSTR + c0]);
        uint32_t sv = (uint32_t)__cvta_generic_to_shared(&Vs[r * VSTR + c0]);
#pragma unroll
        for (int j = 0; j < 8; j++) {
            cp_async16(sk + j * 16, gk + j * 4);
            cp_async16(sv + j * 16, gv + j * 4);
        }
    }
    cp_commit();

    const int r0 = lane >> 2;
    const int qq = lane & 3;
    const int wrow = wid * 16;

    float oacc[16][4];
#pragma unroll
    for (int i = 0; i < 16; i++)
#pragma unroll
        for (int j = 0; j < 4; j++) oacc[i][j] = 0.f;
    float m0 = -1e30f, m1 = -1e30f, l0 = 0.f, l1 = 0.f;

    for (int t = 0; t < 16; t++) {
        const int st = t & 1;
        cp_wait0();
        __syncthreads();

        if (t < 15) {
            int r = tid >> 2, c0 = (tid & 3) * 32;
            int st2 = st ^ 1;
            const float* gk = kbase + (long long)((t + 1) * BC_ + r) * D_ + c0;
            const float* gv = vbase + (long long)((t + 1) * BC_ + r) * D_ + c0;
            uint32_t sk = (uint32_t)__cvta_generic_to_shared(&Ks[st2 * BC_ * KSTR + r * KSTR + c0]);
            uint32_t sv = (uint32_t)__cvta_generic_to_shared(&Vs[st2 * BC_ * VSTR + r * VSTR + c0]);
#pragma unroll
            for (int j = 0; j < 8; j++) {
                cp_async16(sk + j * 16, gk + j * 4);
                cp_async16(sv + j * 16, gv + j * 4);
            }
            cp_commit();
        }

        // ---- S = Q_w @ K^T ----
        float sacc[8][4];
#pragma unroll
        for (int i = 0; i < 8; i++)
#pragma unroll
            for (int j = 0; j < 4; j++) sacc[i][j] = 0.f;

        const float* Qw = Qs + wrow * QSTR;
        const float* Kt = Ks + st * BC_ * KSTR;
#pragma unroll
        for (int ks = 0; ks < 16; ks++) {
            const int kc = ks * 8 + qq;
            const float* pa = Qw + r0 * QSTR + kc;
            unsigned a0 = __float_as_uint(pa[0]);
            unsigned a1 = __float_as_uint(pa[8 * QSTR]);
            unsigned a2 = __float_as_uint(pa[4]);
            unsigned a3 = __float_as_uint(pa[8 * QSTR + 4]);
#pragma unroll
            for (int ni = 0; ni < 8; ni++) {
                const float* pb = Kt + (ni * 8 + r0) * KSTR + kc;
                mma_tf32(sacc[ni], a0, a1, a2, a3,
                         __float_as_uint(pb[0]), __float_as_uint(pb[4]));
            }
        }

        // ---- online softmax ----
        float rmax0 = -1e30f, rmax1 = -1e30f;
#pragma unroll
        for (int ni = 0; ni < 8; ni++) {
            sacc[ni][0] *= scale; sacc[ni][1] *= scale;
            sacc[ni][2] *= scale; sacc[ni][3] *= scale;
            rmax0 = fmaxf(rmax0, fmaxf(sacc[ni][0], sacc[ni][1]));
            rmax1 = fmaxf(rmax1, fmaxf(sacc[ni][2], sacc[ni][3]));
        }
        rmax0 = fmaxf(rmax0, __shfl_xor_sync(0xffffffffu, rmax0, 1));
        rmax0 = fmaxf(rmax0, __shfl_xor_sync(0xffffffffu, rmax0, 2));
        rmax1 = fmaxf(rmax1, __shfl_xor_sync(0xffffffffu, rmax1, 1));
        rmax1 = fmaxf(rmax1, __shfl_xor_sync(0xffffffffu, rmax1, 2));
        float mn0 = fmaxf(m0, rmax0), mn1 = fmaxf(m1, rmax1);
        float c0 = __expf(m0 - mn0), c1 = __expf(m1 - mn1);
        m0 = mn0; m1 = mn1;
        float rs0 = 0.f, rs1 = 0.f;
#pragma unroll
        for (int ni = 0; ni < 8; ni++) {
            sacc[ni][0] = __expf(sacc[ni][0] - m0);
            sacc[ni][1] = __expf(sacc[ni][1] - m0);
            sacc[ni][2] = __expf(sacc[ni][2] - m1);
            sacc[ni][3] = __expf(sacc[ni][3] - m1);
            rs0 += sacc[ni][0] + sacc[ni][1];
            rs1 += sacc[ni][2] + sacc[ni][3];
        }
        rs0 += __shfl_xor_sync(0xffffffffu, rs0, 1);
        rs0 += __shfl_xor_sync(0xffffffffu, rs0, 2);
        rs1 += __shfl_xor_sync(0xffffffffu, rs1, 1);
        rs1 += __shfl_xor_sync(0xffffffffu, rs1, 2);
        l0 = l0 * c0 + rs0;
        l1 = l1 * c1 + rs1;
#pragma unroll
        for (int ni = 0; ni < 16; ni++) {
            oacc[ni][0] *= c0; oacc[ni][1] *= c0;
            oacc[ni][2] *= c1; oacc[ni][3] *= c1;
        }

        // ---- O += P @ V ----
        const float* Vt = Vs + st * BC_ * VSTR;
        const int srcA = (lane & ~3) | (qq >> 1);
        const int srcB = srcA + 2;
#pragma unroll
        for (int ks = 0; ks < 8; ks++) {
            float x0 = __shfl_sync(0xffffffffu, sacc[ks][0], srcA);
            float x1 = __shfl_sync(0xffffffffu, sacc[ks][1], srcA);
            float a0f = (qq & 1) ? x1 : x0;
            float y0 = __shfl_sync(0xffffffffu, sacc[ks][0], srcB);
            float y1 = __shfl_sync(0xffffffffu, sacc[ks][1], srcB);
            float a2f = (qq & 1) ? y1 : y0;
            x0 = __shfl_sync(0xffffffffu, sacc[ks][2], srcA);
            x1 = __shfl_sync(0xffffffffu, sacc[ks][3], srcA);
            float a1f = (qq & 1) ? x1 : x0;
            y0 = __shfl_sync(0xffffffffu, sacc[ks][2], srcB);
            y1 = __shfl_sync(0xffffffffu, sacc[ks][3], srcB);
            float a3f = (qq & 1) ? y1 : y0;
            unsigned a0 = __float_as_uint(a0f), a1 = __float_as_uint(a1f);
            unsigned a2 = __float_as_uint(a2f), a3 = __float_as_uint(a3f);
#pragma unroll
            for (int ni = 0; ni < 16; ni++) {
                const float* pv = Vt + (ks * 8 + qq) * VSTR + ni * 8 + r0;
                mma_tf32(oacc[ni], a0, a1, a2, a3,
                         __float_as_uint(pv[0]), __float_as_uint(pv[4 * VSTR]));
            }
        }
    }

    // ---- epilogue ----
    float inv0 = 1.f / l0, inv1 = 1.f / l1;
    long long row0 = (long long)(qt * 128 + wrow + r0);
    float* ob = og + (long long)seg * SD_ + row0 * D_ + h * DH_;
#pragma unroll
    for (int ni = 0; ni < 16; ni++) {
        int col = ni * 8 + 2 * qq;
        float2 v0 = make_float2(oacc[ni][0] * inv0, oacc[ni][1] * inv0);
        float2 v1 = make_float2(oacc[ni][2] * inv1, oacc[ni][3] * inv1);
        *(float2*)(ob + col)            = v0;
        *(float2*)(ob + 8LL * D_ + col) = v1;
    }
}

// --------------------------- LayerNorm kernels ------------------------------
// hg[seg][i] = LN(x[idx] + t1[seg][i]) * s[e] + b[e]   (gathered rows)
__global__ void ln1g_kernel(const float* __restrict__ x, const float* __restrict__ t1,
                            const int* __restrict__ idx, const int* __restrict__ cnt,
                            const float* __restrict__ s_all, const float* __restrict__ b_all,
                            float* __restrict__ hg)
{
    int i   = blockIdx.x;
    int seg = blockIdx.y;
    if (i >= cnt[seg]) return;
    int e = seg >> 2;
    int token = idx[seg * S_ + i];
    const float* a    = x  + (size_t)token * D_;
    const float* bsrc = t1 + ((size_t)seg * S_ + i) * D_;
    const float* s    = s_all + (size_t)e * D_;
    const float* bb   = b_all + (size_t)e * D_;
    float* out        = hg + ((size_t)seg * S_ + i) * D_;
    int t = threadIdx.x;
    __shared__ float red[128];
    float v[4];
#pragma unroll
    for (int q = 0; q < 4; q++) {
        int d = t + q * 128;
        v[q] = a[d] + bsrc[d];
    }
    float sum = v[0] + v[1] + v[2] + v[3];
    red[t] = sum; __syncthreads();
    for (int o = 64; o > 0; o >>= 1) { if (t < o) red[t] += red[t + o]; __syncthreads(); }
    float mu = red[0] * (1.f / D_); __syncthreads();
    float sq = 0.f;
#pragma unroll
    for (int q = 0; q < 4; q++) { float d2 = v[q] - mu; sq += d2 * d2; }
    red[t] = sq; __syncthreads();
    for (int o = 64; o > 0; o >>= 1) { if (t < o) red[t] += red[t + o]; __syncthreads(); }
    float inv = rsqrtf(red[0] * (1.f / D_) + LN_EPS);
#pragma unroll
    for (int q = 0; q < 4; q++) {
        int d = t + q * 128;
        out[d] = (v[q] - mu) * inv * s[d] + bb[d];
    }
}

// final[n] = sum_e rw * LN2(hg + f2g)  via pos gather (deterministic)
__global__ void ln2_scatter_kernel(const float* __restrict__ hg, const float* __restrict__ f2g,
                                   const float* __restrict__ s_all, const float* __restrict__ b_all,
                                   const float* __restrict__ rw, const int* __restrict__ pos,
                                   float* __restrict__ finalOut)
{
    int n = blockIdx.x;
    int t = threadIdx.x;
    int b = n >> 10;
    __shared__ float red[128];
    float outv[4] = {0.f, 0.f, 0.f, 0.f};
    for (int e = 0; e < E_; e++) {
        float w = rw[n * E_ + e];
        if (w == 0.f) continue;            // uniform across block
        int seg = e * B_ + b;
        int p = pos[n * E_ + e];
        const float* hp = hg  + ((size_t)seg * S_ + p) * D_;
        const float* fp = f2g + ((size_t)seg * S_ + p) * D_;
        const float* s  = s_all + (size_t)e * D_;
        const float* bb = b_all + (size_t)e * D_;
        float v[4];
#pragma unroll
        for (int q = 0; q < 4; q++) {
            int d = t + q * 128;
            v[q] = hp[d] + fp[d];
        }
        float sum = v[0] + v[1] + v[2] + v[3];
        __syncthreads();
        red[t] = sum; __syncthreads();
        for (int o = 64; o > 0; o >>= 1) { if (t < o) red[t] += red[t + o]; __syncthreads(); }
        float mu = red[0] * (1.f / D_); __syncthreads();
        float sq = 0.f;
#pragma unroll
        for (int q = 0; q < 4; q++) { float d2 = v[q] - mu; sq += d2 * d2; }
        red[t] = sq; __syncthreads();
        for (int o = 64; o > 0; o >>= 1) { if (t < o) red[t] += red[t + o]; __syncthreads(); }
        float inv = rsqrtf(red[0] * (1.f / D_) + LN_EPS);
#pragma unroll
        for (int q = 0; q < 4; q++) {
            int d = t + q * 128;
            outv[q] += w * ((v[q] - mu) * inv * s[d] + bb[d]);
        }
    }
#pragma unroll
    for (int q = 0; q < 4; q++)
        finalOut[(size_t)n * D_ + t + q * 128] = outv[q];
}

// ------------------------------ host glue -----------------------------------
extern "C" void kernel_launch(void* const* d_in, const int* in_sizes, int n_in,
                              void* d_out, int out_size)
{
    const float* x      = (const float*)d_in[0];
    const float* gate_w = (const float*)d_in[1];
    const float* gate_b = (const float*)d_in[2];
    const float* ln1_s  = (const float*)d_in[3];
    const float* ln1_b  = (const float*)d_in[4];
    const float* ln2_s  = (const float*)d_in[5];
    const float* ln2_b  = (const float*)d_in[6];
    const float* wq     = (const float*)d_in[7];
    const float* wk     = (const float*)d_in[8];
    const float* wv     = (const float*)d_in[9];
    const float* wo     = (const float*)d_in[10];
    const float* bq     = (const float*)d_in[11];
    const float* bk     = (const float*)d_in[12];
    const float* bv     = (const float*)d_in[13];
    const float* bo     = (const float*)d_in[14];
    const float* w1     = (const float*)d_in[15];
    const float* b1     = (const float*)d_in[16];
    const float* w2     = (const float*)d_in[17];
    const float* b2     = (const float*)d_in[18];

    float* out_final  = (float*)d_out;
    float* out_logits = out_final + (size_t)N_ * D_;

    float *rw, *kv, *qg, *og, *t1, *hg, *f1, *f2;
    int *cnt, *idx, *pos;
    cudaGetSymbolAddress((void**)&rw,  g_rw);
    cudaGetSymbolAddress((void**)&cnt, g_cnt);
    cudaGetSymbolAddress((void**)&idx, g_idx);
    cudaGetSymbolAddress((void**)&pos, g_pos);
    cudaGetSymbolAddress((void**)&kv,  g_kv);
    cudaGetSymbolAddress((void**)&qg,  g_qg);
    cudaGetSymbolAddress((void**)&og,  g_og);
    cudaGetSymbolAddress((void**)&t1,  g_t1);
    cudaGetSymbolAddress((void**)&hg,  g_hg);
    cudaGetSymbolAddress((void**)&f1,  g_f1);
    cudaGetSymbolAddress((void**)&f2,  g_f2);

    cudaFuncSetAttribute(flash_kernel,
                         cudaFuncAttributeMaxDynamicSharedMemorySize, FLASH_SMEM);

    cudaMemsetAsync(cnt, 0, SEGS * sizeof(int));
    cudaMemsetAsync(idx, 0, SEGS * S_ * sizeof(int));

    router_kernel<<<N_ / 8, 256>>>(x, gate_w, gate_b, out_logits, rw);
    build_lists_kernel<<<N_ / 256, 256>>>(rw);

    // K projection (dense, all experts): z = e
    {
        dim3 grid(D_ / 128, N_ / 128, E_);
        tf32_gemm<false><<<grid, 256>>>(
            x, wk, kv, bk,
            D_, D_, D_, D_,
            1, 0, 0, DD_, 0, 2 * ND_, 0, D_,
            nullptr, nullptr);
    }
    // V projection (dense): z = e
    {
        dim3 grid(D_ / 128, N_ / 128, E_);
        tf32_gemm<false><<<grid, 256>>>(
            x, wv, kv + ND_, bv,
            D_, D_, D_, D_,
            1, 0, 0, DD_, 0, 2 * ND_, 0, D_,
            nullptr, nullptr);
    }
    // Q projection (gathered): z = seg = e*4+b, A rows via idx
    {
        dim3 grid(D_ / 128, S_ / 128, SEGS);
        tf32_gemm<false><<<grid, 256>>>(
            x, wq, qg, bq,
            D_, D_, D_, D_,
            B_, 0, 0, DD_, 0, (long long)B_ * SD_, SD_, D_,
            cnt, idx);
    }

    // fused attention on gathered Q tiles
    {
        dim3 grid(S_ / 128, SEGS * H_);
        flash_kernel<<<grid, 256, FLASH_SMEM>>>(qg, kv, cnt, og);
    }

    // O projection (gathered rows): z = seg
    {
        dim3 grid(D_ / 128, S_ / 128, SEGS);
        tf32_gemm<false><<<grid, 256>>>(
            og, wo, t1, bo,
            D_, D_, D_, D_,
            B_, (long long)B_ * SD_, SD_, DD_, 0, (long long)B_ * SD_, SD_, D_,
            cnt, nullptr);
    }

    // LN1 on gathered rows
    {
        dim3 grid(S_, SEGS);
        ln1g_kernel<<<grid, 128>>>(x, t1, idx, cnt, ln1_s, ln1_b, hg);
    }

    // FFN1 (gathered): z = seg
    {
        dim3 grid(F_ / 128, S_ / 128, SEGS);
        tf32_gemm<true><<<grid, 256>>>(
            hg, w1, f1, b1,
            D_, D_, F_, F_,
            B_, (long long)B_ * SD_, SD_, (long long)D_ * F_, 0,
            (long long)B_ * SF_, SF_, F_,
            cnt, nullptr);
    }

    // FFN2 (gathered): z = seg
    {
        dim3 grid(D_ / 128, S_ / 128, SEGS);
        tf32_gemm<false><<<grid, 256>>>(
            f1, w2, f2, b2,
            F_, F_, D_, D_,
            B_, (long long)B_ * SF_, SF_, (long long)F_ * D_, 0,
            (long long)B_ * SD_, SD_, D_,
            cnt, nullptr);
    }

    // final = sum_e rw * LN2(hg + f2)  (dense over tokens, pos-gather)
    ln2_scatter_kernel<<<N_, 128>>>(hg, f2, ln2_s, ln2_b, rw, pos, out_final);
}

// round 6
// speedup vs baseline: 15.9707x; 1.5503x over previous
#include <cuda_runtime.h>
#include <cuda_fp16.h>
#include <cstdint>

// ---------------------------------------------------------------------------
// SEMMBlock: spiking-router MoE transformer block.
// B=4 S=1024 D=512 E=8 F=2048 H=4 dh=128.
// Round 6: fp16 tensor cores (m16n8k16, fp32 accum) everywhere, transposed
// fp16 weights, 3-stage cp.async GEMM, fp16 flash attention (2 CTA/SM).
// ---------------------------------------------------------------------------

#define B_  4
#define S_  1024
#define D_  512
#define E_  8
#define F_  2048
#define H_  4
#define DH_ 128
#define N_  (B_ * S_)          // 4096 tokens
#define SEGS (E_ * B_)         // 32 (expert, batch) segments
#define LN_EPS 1e-5f

#define DD_  (D_ * D_)
#define ND_  ((long long)N_ * D_)
#define SD_  ((long long)S_ * D_)
#define SF_  ((long long)S_ * F_)

// ------------------------- scratch (device globals) ------------------------
__device__ float  g_rw[N_ * E_];
__device__ int    g_cnt[SEGS];
__device__ int    g_idx[SEGS * S_];
__device__ int    g_pos[N_ * E_];
__device__ __half g_xh[N_ * D_];
__device__ __half g_wqh[E_ * DD_];
__device__ __half g_wkh[E_ * DD_];
__device__ __half g_wvh[E_ * DD_];
__device__ __half g_woh[E_ * DD_];
__device__ __half g_w1h[(size_t)E_ * D_ * F_];
__device__ __half g_w2h[(size_t)E_ * F_ * D_];
__device__ __half g_kvh[(size_t)E_ * 2 * N_ * D_];
__device__ __half g_qh[(size_t)SEGS * S_ * D_];
__device__ __half g_ogh[(size_t)SEGS * S_ * D_];
__device__ __half g_hgh[(size_t)SEGS * S_ * D_];
__device__ __half g_f1h[(size_t)SEGS * S_ * F_];
__device__ float  g_t1[(size_t)SEGS * S_ * D_];
__device__ float  g_hg[(size_t)SEGS * S_ * D_];
__device__ float  g_f2[(size_t)SEGS * S_ * D_];

// ------------------------------ helpers -------------------------------------
__device__ __forceinline__ void cp_async16(uint32_t smem, const void* gptr) {
    asm volatile("cp.async.cg.shared.global [%0], [%1], 16;\n" :: "r"(smem), "l"(gptr));
}
__device__ __forceinline__ void cp_commit() {
    asm volatile("cp.async.commit_group;\n");
}
__device__ __forceinline__ void cp_wait0() {
    asm volatile("cp.async.wait_group 0;\n");
}
__device__ __forceinline__ void cp_wait1() {
    asm volatile("cp.async.wait_group 1;\n");
}
__device__ __forceinline__ void mma_f16(float* c, unsigned a0, unsigned a1,
                                        unsigned a2, unsigned a3,
                                        unsigned b0, unsigned b1) {
    asm volatile(
        "mma.sync.aligned.m16n8k16.row.col.f32.f16.f16.f32 "
        "{%0,%1,%2,%3}, {%4,%5,%6,%7}, {%8,%9}, {%0,%1,%2,%3};\n"
        : "+f"(c[0]), "+f"(c[1]), "+f"(c[2]), "+f"(c[3])
        : "r"(a0), "r"(a1), "r"(a2), "r"(a3), "r"(b0), "r"(b1));
}
__device__ __forceinline__ unsigned h2pack(float x, float y) {
    __half2 h = __floats2half2_rn(x, y);
    return *(unsigned*)&h;
}

// ------------------------------- router -------------------------------------
__global__ void router_kernel(const float* __restrict__ x,
                              const float* __restrict__ gw,
                              const float* __restrict__ gb,
                              float* __restrict__ logits,
                              float* __restrict__ rw)
{
    int warp = (blockIdx.x * blockDim.x + threadIdx.x) >> 5;
    int lane = threadIdx.x & 31;
    if (warp >= N_) return;
    const float* xr = x + (size_t)warp * D_;
    float acc[E_];
#pragma unroll
    for (int e = 0; e < E_; e++) acc[e] = 0.f;
    for (int i = lane; i < D_; i += 32) {
        float xv = xr[i];
        const float* g = gw + i * E_;
#pragma unroll
        for (int e = 0; e < E_; e++) acc[e] += xv * g[e];
    }
#pragma unroll
    for (int e = 0; e < E_; e++) {
#pragma unroll
        for (int o = 16; o > 0; o >>= 1)
            acc[e] += __shfl_down_sync(0xffffffffu, acc[e], o);
    }
    if (lane == 0) {
        float lg[E_];
#pragma unroll
        for (int e = 0; e < E_; e++) {
            lg[e] = acc[e] + gb[e];
            logits[warp * E_ + e] = lg[e];
        }
        int i1 = 0;
#pragma unroll
        for (int e = 1; e < E_; e++) if (lg[e] > lg[i1]) i1 = e;
        int i2 = -1;
#pragma unroll
        for (int e = 0; e < E_; e++) {
            if (e == i1) continue;
            if (i2 < 0 || lg[e] > lg[i2]) i2 = e;
        }
#pragma unroll
        for (int e = 0; e < E_; e++) {
            float r = 0.f;
            if (e == i1 || e == i2) {
                float mem = lg[e] > 0.f ? lg[e] : 0.f;
#pragma unroll
                for (int lvl = 0; lvl < 4; lvl++) {
                    float thr = 4.0f / (float)(1 << lvl);
                    if (mem >= thr) { r += thr; mem -= thr; }
                }
            }
            rw[warp * E_ + e] = r;
        }
    }
}

// -------------------------- build gather lists -------------------------------
__global__ void build_lists_kernel(const float* __restrict__ rw)
{
    int n = blockIdx.x * blockDim.x + threadIdx.x;
    if (n >= N_) return;
    int b = n >> 10;
#pragma unroll
    for (int e = 0; e < E_; e++) {
        if (rw[n * E_ + e] != 0.f) {
            int seg = e * B_ + b;
            int i = atomicAdd(&g_cnt[seg], 1);
            g_idx[seg * S_ + i] = n;
            g_pos[n * E_ + e] = i;
        }
    }
}

// ----------------------------- conversions -----------------------------------
__global__ void xconv_kernel(const float* __restrict__ x, __half* __restrict__ xh)
{
    int i = (blockIdx.x * blockDim.x + threadIdx.x) * 4;
    float4 v = *(const float4*)(x + i);
    __half2 h0 = __floats2half2_rn(v.x, v.y);
    __half2 h1 = __floats2half2_rn(v.z, v.w);
    *(__half2*)(xh + i)     = h0;
    *(__half2*)(xh + i + 2) = h1;
}

// W fp32 [e][K][Nc] -> Wh fp16 [e][Nc][K]  (transposed)
__global__ void wconv_kernel(const float* __restrict__ W, __half* __restrict__ Wh,
                             int K, int Nc)
{
    __shared__ float tile[32][33];
    int e  = blockIdx.z;
    const float* Wp = W + (long long)e * K * Nc;
    __half* Whp = Wh + (long long)e * K * Nc;
    int n0 = blockIdx.x * 32, k0 = blockIdx.y * 32;
    int tx = threadIdx.x, ty = threadIdx.y;     // (32, 8)
#pragma unroll
    for (int j = 0; j < 4; j++)
        tile[ty + 8 * j][tx] = Wp[(long long)(k0 + ty + 8 * j) * Nc + n0 + tx];
    __syncthreads();
#pragma unroll
    for (int j = 0; j < 4; j++)
        Whp[(long long)(n0 + ty + 8 * j) * K + k0 + tx] =
            __float2half_rn(tile[tx][ty + 8 * j]);
}

// --------------------------- fp16 tensor GEMM --------------------------------
// C = A[.,K] @ B[N][K]^T + bias (relu). A,B fp16; accum fp32.
// BM=BN=128, BK=32, 256 thr, 8 warps of 64x32. 3-stage cp.async pipeline.
// z -> (z0=z/div1, z1=z%div1). Optional outputs Ch (fp16) / Cf (fp32),
// A-row gather (gidx), per-z row-count early exit (mlim).
#define HAPAD 40        // halfs per smem row (32 data + 8 pad)
#define HGEMM_SMEM (3 * 2 * 128 * HAPAD * 2)

template <bool RELU>
__global__ __launch_bounds__(256, 2) void hgemm(
    const __half* __restrict__ A, const __half* __restrict__ Bp,
    __half* __restrict__ Ch, float* __restrict__ Cf,
    const float* __restrict__ bias,
    int K, int lda, int ldb, int ldc,
    int div1,
    long long sA0, long long sA1,
    long long sB0, long long sB1,
    long long sC0, long long sC1,
    long long sb0,
    const int* __restrict__ mlim, const int* __restrict__ gidx)
{
    const int z  = blockIdx.z;
    const int bm = blockIdx.y * 128;
    if (mlim && bm >= mlim[z]) return;
    const int z0 = z / div1, z1 = z - z0 * div1;
    A  += z0 * sA0 + z1 * sA1;
    Bp += z0 * sB0 + z1 * sB1;
    const long long coff = z0 * sC0 + z1 * sC1;
    const float* biasp = bias + z0 * sb0;

    extern __shared__ __half hsm[];
    __half* As = hsm;                        // [3][128*HAPAD]
    __half* Bs = hsm + 3 * 128 * HAPAD;

    const int tid  = threadIdx.x;
    const int lane = tid & 31;
    const int wid  = tid >> 5;
    const int warpM = (wid >> 2) * 64;
    const int warpN = (wid & 3) * 32;
    const int bn = blockIdx.x * 128;

    const int srow = tid >> 1;               // 0..127
    const int sch  = (tid & 1) * 16;         // half offset 0 or 16

    long long arow = bm + srow;
    if (gidx) arow = gidx[(long long)z * S_ + arow];
    const __half* gA = A + arow * lda + sch;
    const __half* gB = Bp + (long long)(bn + srow) * ldb + sch;
    uint32_t sA = (uint32_t)__cvta_generic_to_shared(As + srow * HAPAD + sch);
    uint32_t sB = (uint32_t)__cvta_generic_to_shared(Bs + srow * HAPAD + sch);
    const uint32_t stg = 128 * HAPAD * 2;    // stage bytes

    float acc[4][4][4];
#pragma unroll
    for (int i = 0; i < 4; i++)
#pragma unroll
        for (int j = 0; j < 4; j++)
#pragma unroll
            for (int q = 0; q < 4; q++) acc[i][j][q] = 0.f;

    // prologue: stages 0,1
    cp_async16(sA,      gA);
    cp_async16(sA + 16, gA + 8);
    cp_async16(sB,      gB);
    cp_async16(sB + 16, gB + 8);
    cp_commit();
    cp_async16(sA + stg,      gA + 32);
    cp_async16(sA + stg + 16, gA + 40);
    cp_async16(sB + stg,      gB + 32);
    cp_async16(sB + stg + 16, gB + 40);
    cp_commit();

    const int mrow = warpM + (lane >> 2);
    const int ncol = warpN + (lane >> 2);
    const int qq2  = (lane & 3) * 2;

    int it = 0;
    for (int k0 = 0; k0 < K; k0 += 32, it++) {
        const int st = it % 3;
        cp_wait1();
        __syncthreads();

        if (k0 + 64 < K) {
            const int sp = (it + 2) % 3;
            const __half* gA2 = gA + k0 + 64;
            const __half* gB2 = gB + k0 + 64;
            cp_async16(sA + sp * stg,      gA2);
            cp_async16(sA + sp * stg + 16, gA2 + 8);
            cp_async16(sB + sp * stg,      gB2);
            cp_async16(sB + sp * stg + 16, gB2 + 8);
        }
        cp_commit();

        const __half* As0 = As + st * 128 * HAPAD;
        const __half* Bs0 = Bs + st * 128 * HAPAD;

#pragma unroll
        for (int ks = 0; ks < 2; ks++) {
            const int kb = ks * 16 + qq2;
            unsigned af[4][4], bf[4][2];
#pragma unroll
            for (int mi = 0; mi < 4; mi++) {
                const __half* pa = As0 + (mrow + mi * 16) * HAPAD + kb;
                af[mi][0] = *(const unsigned*)(pa);
                af[mi][1] = *(const unsigned*)(pa + 8 * HAPAD);
                af[mi][2] = *(const unsigned*)(pa + 8);
                af[mi][3] = *(const unsigned*)(pa + 8 * HAPAD + 8);
            }
#pragma unroll
            for (int ni = 0; ni < 4; ni++) {
                const __half* pb = Bs0 + (ncol + ni * 8) * HAPAD + kb;
                bf[ni][0] = *(const unsigned*)(pb);
                bf[ni][1] = *(const unsigned*)(pb + 8);
            }
#pragma unroll
            for (int mi = 0; mi < 4; mi++)
#pragma unroll
                for (int ni = 0; ni < 4; ni++)
                    mma_f16(acc[mi][ni], af[mi][0], af[mi][1], af[mi][2], af[mi][3],
                            bf[ni][0], bf[ni][1]);
        }
    }

    // epilogue
#pragma unroll
    for (int mi = 0; mi < 4; mi++) {
        long long row0 = bm + warpM + mi * 16 + (lane >> 2);
#pragma unroll
        for (int ni = 0; ni < 4; ni++) {
            int col = bn + warpN + ni * 8 + qq2;
            float b0 = biasp[col], b1 = biasp[col + 1];
            float v0 = acc[mi][ni][0] + b0;
            float v1 = acc[mi][ni][1] + b1;
            float v2 = acc[mi][ni][2] + b0;
            float v3 = acc[mi][ni][3] + b1;
            if (RELU) {
                v0 = fmaxf(v0, 0.f); v1 = fmaxf(v1, 0.f);
                v2 = fmaxf(v2, 0.f); v3 = fmaxf(v3, 0.f);
            }
            if (Ch) {
                *(__half2*)(Ch + coff + row0 * ldc + col)       = __floats2half2_rn(v0, v1);
                *(__half2*)(Ch + coff + (row0 + 8) * ldc + col) = __floats2half2_rn(v2, v3);
            }
            if (Cf) {
                *(float2*)(Cf + coff + row0 * ldc + col)       = make_float2(v0, v1);
                *(float2*)(Cf + coff + (row0 + 8) * ldc + col) = make_float2(v2, v3);
            }
        }
    }
}

// ------------------------- fused flash attention (fp16) ----------------------
// Block: 128 gathered Q rows of one (seg, h). 256 thr, 8 warps, 16 rows/warp.
// KV tiles of 64 keys, double-buffered. fp32 online softmax; P->a-frag is a
// per-thread half2 pack (no shuffles). V b-frags via ldmatrix.x2.trans.
#define BC_   64
#define FSTR  136   // halfs per smem row
#define FLASH_SMEM ((128 * FSTR + 2 * BC_ * FSTR + 2 * BC_ * FSTR) * 2)

__global__ __launch_bounds__(256, 2) void flash_kernel(const __half* __restrict__ qh,
                                                       const __half* __restrict__ kvh,
                                                       const int* __restrict__ cnt,
                                                       __half* __restrict__ ogh)
{
    const int qt  = blockIdx.x;                // Q tile 0..7
    const int seg = blockIdx.y >> 2;
    const int h   = blockIdx.y & 3;
    if (qt * 128 >= cnt[seg]) return;
    const int e = seg >> 2;
    const int b = seg & 3;

    extern __shared__ __half fsm[];
    __half* Qs = fsm;
    __half* Ks = fsm + 128 * FSTR;
    __half* Vs = Ks + 2 * BC_ * FSTR;

    const int tid  = threadIdx.x;
    const int lane = tid & 31;
    const int wid  = tid >> 5;
    const float scale = 0.08838834764831845f;  // 1/sqrt(128)

    const __half* qbase = qh + (long long)seg * SD_ + (long long)(qt * 128) * D_ + h * DH_;
    const __half* kbase = kvh + (long long)e * 2 * ND_ + (long long)(b * S_) * D_ + h * DH_;
    const __half* vbase = kbase + ND_;

    // ---- stage Q tile (128 rows x 128 halfs) ----
    {
        int r = tid >> 1, c0 = (tid & 1) * 64;
        const __half* g = qbase + (long long)r * D_ + c0;
        uint32_t s = (uint32_t)__cvta_generic_to_shared(Qs + r * FSTR + c0);
#pragma unroll
        for (int j = 0; j < 8; j++) cp_async16(s + j * 16, g + j * 8);
    }
    // ---- stage KV tile 0 ----
    {
        int r = tid >> 2, c0 = (tid & 3) * 32;
        const __half* gk = kbase + (long long)r * D_ + c0;
        const __half* gv = vbase + (long long)r * D_ + c0;
        uint32_t sk = (uint32_t)__cvta_generic_to_shared(Ks + r * FSTR + c0);
        uint32_t sv = (uint32_t)__cvta_generic_to_shared(Vs + r * FSTR + c0);
#pragma unroll
        for (int j = 0; j < 4; j++) {
            cp_async16(sk + j * 16, gk + j * 8);
            cp_async16(sv + j * 16, gv + j * 8);
        }
    }
    cp_commit();

    const int r0  = lane >> 2;
    const int qq2 = (lane & 3) * 2;
    const int wrow = wid * 16;

    float oacc[16][4];
#pragma unroll
    for (int i = 0; i < 16; i++)
#pragma unroll
        for (int j = 0; j < 4; j++) oacc[i][j] = 0.f;
    float m0 = -1e30f, m1 = -1e30f, l0 = 0.f, l1 = 0.f;

    for (int t = 0; t < 16; t++) {
        const int st = t & 1;
        cp_wait0();
        __syncthreads();

        if (t < 15) {
            int r = tid >> 2, c0 = (tid & 3) * 32;
            int st2 = st ^ 1;
            const __half* gk = kbase + (long long)((t + 1) * BC_ + r) * D_ + c0;
            const __half* gv = vbase + (long long)((t + 1) * BC_ + r) * D_ + c0;
            uint32_t sk = (uint32_t)__cvta_generic_to_shared(Ks + st2 * BC_ * FSTR + r * FSTR + c0);
            uint32_t sv = (uint32_t)__cvta_generic_to_shared(Vs + st2 * BC_ * FSTR + r * FSTR + c0);
#pragma unroll
            for (int j = 0; j < 4; j++) {
                cp_async16(sk + j * 16, gk + j * 8);
                cp_async16(sv + j * 16, gv + j * 8);
            }
            cp_commit();
        }

        // ---- S = Q_w @ K^T (16 x 64, k = 128 dh) ----
        float sacc[8][4];
#pragma unroll
        for (int i = 0; i < 8; i++)
#pragma unroll
            for (int j = 0; j < 4; j++) sacc[i][j] = 0.f;

        const __half* Qw = Qs + (wrow + r0) * FSTR;
        const __half* Kt = Ks + st * BC_ * FSTR;
#pragma unroll
        for (int ks = 0; ks < 8; ks++) {
            const int kb = ks * 16 + qq2;
            const __half* pa = Qw + kb;
            unsigned a0 = *(const unsigned*)(pa);
            unsigned a1 = *(const unsigned*)(pa + 8 * FSTR);
            unsigned a2 = *(const unsigned*)(pa + 8);
            unsigned a3 = *(const unsigned*)(pa + 8 * FSTR + 8);
#pragma unroll
            for (int ni = 0; ni < 8; ni++) {
                const __half* pb = Kt + (ni * 8 + r0) * FSTR + kb;
                mma_f16(sacc[ni], a0, a1, a2, a3,
                        *(const unsigned*)(pb), *(const unsigned*)(pb + 8));
            }
        }

        // ---- online softmax (fp32) ----
        float rmax0 = -1e30f, rmax1 = -1e30f;
#pragma unroll
        for (int ni = 0; ni < 8; ni++) {
            sacc[ni][0] *= scale; sacc[ni][1] *= scale;
            sacc[ni][2] *= scale; sacc[ni][3] *= scale;
            rmax0 = fmaxf(rmax0, fmaxf(sacc[ni][0], sacc[ni][1]));
            rmax1 = fmaxf(rmax1, fmaxf(sacc[ni][2], sacc[ni][3]));
        }
        rmax0 = fmaxf(rmax0, __shfl_xor_sync(0xffffffffu, rmax0, 1));
        rmax0 = fmaxf(rmax0, __shfl_xor_sync(0xffffffffu, rmax0, 2));
        rmax1 = fmaxf(rmax1, __shfl_xor_sync(0xffffffffu, rmax1, 1));
        rmax1 = fmaxf(rmax1, __shfl_xor_sync(0xffffffffu, rmax1, 2));
        float mn0 = fmaxf(m0, rmax0), mn1 = fmaxf(m1, rmax1);
        float c0 = __expf(m0 - mn0), c1 = __expf(m1 - mn1);
        m0 = mn0; m1 = mn1;
        float rs0 = 0.f, rs1 = 0.f;
#pragma unroll
        for (int ni = 0; ni < 8; ni++) {
            sacc[ni][0] = __expf(sacc[ni][0] - m0);
            sacc[ni][1] = __expf(sacc[ni][1] - m0);
            sacc[ni][2] = __expf(sacc[ni][2] - m1);
            sacc[ni][3] = __expf(sacc[ni][3] - m1);
            rs0 += sacc[ni][0] + sacc[ni][1];
            rs1 += sacc[ni][2] + sacc[ni][3];
        }
        rs0 += __shfl_xor_sync(0xffffffffu, rs0, 1);
        rs0 += __shfl_xor_sync(0xffffffffu, rs0, 2);
        rs1 += __shfl_xor_sync(0xffffffffu, rs1, 1);
        rs1 += __shfl_xor_sync(0xffffffffu, rs1, 2);
        l0 = l0 * c0 + rs0;
        l1 = l1 * c1 + rs1;
#pragma unroll
        for (int ni = 0; ni < 16; ni++) {
            oacc[ni][0] *= c0; oacc[ni][1] *= c0;
            oacc[ni][2] *= c1; oacc[ni][3] *= c1;
        }

        // ---- O += P @ V  (P c-frag -> a-frag = per-thread half2 pack) ----
        const __half* Vt = Vs + st * BC_ * FSTR;
#pragma unroll
        for (int ks = 0; ks < 4; ks++) {
            unsigned a0 = h2pack(sacc[2 * ks][0],     sacc[2 * ks][1]);
            unsigned a1 = h2pack(sacc[2 * ks][2],     sacc[2 * ks][3]);
            unsigned a2 = h2pack(sacc[2 * ks + 1][0], sacc[2 * ks + 1][1]);
            unsigned a3 = h2pack(sacc[2 * ks + 1][2], sacc[2 * ks + 1][3]);
            uint32_t vrow = (uint32_t)__cvta_generic_to_shared(
                Vt + (16 * ks + (lane & 15)) * FSTR);
#pragma unroll
            for (int ni = 0; ni < 16; ni++) {
                unsigned b0, b1;
                asm volatile(
                    "ldmatrix.sync.aligned.m8n8.x2.trans.shared.b16 {%0,%1}, [%2];\n"
                    : "=r"(b0), "=r"(b1) : "r"(vrow + ni * 16));
                mma_f16(oacc[ni], a0, a1, a2, a3, b0, b1);
            }
        }
    }

    // ---- epilogue: O /= l, store fp16 ----
    float inv0 = 1.f / l0, inv1 = 1.f / l1;
    long long row0 = (long long)(qt * 128 + wrow + r0);
    __half* ob = ogh + (long long)seg * SD_ + row0 * D_ + h * DH_;
#pragma unroll
    for (int ni = 0; ni < 16; ni++) {
        int col = ni * 8 + qq2;
        *(__half2*)(ob + col)            = __floats2half2_rn(oacc[ni][0] * inv0, oacc[ni][1] * inv0);
        *(__half2*)(ob + 8LL * D_ + col) = __floats2half2_rn(oacc[ni][2] * inv1, oacc[ni][3] * inv1);
    }
}

// --------------------------- LayerNorm kernels ------------------------------
// hg[seg][i] = LN(x[idx] + t1[seg][i]) * s[e] + b[e];  writes fp32 + fp16
__global__ void ln1g_kernel(const float* __restrict__ x, const float* __restrict__ t1,
                            const int* __restrict__ idx, const int* __restrict__ cnt,
                            const float* __restrict__ s_all, const float* __restrict__ b_all,
                            float* __restrict__ hg, __half* __restrict__ hgh)
{
    int i   = blockIdx.x;
    int seg = blockIdx.y;
    if (i >= cnt[seg]) return;
    int e = seg >> 2;
    int token = idx[seg * S_ + i];
    const float* a    = x  + (size_t)token * D_;
    const float* bsrc = t1 + ((size_t)seg * S_ + i) * D_;
    const float* s    = s_all + (size_t)e * D_;
    const float* bb   = b_all + (size_t)e * D_;
    float*  outf = hg  + ((size_t)seg * S_ + i) * D_;
    __half* outh = hgh + ((size_t)seg * S_ + i) * D_;
    int t = threadIdx.x;
    __shared__ float red[128];
    float v[4];
#pragma unroll
    for (int q = 0; q < 4; q++) {
        int d = t + q * 128;
        v[q] = a[d] + bsrc[d];
    }
    float sum = v[0] + v[1] + v[2] + v[3];
    red[t] = sum; __syncthreads();
    for (int o = 64; o > 0; o >>= 1) { if (t < o) red[t] += red[t + o]; __syncthreads(); }
    float mu = red[0] * (1.f / D_); __syncthreads();
    float sq = 0.f;
#pragma unroll
    for (int q = 0; q < 4; q++) { float d2 = v[q] - mu; sq += d2 * d2; }
    red[t] = sq; __syncthreads();
    for (int o = 64; o > 0; o >>= 1) { if (t < o) red[t] += red[t + o]; __syncthreads(); }
    float inv = rsqrtf(red[0] * (1.f / D_) + LN_EPS);
#pragma unroll
    for (int q = 0; q < 4; q++) {
        int d = t + q * 128;
        float y = (v[q] - mu) * inv * s[d] + bb[d];
        outf[d] = y;
        outh[d] = __float2half_rn(y);
    }
}

// final[n] = sum_e rw * LN2(hg + f2) via pos gather
__global__ void ln2_scatter_kernel(const float* __restrict__ hg, const float* __restrict__ f2g,
                                   const float* __restrict__ s_all, const float* __restrict__ b_all,
                                   const float* __restrict__ rw, const int* __restrict__ pos,
                                   float* __restrict__ finalOut)
{
    int n = blockIdx.x;
    int t = threadIdx.x;
    int b = n >> 10;
    __shared__ float red[128];
    float outv[4] = {0.f, 0.f, 0.f, 0.f};
    for (int e = 0; e < E_; e++) {
        float w = rw[n * E_ + e];
        if (w == 0.f) continue;            // uniform across block
        int seg = e * B_ + b;
        int p = pos[n * E_ + e];
        const float* hp = hg  + ((size_t)seg * S_ + p) * D_;
        const float* fp = f2g + ((size_t)seg * S_ + p) * D_;
        const float* s  = s_all + (size_t)e * D_;
        const float* bb = b_all + (size_t)e * D_;
        float v[4];
#pragma unroll
        for (int q = 0; q < 4; q++) {
            int d = t + q * 128;
            v[q] = hp[d] + fp[d];
        }
        float sum = v[0] + v[1] + v[2] + v[3];
        __syncthreads();
        red[t] = sum; __syncthreads();
        for (int o = 64; o > 0; o >>= 1) { if (t < o) red[t] += red[t + o]; __syncthreads(); }
        float mu = red[0] * (1.f / D_); __syncthreads();
        float sq = 0.f;
#pragma unroll
        for (int q = 0; q < 4; q++) { float d2 = v[q] - mu; sq += d2 * d2; }
        red[t] = sq; __syncthreads();
        for (int o = 64; o > 0; o >>= 1) { if (t < o) red[t] += red[t + o]; __syncthreads(); }
        float inv = rsqrtf(red[0] * (1.f / D_) + LN_EPS);
#pragma unroll
        for (int q = 0; q < 4; q++) {
            int d = t + q * 128;
            outv[q] += w * ((v[q] - mu) * inv * s[d] + bb[d]);
        }
    }
#pragma unroll
    for (int q = 0; q < 4; q++)
        finalOut[(size_t)n * D_ + t + q * 128] = outv[q];
}

// ------------------------------ host glue -----------------------------------
extern "C" void kernel_launch(void* const* d_in, const int* in_sizes, int n_in,
                              void* d_out, int out_size)
{
    const float* x      = (const float*)d_in[0];
    const float* gate_w = (const float*)d_in[1];
    const float* gate_b = (const float*)d_in[2];
    const float* ln1_s  = (const float*)d_in[3];
    const float* ln1_b  = (const float*)d_in[4];
    const float* ln2_s  = (const float*)d_in[5];
    const float* ln2_b  = (const float*)d_in[6];
    const float* wq     = (const float*)d_in[7];
    const float* wk     = (const float*)d_in[8];
    const float* wv     = (const float*)d_in[9];
    const float* wo     = (const float*)d_in[10];
    const float* bq     = (const float*)d_in[11];
    const float* bk     = (const float*)d_in[12];
    const float* bv     = (const float*)d_in[13];
    const float* bo     = (const float*)d_in[14];
    const float* w1     = (const float*)d_in[15];
    const float* b1     = (const float*)d_in[16];
    const float* w2     = (const float*)d_in[17];
    const float* b2     = (const float*)d_in[18];

    float* out_final  = (float*)d_out;
    float* out_logits = out_final + (size_t)N_ * D_;

    float *rw, *t1, *hg, *f2;
    int *cnt, *idx, *pos;
    __half *xh, *wqh, *wkh, *wvh, *woh, *w1h, *w2h, *kvh, *qh, *ogh, *hgh, *f1h;
    cudaGetSymbolAddress((void**)&rw,  g_rw);
    cudaGetSymbolAddress((void**)&cnt, g_cnt);
    cudaGetSymbolAddress((void**)&idx, g_idx);
    cudaGetSymbolAddress((void**)&pos, g_pos);
    cudaGetSymbolAddress((void**)&xh,  g_xh);
    cudaGetSymbolAddress((void**)&wqh, g_wqh);
    cudaGetSymbolAddress((void**)&wkh, g_wkh);
    cudaGetSymbolAddress((void**)&wvh, g_wvh);
    cudaGetSymbolAddress((void**)&woh, g_woh);
    cudaGetSymbolAddress((void**)&w1h, g_w1h);
    cudaGetSymbolAddress((void**)&w2h, g_w2h);
    cudaGetSymbolAddress((void**)&kvh, g_kvh);
    cudaGetSymbolAddress((void**)&qh,  g_qh);
    cudaGetSymbolAddress((void**)&ogh, g_ogh);
    cudaGetSymbolAddress((void**)&hgh, g_hgh);
    cudaGetSymbolAddress((void**)&f1h, g_f1h);
    cudaGetSymbolAddress((void**)&t1,  g_t1);
    cudaGetSymbolAddress((void**)&hg,  g_hg);
    cudaGetSymbolAddress((void**)&f2,  g_f2);

    cudaFuncSetAttribute(flash_kernel,
                         cudaFuncAttributeMaxDynamicSharedMemorySize, FLASH_SMEM);
    cudaFuncSetAttribute(hgemm<false>,
                         cudaFuncAttributeMaxDynamicSharedMemorySize, HGEMM_SMEM);
    cudaFuncSetAttribute(hgemm<true>,
                         cudaFuncAttributeMaxDynamicSharedMemorySize, HGEMM_SMEM);

    cudaMemsetAsync(cnt, 0, SEGS * sizeof(int));
    cudaMemsetAsync(idx, 0, SEGS * S_ * sizeof(int));

    router_kernel<<<N_ / 8, 256>>>(x, gate_w, gate_b, out_logits, rw);
    build_lists_kernel<<<N_ / 256, 256>>>(rw);

    // conversions
    xconv_kernel<<<(N_ * D_) / 1024, 256>>>(x, xh);
    {
        dim3 blk(32, 8);
        wconv_kernel<<<dim3(16, 16, E_), blk>>>(wq, wqh, D_, D_);
        wconv_kernel<<<dim3(16, 16, E_), blk>>>(wk, wkh, D_, D_);
        wconv_kernel<<<dim3(16, 16, E_), blk>>>(wv, wvh, D_, D_);
        wconv_kernel<<<dim3(16, 16, E_), blk>>>(wo, woh, D_, D_);
        wconv_kernel<<<dim3(F_ / 32, 16, E_), blk>>>(w1, w1h, D_, F_);
        wconv_kernel<<<dim3(16, F_ / 32, E_), blk>>>(w2, w2h, F_, D_);
    }

    // K projection (dense): z = e
    {
        dim3 grid(D_ / 128, N_ / 128, E_);
        hgemm<false><<<grid, 256, HGEMM_SMEM>>>(
            xh, wkh, kvh, nullptr, bk,
            D_, D_, D_, D_,
            1, 0, 0, DD_, 0, 2 * ND_, 0, D_,
            nullptr, nullptr);
    }
    // V projection (dense): z = e
    {
        dim3 grid(D_ / 128, N_ / 128, E_);
        hgemm<false><<<grid, 256, HGEMM_SMEM>>>(
            xh, wvh, kvh + ND_, nullptr, bv,
            D_, D_, D_, D_,
            1, 0, 0, DD_, 0, 2 * ND_, 0, D_,
            nullptr, nullptr);
    }
    // Q projection (gathered): z = seg
    {
        dim3 grid(D_ / 128, S_ / 128, SEGS);
        hgemm<false><<<grid, 256, HGEMM_SMEM>>>(
            xh, wqh, qh, nullptr, bq,
            D_, D_, D_, D_,
            B_, 0, 0, DD_, 0, (long long)B_ * SD_, SD_, D_,
            cnt, idx);
    }

    // fused attention
    {
        dim3 grid(S_ / 128, SEGS * H_);
        flash_kernel<<<grid, 256, FLASH_SMEM>>>(qh, kvh, cnt, ogh);
    }

    // O projection -> t1 (fp32): z = seg
    {
        dim3 grid(D_ / 128, S_ / 128, SEGS);
        hgemm<false><<<grid, 256, HGEMM_SMEM>>>(
            ogh, woh, nullptr, t1, bo,
            D_, D_, D_, D_,
            B_, (long long)B_ * SD_, SD_, DD_, 0, (long long)B_ * SD_, SD_, D_,
            cnt, nullptr);
    }

    // LN1 -> hg (fp32) + hgh (fp16)
    {
        dim3 grid(S_, SEGS);
        ln1g_kernel<<<grid, 128>>>(x, t1, idx, cnt, ln1_s, ln1_b, hg, hgh);
    }

    // FFN1 -> f1h: z = seg
    {
        dim3 grid(F_ / 128, S_ / 128, SEGS);
        hgemm<true><<<grid, 256, HGEMM_SMEM>>>(
            hgh, w1h, f1h, nullptr, b1,
            D_, D_, D_, F_,
            B_, (long long)B_ * SD_, SD_, (long long)D_ * F_, 0,
            (long long)B_ * SF_, SF_, F_,
            cnt, nullptr);
    }

    // FFN2 -> f2 (fp32): z = seg
    {
        dim3 grid(D_ / 128, S_ / 128, SEGS);
        hgemm<false><<<grid, 256, HGEMM_SMEM>>>(
            f1h, w2h, nullptr, f2, b2,
            F_, F_, F_, D_,
            B_, (long long)B_ * SF_, SF_, (long long)F_ * D_, 0,
            (long long)B_ * SD_, SD_, D_,
            cnt, nullptr);
    }

    // final = sum_e rw * LN2(hg + f2)
    ln2_scatter_kernel<<<N_, 128>>>(hg, f2, ln2_s, ln2_b, rw, pos, out_final);
}

// round 8
// speedup vs baseline: 17.6091x; 1.1026x over previous
#include <cuda_runtime.h>
#include <cuda_fp16.h>
#include <cstdint>

// ---------------------------------------------------------------------------
// SEMMBlock: spiking-router MoE transformer block.
// B=4 S=1024 D=512 E=8 F=2048 H=4 dh=128.
// Round 8: fp16 mma.sync everywhere (tcgen05 rejected by toolchain);
// untransposed weights + ldmatrix.trans B-fragments => conversions are pure
// streaming; router sparsity as rounds 5-6.
// ---------------------------------------------------------------------------

#define B_  4
#define S_  1024
#define D_  512
#define E_  8
#define F_  2048
#define H_  4
#define DH_ 128
#define N_  (B_ * S_)
#define SEGS (E_ * B_)
#define LN_EPS 1e-5f

#define DD_  (D_ * D_)
#define ND_  ((long long)N_ * D_)
#define SD_  ((long long)S_ * D_)
#define SF_  ((long long)S_ * F_)

// ------------------------- scratch (device globals) ------------------------
__device__ float  g_rw[N_ * E_];
__device__ int    g_cnt[SEGS];
__device__ int    g_idx[SEGS * S_];
__device__ int    g_pos[N_ * E_];
__device__ __half g_xh[N_ * D_];
__device__ __half g_wqh[E_ * DD_];          // [e][K][N] fp16 (NOT transposed)
__device__ __half g_wkh[E_ * DD_];
__device__ __half g_wvh[E_ * DD_];
__device__ __half g_woh[E_ * DD_];
__device__ __half g_w1h[(size_t)E_ * D_ * F_];
__device__ __half g_w2h[(size_t)E_ * F_ * D_];
__device__ __half g_kvh[(size_t)E_ * 2 * N_ * D_];
__device__ __half g_qh[(size_t)SEGS * S_ * D_];
__device__ __half g_ogh[(size_t)SEGS * S_ * D_];
__device__ __half g_hgh[(size_t)SEGS * S_ * D_];
__device__ __half g_f1h[(size_t)SEGS * S_ * F_];
__device__ float  g_t1[(size_t)SEGS * S_ * D_];
__device__ float  g_hg[(size_t)SEGS * S_ * D_];
__device__ float  g_f2[(size_t)SEGS * S_ * D_];

// ------------------------------ helpers -------------------------------------
__device__ __forceinline__ void cp_async16(uint32_t smem, const void* gptr) {
    asm volatile("cp.async.cg.shared.global [%0], [%1], 16;\n" :: "r"(smem), "l"(gptr));
}
__device__ __forceinline__ void cp_commit() {
    asm volatile("cp.async.commit_group;\n");
}
__device__ __forceinline__ void cp_wait0() {
    asm volatile("cp.async.wait_group 0;\n");
}
__device__ __forceinline__ void cp_wait1() {
    asm volatile("cp.async.wait_group 1;\n");
}
__device__ __forceinline__ void mma_f16(float* c, unsigned a0, unsigned a1,
                                        unsigned a2, unsigned a3,
                                        unsigned b0, unsigned b1) {
    asm volatile(
        "mma.sync.aligned.m16n8k16.row.col.f32.f16.f16.f32 "
        "{%0,%1,%2,%3}, {%4,%5,%6,%7}, {%8,%9}, {%0,%1,%2,%3};\n"
        : "+f"(c[0]), "+f"(c[1]), "+f"(c[2]), "+f"(c[3])
        : "r"(a0), "r"(a1), "r"(a2), "r"(a3), "r"(b0), "r"(b1));
}
__device__ __forceinline__ unsigned h2pack(float x, float y) {
    __half2 h = __floats2half2_rn(x, y);
    return *(unsigned*)&h;
}

// ------------------------------- router -------------------------------------
__global__ void router_kernel(const float* __restrict__ x,
                              const float* __restrict__ gw,
                              const float* __restrict__ gb,
                              float* __restrict__ logits,
                              float* __restrict__ rw)
{
    int warp = (blockIdx.x * blockDim.x + threadIdx.x) >> 5;
    int lane = threadIdx.x & 31;
    if (warp >= N_) return;
    const float* xr = x + (size_t)warp * D_;
    float acc[E_];
#pragma unroll
    for (int e = 0; e < E_; e++) acc[e] = 0.f;
    for (int i = lane; i < D_; i += 32) {
        float xv = xr[i];
        const float* g = gw + i * E_;
#pragma unroll
        for (int e = 0; e < E_; e++) acc[e] += xv * g[e];
    }
#pragma unroll
    for (int e = 0; e < E_; e++) {
#pragma unroll
        for (int o = 16; o > 0; o >>= 1)
            acc[e] += __shfl_down_sync(0xffffffffu, acc[e], o);
    }
    if (lane == 0) {
        float lg[E_];
#pragma unroll
        for (int e = 0; e < E_; e++) {
            lg[e] = acc[e] + gb[e];
            logits[warp * E_ + e] = lg[e];
        }
        int i1 = 0;
#pragma unroll
        for (int e = 1; e < E_; e++) if (lg[e] > lg[i1]) i1 = e;
        int i2 = -1;
#pragma unroll
        for (int e = 0; e < E_; e++) {
            if (e == i1) continue;
            if (i2 < 0 || lg[e] > lg[i2]) i2 = e;
        }
#pragma unroll
        for (int e = 0; e < E_; e++) {
            float r = 0.f;
            if (e == i1 || e == i2) {
                float mem = lg[e] > 0.f ? lg[e] : 0.f;
#pragma unroll
                for (int lvl = 0; lvl < 4; lvl++) {
                    float thr = 4.0f / (float)(1 << lvl);
                    if (mem >= thr) { r += thr; mem -= thr; }
                }
            }
            rw[warp * E_ + e] = r;
        }
    }
}

// -------------------------- build gather lists -------------------------------
__global__ void build_lists_kernel(const float* __restrict__ rw)
{
    int n = blockIdx.x * blockDim.x + threadIdx.x;
    if (n >= N_) return;
    int b = n >> 10;
#pragma unroll
    for (int e = 0; e < E_; e++) {
        if (rw[n * E_ + e] != 0.f) {
            int seg = e * B_ + b;
            int i = atomicAdd(&g_cnt[seg], 1);
            g_idx[seg * S_ + i] = n;
            g_pos[n * E_ + e] = i;
        }
    }
}

// ----------------------------- conversions -----------------------------------
// pure streaming fp32 -> fp16 (8 elems / thread)
__global__ void hconv_kernel(const float* __restrict__ src, __half* __restrict__ dst)
{
    int i = (blockIdx.x * blockDim.x + threadIdx.x) * 8;
    float4 a = *(const float4*)(src + i);
    float4 b = *(const float4*)(src + i + 4);
    *(__half2*)(dst + i)     = __floats2half2_rn(a.x, a.y);
    *(__half2*)(dst + i + 2) = __floats2half2_rn(a.z, a.w);
    *(__half2*)(dst + i + 4) = __floats2half2_rn(b.x, b.y);
    *(__half2*)(dst + i + 6) = __floats2half2_rn(b.z, b.w);
}

// --------------------------- fp16 tensor GEMM --------------------------------
// C = A[.,K] @ B[K][N] + bias (relu). A fp16 K-major; B fp16 UNTRANSPOSED
// [K][N]; b-frags via ldmatrix.x2.trans (same pattern as flash P@V).
// BM=BN=128, BK=32, 256 thr, 8 warps of 64x32. 3-stage cp.async pipeline.
#define HAPAD 40        // halfs per A smem row (32 data + 8 pad)
#define BSTR  136       // halfs per B smem row (128 data + 8 pad)
#define HGEMM_SMEM (3 * (128 * HAPAD + 32 * BSTR) * 2)

template <bool RELU>
__global__ __launch_bounds__(256, 2) void hgemm(
    const __half* __restrict__ A, const __half* __restrict__ Bp,
    __half* __restrict__ Ch, float* __restrict__ Cf,
    const float* __restrict__ bias,
    int K, int lda, int ldb, int ldc,
    int div1,
    long long sA0, long long sA1,
    long long sB0, long long sB1,
    long long sC0, long long sC1,
    long long sb0,
    const int* __restrict__ mlim, const int* __restrict__ gidx)
{
    const int z  = blockIdx.z;
    const int bm = blockIdx.y * 128;
    if (mlim && bm >= mlim[z]) return;
    const int z0 = z / div1, z1 = z - z0 * div1;
    A  += z0 * sA0 + z1 * sA1;
    Bp += z0 * sB0 + z1 * sB1;
    const long long coff = z0 * sC0 + z1 * sC1;
    const float* biasp = bias + z0 * sb0;

    extern __shared__ __half hsm[];
    __half* As = hsm;                        // [3][128*HAPAD]
    __half* Bs = hsm + 3 * 128 * HAPAD;      // [3][32*BSTR]

    const int tid  = threadIdx.x;
    const int lane = tid & 31;
    const int wid  = tid >> 5;
    const int warpM = (wid >> 2) * 64;
    const int warpN = (wid & 3) * 32;
    const int bn = blockIdx.x * 128;

    // A staging: 2 x 16B per thread
    const int srow = tid >> 1;               // 0..127
    const int sch  = (tid & 1) * 16;         // half offset 0 or 16
    long long arow = bm + srow;
    if (gidx) arow = gidx[(long long)z * S_ + arow];
    const __half* gA = A + arow * lda + sch;
    uint32_t sA = (uint32_t)__cvta_generic_to_shared(As + srow * HAPAD + sch);

    // B staging: rows = K (32/stage), cols = 128 @ bn. 2 x 16B per thread.
    const int brow = tid >> 4;               // 0..15
    const int bc16 = (tid & 15) * 8;         // half col offset 0..120
    const __half* gB = Bp + (long long)brow * ldb + bn + bc16;   // rows brow, brow+16
    uint32_t sB = (uint32_t)__cvta_generic_to_shared(Bs + brow * BSTR + bc16);

    const uint32_t stgA = 128 * HAPAD * 2;   // A stage bytes
    const uint32_t stgB = 32 * BSTR * 2;     // B stage bytes
    const long long ldb16 = 16LL * ldb;

    float acc[4][4][4];
#pragma unroll
    for (int i = 0; i < 4; i++)
#pragma unroll
        for (int j = 0; j < 4; j++)
#pragma unroll
            for (int q = 0; q < 4; q++) acc[i][j][q] = 0.f;

    // prologue: stage0 (k 0..31), stage1 (k 32..63)
    cp_async16(sA,      gA);
    cp_async16(sA + 16, gA + 8);
    cp_async16(sB,                gB);
    cp_async16(sB + 16 * BSTR * 2, gB + ldb16);
    cp_commit();
    cp_async16(sA + stgA,      gA + 32);
    cp_async16(sA + stgA + 16, gA + 40);
    cp_async16(sB + stgB,                gB + 2 * ldb16);
    cp_async16(sB + stgB + 16 * BSTR * 2, gB + 3 * ldb16);
    cp_commit();

    const int mrow = warpM + (lane >> 2);
    const int qq2  = (lane & 3) * 2;

    int it = 0;
    for (int k0 = 0; k0 < K; k0 += 32, it++) {
        const int st = it % 3;
        cp_wait1();
        __syncthreads();

        if (k0 + 64 < K) {
            const int sp = (it + 2) % 3;
            const __half* gA2 = gA + k0 + 64;
            const __half* gB2 = gB + (long long)(k0 + 64) * ldb;
            cp_async16(sA + sp * stgA,      gA2);
            cp_async16(sA + sp * stgA + 16, gA2 + 8);
            cp_async16(sB + sp * stgB,                gB2);
            cp_async16(sB + sp * stgB + 16 * BSTR * 2, gB2 + ldb16);
        }
        cp_commit();

        const __half* As0 = As + st * 128 * HAPAD;
        const __half* Bs0 = Bs + st * 32 * BSTR;

#pragma unroll
        for (int ks = 0; ks < 2; ks++) {
            const int kb = ks * 16;
            unsigned af[4][4], bf[4][2];
#pragma unroll
            for (int mi = 0; mi < 4; mi++) {
                const __half* pa = As0 + (mrow + mi * 16) * HAPAD + kb + qq2;
                af[mi][0] = *(const unsigned*)(pa);
                af[mi][1] = *(const unsigned*)(pa + 8 * HAPAD);
                af[mi][2] = *(const unsigned*)(pa + 8);
                af[mi][3] = *(const unsigned*)(pa + 8 * HAPAD + 8);
            }
            uint32_t bbase = (uint32_t)__cvta_generic_to_shared(
                Bs0 + (kb + (lane & 15)) * BSTR + warpN);
#pragma unroll
            for (int ni = 0; ni < 4; ni++) {
                asm volatile(
                    "ldmatrix.sync.aligned.m8n8.x2.trans.shared.b16 {%0,%1}, [%2];\n"
                    : "=r"(bf[ni][0]), "=r"(bf[ni][1]) : "r"(bbase + ni * 16));
            }
#pragma unroll
            for (int mi = 0; mi < 4; mi++)
#pragma unroll
                for (int ni = 0; ni < 4; ni++)
                    mma_f16(acc[mi][ni], af[mi][0], af[mi][1], af[mi][2], af[mi][3],
                            bf[ni][0], bf[ni][1]);
        }
    }

    // epilogue
#pragma unroll
    for (int mi = 0; mi < 4; mi++) {
        long long row0 = bm + warpM + mi * 16 + (lane >> 2);
#pragma unroll
        for (int ni = 0; ni < 4; ni++) {
            int col = bn + warpN + ni * 8 + qq2;
            float b0 = biasp[col], b1 = biasp[col + 1];
            float v0 = acc[mi][ni][0] + b0;
            float v1 = acc[mi][ni][1] + b1;
            float v2 = acc[mi][ni][2] + b0;
            float v3 = acc[mi][ni][3] + b1;
            if (RELU) {
                v0 = fmaxf(v0, 0.f); v1 = fmaxf(v1, 0.f);
                v2 = fmaxf(v2, 0.f); v3 = fmaxf(v3, 0.f);
            }
            if (Ch) {
                *(__half2*)(Ch + coff + row0 * ldc + col)       = __floats2half2_rn(v0, v1);
                *(__half2*)(Ch + coff + (row0 + 8) * ldc + col) = __floats2half2_rn(v2, v3);
            }
            if (Cf) {
                *(float2*)(Cf + coff + row0 * ldc + col)       = make_float2(v0, v1);
                *(float2*)(Cf + coff + (row0 + 8) * ldc + col) = make_float2(v2, v3);
            }
        }
    }
}

// ------------------------- fused flash attention (fp16) ----------------------
#define BC_   64
#define FSTR  136
#define FLASH_SMEM ((128 * FSTR + 2 * BC_ * FSTR + 2 * BC_ * FSTR) * 2)

__global__ __launch_bounds__(256, 2) void flash_kernel(const __half* __restrict__ qh,
                                                       const __half* __restrict__ kvh,
                                                       const int* __restrict__ cnt,
                                                       __half* __restrict__ ogh)
{
    const int qt  = blockIdx.x;
    const int seg = blockIdx.y >> 2;
    const int h   = blockIdx.y & 3;
    if (qt * 128 >= cnt[seg]) return;
    const int e = seg >> 2;
    const int b = seg & 3;

    extern __shared__ __half fsm[];
    __half* Qs = fsm;
    __half* Ks = fsm + 128 * FSTR;
    __half* Vs = Ks + 2 * BC_ * FSTR;

    const int tid  = threadIdx.x;
    const int lane = tid & 31;
    const int wid  = tid >> 5;
    const float scale = 0.08838834764831845f;

    const __half* qbase = qh + (long long)seg * SD_ + (long long)(qt * 128) * D_ + h * DH_;
    const __half* kbase = kvh + (long long)e * 2 * ND_ + (long long)(b * S_) * D_ + h * DH_;
    const __half* vbase = kbase + ND_;

    {
        int r = tid >> 1, c0 = (tid & 1) * 64;
        const __half* g = qbase + (long long)r * D_ + c0;
        uint32_t s = (uint32_t)__cvta_generic_to_shared(Qs + r * FSTR + c0);
#pragma unroll
        for (int j = 0; j < 8; j++) cp_async16(s + j * 16, g + j * 8);
    }
    {
        int r = tid >> 2, c0 = (tid & 3) * 32;
        const __half* gk = kbase + (long long)r * D_ + c0;
        const __half* gv = vbase + (long long)r * D_ + c0;
        uint32_t sk = (uint32_t)__cvta_generic_to_shared(Ks + r * FSTR + c0);
        uint32_t sv = (uint32_t)__cvta_generic_to_shared(Vs + r * FSTR + c0);
#pragma unroll
        for (int j = 0; j < 4; j++) {
            cp_async16(sk + j * 16, gk + j * 8);
            cp_async16(sv + j * 16, gv + j * 8);
        }
    }
    cp_commit();

    const int r0  = lane >> 2;
    const int qq2 = (lane & 3) * 2;
    const int wrow = wid * 16;

    float oacc[16][4];
#pragma unroll
    for (int i = 0; i < 16; i++)
#pragma unroll
        for (int j = 0; j < 4; j++) oacc[i][j] = 0.f;
    float m0 = -1e30f, m1 = -1e30f, l0 = 0.f, l1 = 0.f;

    for (int t = 0; t < 16; t++) {
        const int st = t & 1;
        cp_wait0();
        __syncthreads();

        if (t < 15) {
            int r = tid >> 2, c0 = (tid & 3) * 32;
            int st2 = st ^ 1;
            const __half* gk = kbase + (long long)((t + 1) * BC_ + r) * D_ + c0;
            const __half* gv = vbase + (long long)((t + 1) * BC_ + r) * D_ + c0;
            uint32_t sk = (uint32_t)__cvta_generic_to_shared(Ks + st2 * BC_ * FSTR + r * FSTR + c0);
            uint32_t sv = (uint32_t)__cvta_generic_to_shared(Vs + st2 * BC_ * FSTR + r * FSTR + c0);
#pragma unroll
            for (int j = 0; j < 4; j++) {
                cp_async16(sk + j * 16, gk + j * 8);
                cp_async16(sv + j * 16, gv + j * 8);
            }
            cp_commit();
        }

        float sacc[8][4];
#pragma unroll
        for (int i = 0; i < 8; i++)
#pragma unroll
            for (int j = 0; j < 4; j++) sacc[i][j] = 0.f;

        const __half* Qw = Qs + (wrow + r0) * FSTR;
        const __half* Kt = Ks + st * BC_ * FSTR;
#pragma unroll
        for (int ks = 0; ks < 8; ks++) {
            const int kb = ks * 16 + qq2;
            const __half* pa = Qw + kb;
            unsigned a0 = *(const unsigned*)(pa);
            unsigned a1 = *(const unsigned*)(pa + 8 * FSTR);
            unsigned a2 = *(const unsigned*)(pa + 8);
            unsigned a3 = *(const unsigned*)(pa + 8 * FSTR + 8);
#pragma unroll
            for (int ni = 0; ni < 8; ni++) {
                const __half* pb = Kt + (ni * 8 + r0) * FSTR + kb;
                mma_f16(sacc[ni], a0, a1, a2, a3,
                        *(const unsigned*)(pb), *(const unsigned*)(pb + 8));
            }
        }

        float rmax0 = -1e30f, rmax1 = -1e30f;
#pragma unroll
        for (int ni = 0; ni < 8; ni++) {
            sacc[ni][0] *= scale; sacc[ni][1] *= scale;
            sacc[ni][2] *= scale; sacc[ni][3] *= scale;
            rmax0 = fmaxf(rmax0, fmaxf(sacc[ni][0], sacc[ni][1]));
            rmax1 = fmaxf(rmax1, fmaxf(sacc[ni][2], sacc[ni][3]));
        }
        rmax0 = fmaxf(rmax0, __shfl_xor_sync(0xffffffffu, rmax0, 1));
        rmax0 = fmaxf(rmax0, __shfl_xor_sync(0xffffffffu, rmax0, 2));
        rmax1 = fmaxf(rmax1, __shfl_xor_sync(0xffffffffu, rmax1, 1));
        rmax1 = fmaxf(rmax1, __shfl_xor_sync(0xffffffffu, rmax1, 2));
        float mn0 = fmaxf(m0, rmax0), mn1 = fmaxf(m1, rmax1);
        float c0 = __expf(m0 - mn0), c1 = __expf(m1 - mn1);
        m0 = mn0; m1 = mn1;
        float rs0 = 0.f, rs1 = 0.f;
#pragma unroll
        for (int ni = 0; ni < 8; ni++) {
            sacc[ni][0] = __expf(sacc[ni][0] - m0);
            sacc[ni][1] = __expf(sacc[ni][1] - m0);
            sacc[ni][2] = __expf(sacc[ni][2] - m1);
            sacc[ni][3] = __expf(sacc[ni][3] - m1);
            rs0 += sacc[ni][0] + sacc[ni][1];
            rs1 += sacc[ni][2] + sacc[ni][3];
        }
        rs0 += __shfl_xor_sync(0xffffffffu, rs0, 1);
        rs0 += __shfl_xor_sync(0xffffffffu, rs0, 2);
        rs1 += __shfl_xor_sync(0xffffffffu, rs1, 1);
        rs1 += __shfl_xor_sync(0xffffffffu, rs1, 2);
        l0 = l0 * c0 + rs0;
        l1 = l1 * c1 + rs1;
#pragma unroll
        for (int ni = 0; ni < 16; ni++) {
            oacc[ni][0] *= c0; oacc[ni][1] *= c0;
            oacc[ni][2] *= c1; oacc[ni][3] *= c1;
        }

        const __half* Vt = Vs + st * BC_ * FSTR;
#pragma unroll
        for (int ks = 0; ks < 4; ks++) {
            unsigned a0 = h2pack(sacc[2 * ks][0],     sacc[2 * ks][1]);
            unsigned a1 = h2pack(sacc[2 * ks][2],     sacc[2 * ks][3]);
            unsigned a2 = h2pack(sacc[2 * ks + 1][0], sacc[2 * ks + 1][1]);
            unsigned a3 = h2pack(sacc[2 * ks + 1][2], sacc[2 * ks + 1][3]);
            uint32_t vrow = (uint32_t)__cvta_generic_to_shared(
                Vt + (16 * ks + (lane & 15)) * FSTR);
#pragma unroll
            for (int ni = 0; ni < 16; ni++) {
                unsigned b0, b1;
                asm volatile(
                    "ldmatrix.sync.aligned.m8n8.x2.trans.shared.b16 {%0,%1}, [%2];\n"
                    : "=r"(b0), "=r"(b1) : "r"(vrow + ni * 16));
                mma_f16(oacc[ni], a0, a1, a2, a3, b0, b1);
            }
        }
    }

    float inv0 = 1.f / l0, inv1 = 1.f / l1;
    long long row0 = (long long)(qt * 128 + wrow + r0);
    __half* ob = ogh + (long long)seg * SD_ + row0 * D_ + h * DH_;
#pragma unroll
    for (int ni = 0; ni < 16; ni++) {
        int col = ni * 8 + qq2;
        *(__half2*)(ob + col)            = __floats2half2_rn(oacc[ni][0] * inv0, oacc[ni][1] * inv0);
        *(__half2*)(ob + 8LL * D_ + col) = __floats2half2_rn(oacc[ni][2] * inv1, oacc[ni][3] * inv1);
    }
}

// --------------------------- LayerNorm kernels ------------------------------
__global__ void ln1g_kernel(const float* __restrict__ x, const float* __restrict__ t1,
                            const int* __restrict__ idx, const int* __restrict__ cnt,
                            const float* __restrict__ s_all, const float* __restrict__ b_all,
                            float* __restrict__ hg, __half* __restrict__ hgh)
{
    int i   = blockIdx.x;
    int seg = blockIdx.y;
    if (i >= cnt[seg]) return;
    int e = seg >> 2;
    int token = idx[seg * S_ + i];
    const float* a    = x  + (size_t)token * D_;
    const float* bsrc = t1 + ((size_t)seg * S_ + i) * D_;
    const float* s    = s_all + (size_t)e * D_;
    const float* bb   = b_all + (size_t)e * D_;
    float*  outf = hg  + ((size_t)seg * S_ + i) * D_;
    __half* outh = hgh + ((size_t)seg * S_ + i) * D_;
    int t = threadIdx.x;
    __shared__ float red[128];
    float v[4];
#pragma unroll
    for (int q = 0; q < 4; q++) {
        int d = t + q * 128;
        v[q] = a[d] + bsrc[d];
    }
    float sum = v[0] + v[1] + v[2] + v[3];
    red[t] = sum; __syncthreads();
    for (int o = 64; o > 0; o >>= 1) { if (t < o) red[t] += red[t + o]; __syncthreads(); }
    float mu = red[0] * (1.f / D_); __syncthreads();
    float sq = 0.f;
#pragma unroll
    for (int q = 0; q < 4; q++) { float d2 = v[q] - mu; sq += d2 * d2; }
    red[t] = sq; __syncthreads();
    for (int o = 64; o > 0; o >>= 1) { if (t < o) red[t] += red[t + o]; __syncthreads(); }
    float inv = rsqrtf(red[0] * (1.f / D_) + LN_EPS);
#pragma unroll
    for (int q = 0; q < 4; q++) {
        int d = t + q * 128;
        float y = (v[q] - mu) * inv * s[d] + bb[d];
        outf[d] = y;
        outh[d] = __float2half_rn(y);
    }
}

__global__ void ln2_scatter_kernel(const float* __restrict__ hg, const float* __restrict__ f2g,
                                   const float* __restrict__ s_all, const float* __restrict__ b_all,
                                   const float* __restrict__ rw, const int* __restrict__ pos,
                                   float* __restrict__ finalOut)
{
    int n = blockIdx.x;
    int t = threadIdx.x;
    int b = n >> 10;
    __shared__ float red[128];
    float outv[4] = {0.f, 0.f, 0.f, 0.f};
    for (int e = 0; e < E_; e++) {
        float w = rw[n * E_ + e];
        if (w == 0.f) continue;
        int seg = e * B_ + b;
        int p = pos[n * E_ + e];
        const float* hp = hg  + ((size_t)seg * S_ + p) * D_;
        const float* fp = f2g + ((size_t)seg * S_ + p) * D_;
        const float* s  = s_all + (size_t)e * D_;
        const float* bb = b_all + (size_t)e * D_;
        float v[4];
#pragma unroll
        for (int q = 0; q < 4; q++) {
            int d = t + q * 128;
            v[q] = hp[d] + fp[d];
        }
        float sum = v[0] + v[1] + v[2] + v[3];
        __syncthreads();
        red[t] = sum; __syncthreads();
        for (int o = 64; o > 0; o >>= 1) { if (t < o) red[t] += red[t + o]; __syncthreads(); }
        float mu = red[0] * (1.f / D_); __syncthreads();
        float sq = 0.f;
#pragma unroll
        for (int q = 0; q < 4; q++) { float d2 = v[q] - mu; sq += d2 * d2; }
        red[t] = sq; __syncthreads();
        for (int o = 64; o > 0; o >>= 1) { if (t < o) red[t] += red[t + o]; __syncthreads(); }
        float inv = rsqrtf(red[0] * (1.f / D_) + LN_EPS);
#pragma unroll
        for (int q = 0; q < 4; q++) {
            int d = t + q * 128;
            outv[q] += w * ((v[q] - mu) * inv * s[d] + bb[d]);
        }
    }
#pragma unroll
    for (int q = 0; q < 4; q++)
        finalOut[(size_t)n * D_ + t + q * 128] = outv[q];
}

// ------------------------------ host glue -----------------------------------
extern "C" void kernel_launch(void* const* d_in, const int* in_sizes, int n_in,
                              void* d_out, int out_size)
{
    const float* x      = (const float*)d_in[0];
    const float* gate_w = (const float*)d_in[1];
    const float* gate_b = (const float*)d_in[2];
    const float* ln1_s  = (const float*)d_in[3];
    const float* ln1_b  = (const float*)d_in[4];
    const float* ln2_s  = (const float*)d_in[5];
    const float* ln2_b  = (const float*)d_in[6];
    const float* wq     = (const float*)d_in[7];
    const float* wk     = (const float*)d_in[8];
    const float* wv     = (const float*)d_in[9];
    const float* wo     = (const float*)d_in[10];
    const float* bq     = (const float*)d_in[11];
    const float* bk     = (const float*)d_in[12];
    const float* bv     = (const float*)d_in[13];
    const float* bo     = (const float*)d_in[14];
    const float* w1     = (const float*)d_in[15];
    const float* b1     = (const float*)d_in[16];
    const float* w2     = (const float*)d_in[17];
    const float* b2     = (const float*)d_in[18];

    float* out_final  = (float*)d_out;
    float* out_logits = out_final + (size_t)N_ * D_;

    float *rw, *t1, *hg, *f2;
    int *cnt, *idx, *pos;
    __half *xh, *wqh, *wkh, *wvh, *woh, *w1h, *w2h, *kvh, *qh, *ogh, *hgh, *f1h;
    cudaGetSymbolAddress((void**)&rw,  g_rw);
    cudaGetSymbolAddress((void**)&cnt, g_cnt);
    cudaGetSymbolAddress((void**)&idx, g_idx);
    cudaGetSymbolAddress((void**)&pos, g_pos);
    cudaGetSymbolAddress((void**)&xh,  g_xh);
    cudaGetSymbolAddress((void**)&wqh, g_wqh);
    cudaGetSymbolAddress((void**)&wkh, g_wkh);
    cudaGetSymbolAddress((void**)&wvh, g_wvh);
    cudaGetSymbolAddress((void**)&woh, g_woh);
    cudaGetSymbolAddress((void**)&w1h, g_w1h);
    cudaGetSymbolAddress((void**)&w2h, g_w2h);
    cudaGetSymbolAddress((void**)&kvh, g_kvh);
    cudaGetSymbolAddress((void**)&qh,  g_qh);
    cudaGetSymbolAddress((void**)&ogh, g_ogh);
    cudaGetSymbolAddress((void**)&hgh, g_hgh);
    cudaGetSymbolAddress((void**)&f1h, g_f1h);
    cudaGetSymbolAddress((void**)&t1,  g_t1);
    cudaGetSymbolAddress((void**)&hg,  g_hg);
    cudaGetSymbolAddress((void**)&f2,  g_f2);

    cudaFuncSetAttribute(flash_kernel,
                         cudaFuncAttributeMaxDynamicSharedMemorySize, FLASH_SMEM);
    cudaFuncSetAttribute(hgemm<false>,
                         cudaFuncAttributeMaxDynamicSharedMemorySize, HGEMM_SMEM);
    cudaFuncSetAttribute(hgemm<true>,
                         cudaFuncAttributeMaxDynamicSharedMemorySize, HGEMM_SMEM);

    cudaMemsetAsync(cnt, 0, SEGS * sizeof(int));
    cudaMemsetAsync(idx, 0, SEGS * S_ * sizeof(int));

    router_kernel<<<N_ / 8, 256>>>(x, gate_w, gate_b, out_logits, rw);
    build_lists_kernel<<<N_ / 256, 256>>>(rw);

    // streaming conversions (no transpose)
    hconv_kernel<<<(N_ * D_) / 2048, 256>>>(x, xh);
    hconv_kernel<<<(E_ * DD_) / 2048, 256>>>(wq, wqh);
    hconv_kernel<<<(E_ * DD_) / 2048, 256>>>(wk, wkh);
    hconv_kernel<<<(E_ * DD_) / 2048, 256>>>(wv, wvh);
    hconv_kernel<<<(E_ * DD_) / 2048, 256>>>(wo, woh);
    hconv_kernel<<<(E_ * D_ * F_) / 2048, 256>>>(w1, w1h);
    hconv_kernel<<<(E_ * F_ * D_) / 2048, 256>>>(w2, w2h);

    // K projection (dense): z = e
    {
        dim3 grid(D_ / 128, N_ / 128, E_);
        hgemm<false><<<grid, 256, HGEMM_SMEM>>>(
            xh, wkh, kvh, nullptr, bk,
            D_, D_, D_, D_,
            1, 0, 0, DD_, 0, 2 * ND_, 0, D_,
            nullptr, nullptr);
    }
    // V projection (dense): z = e
    {
        dim3 grid(D_ / 128, N_ / 128, E_);
        hgemm<false><<<grid, 256, HGEMM_SMEM>>>(
            xh, wvh, kvh + ND_, nullptr, bv,
            D_, D_, D_, D_,
            1, 0, 0, DD_, 0, 2 * ND_, 0, D_,
            nullptr, nullptr);
    }
    // Q projection (gathered): z = seg
    {
        dim3 grid(D_ / 128, S_ / 128, SEGS);
        hgemm<false><<<grid, 256, HGEMM_SMEM>>>(
            xh, wqh, qh, nullptr, bq,
            D_, D_, D_, D_,
            B_, 0, 0, DD_, 0, (long long)B_ * SD_, SD_, D_,
            cnt, idx);
    }

    // fused attention
    {
        dim3 grid(S_ / 128, SEGS * H_);
        flash_kernel<<<grid, 256, FLASH_SMEM>>>(qh, kvh, cnt, ogh);
    }

    // O projection -> t1 (fp32): z = seg
    {
        dim3 grid(D_ / 128, S_ / 128, SEGS);
        hgemm<false><<<grid, 256, HGEMM_SMEM>>>(
            ogh, woh, nullptr, t1, bo,
            D_, D_, D_, D_,
            B_, (long long)B_ * SD_, SD_, DD_, 0, (long long)B_ * SD_, SD_, D_,
            cnt, nullptr);
    }

    // LN1 -> hg (fp32) + hgh (fp16)
    {
        dim3 grid(S_, SEGS);
        ln1g_kernel<<<grid, 128>>>(x, t1, idx, cnt, ln1_s, ln1_b, hg, hgh);
    }

    // FFN1 -> f1h (relu): z = seg
    {
        dim3 grid(F_ / 128, S_ / 128, SEGS);
        hgemm<true><<<grid, 256, HGEMM_SMEM>>>(
            hgh, w1h, f1h, nullptr, b1,
            D_, D_, F_, F_,
            B_, (long long)B_ * SD_, SD_, (long long)D_ * F_, 0,
            (long long)B_ * SF_, SF_, F_,
            cnt, nullptr);
    }

    // FFN2 -> f2 (fp32): z = seg
    {
        dim3 grid(D_ / 128, S_ / 128, SEGS);
        hgemm<false><<<grid, 256, HGEMM_SMEM>>>(
            f1h, w2h, nullptr, f2, b2,
            F_, F_, D_, D_,
            B_, (long long)B_ * SF_, SF_, (long long)F_ * D_, 0,
            (long long)B_ * SD_, SD_, D_,
            cnt, nullptr);
    }

    // final = sum_e rw * LN2(hg + f2)
    ln2_scatter_kernel<<<N_, 128>>>(hg, f2, ln2_s, ln2_b, rw, pos, out_final);
}

// round 10
// speedup vs baseline: 19.1789x; 1.0891x over previous
#include <cuda_runtime.h>
#include <cuda_fp16.h>
#include <cstdint>

// ---------------------------------------------------------------------------
// SEMMBlock: spiking-router MoE transformer block.
// B=4 S=1024 D=512 E=8 F=2048 H=4 dh=128.
// Round 9: fused one-shot fp32->fp16 conversion, merged K+V GEMM launch,
// ldmatrix everywhere (hgemm A, flash QK A+B), warp-shuffle LayerNorms.
// ---------------------------------------------------------------------------

#define B_  4
#define S_  1024
#define D_  512
#define E_  8
#define F_  2048
#define H_  4
#define DH_ 128
#define N_  (B_ * S_)
#define SEGS (E_ * B_)
#define LN_EPS 1e-5f

#define DD_  (D_ * D_)
#define ND_  ((long long)N_ * D_)
#define SD_  ((long long)S_ * D_)
#define SF_  ((long long)S_ * F_)

// ------------------------- scratch (device globals) ------------------------
__device__ float  g_rw[N_ * E_];
__device__ int    g_cnt[SEGS];
__device__ int    g_idx[SEGS * S_];
__device__ int    g_pos[N_ * E_];
__device__ float  g_bkv[E_ * 2 * D_];
__device__ __half g_xh[N_ * D_];
__device__ __half g_wqh[E_ * DD_];             // [e][K][N] fp16 (untransposed)
__device__ __half g_wkvh[(size_t)E_ * 2 * DD_];// [e][{k,v}][K][N]
__device__ __half g_woh[E_ * DD_];
__device__ __half g_w1h[(size_t)E_ * D_ * F_];
__device__ __half g_w2h[(size_t)E_ * F_ * D_];
__device__ __half g_kvh[(size_t)E_ * 2 * N_ * D_];
__device__ __half g_qh[(size_t)SEGS * S_ * D_];
__device__ __half g_ogh[(size_t)SEGS * S_ * D_];
__device__ __half g_hgh[(size_t)SEGS * S_ * D_];
__device__ __half g_f1h[(size_t)SEGS * S_ * F_];
__device__ float  g_t1[(size_t)SEGS * S_ * D_];
__device__ float  g_hg[(size_t)SEGS * S_ * D_];
__device__ float  g_f2[(size_t)SEGS * S_ * D_];

// ------------------------------ helpers -------------------------------------
__device__ __forceinline__ void cp_async16(uint32_t smem, const void* gptr) {
    asm volatile("cp.async.cg.shared.global [%0], [%1], 16;\n" :: "r"(smem), "l"(gptr));
}
__device__ __forceinline__ void cp_commit() {
    asm volatile("cp.async.commit_group;\n");
}
__device__ __forceinline__ void cp_wait0() {
    asm volatile("cp.async.wait_group 0;\n");
}
__device__ __forceinline__ void cp_wait1() {
    asm volatile("cp.async.wait_group 1;\n");
}
__device__ __forceinline__ void mma_f16(float* c, unsigned a0, unsigned a1,
                                        unsigned a2, unsigned a3,
                                        unsigned b0, unsigned b1) {
    asm volatile(
        "mma.sync.aligned.m16n8k16.row.col.f32.f16.f16.f32 "
        "{%0,%1,%2,%3}, {%4,%5,%6,%7}, {%8,%9}, {%0,%1,%2,%3};\n"
        : "+f"(c[0]), "+f"(c[1]), "+f"(c[2]), "+f"(c[3])
        : "r"(a0), "r"(a1), "r"(a2), "r"(a3), "r"(b0), "r"(b1));
}
__device__ __forceinline__ unsigned h2pack(float x, float y) {
    __half2 h = __floats2half2_rn(x, y);
    return *(unsigned*)&h;
}
// block-wide sum over 128 threads (4 warps); red4 = 4-float smem scratch
__device__ __forceinline__ float blocksum128(float v, float* red4, int t) {
#pragma unroll
    for (int o = 16; o > 0; o >>= 1) v += __shfl_xor_sync(0xffffffffu, v, o);
    if ((t & 31) == 0) red4[t >> 5] = v;
    __syncthreads();
    float s = red4[0] + red4[1] + red4[2] + red4[3];
    __syncthreads();
    return s;
}

// ------------------------------- router -------------------------------------
__global__ void router_kernel(const float* __restrict__ x,
                              const float* __restrict__ gw,
                              const float* __restrict__ gb,
                              float* __restrict__ logits,
                              float* __restrict__ rw)
{
    int warp = (blockIdx.x * blockDim.x + threadIdx.x) >> 5;
    int lane = threadIdx.x & 31;
    if (warp >= N_) return;
    const float* xr = x + (size_t)warp * D_;
    float acc[E_];
#pragma unroll
    for (int e = 0; e < E_; e++) acc[e] = 0.f;
    for (int i = lane; i < D_; i += 32) {
        float xv = xr[i];
        const float* g = gw + i * E_;
#pragma unroll
        for (int e = 0; e < E_; e++) acc[e] += xv * g[e];
    }
#pragma unroll
    for (int e = 0; e < E_; e++) {
#pragma unroll
        for (int o = 16; o > 0; o >>= 1)
            acc[e] += __shfl_down_sync(0xffffffffu, acc[e], o);
    }
    if (lane == 0) {
        float lg[E_];
#pragma unroll
        for (int e = 0; e < E_; e++) {
            lg[e] = acc[e] + gb[e];
            logits[warp * E_ + e] = lg[e];
        }
        int i1 = 0;
#pragma unroll
        for (int e = 1; e < E_; e++) if (lg[e] > lg[i1]) i1 = e;
        int i2 = -1;
#pragma unroll
        for (int e = 0; e < E_; e++) {
            if (e == i1) continue;
            if (i2 < 0 || lg[e] > lg[i2]) i2 = e;
        }
#pragma unroll
        for (int e = 0; e < E_; e++) {
            float r = 0.f;
            if (e == i1 || e == i2) {
                float mem = lg[e] > 0.f ? lg[e] : 0.f;
#pragma unroll
                for (int lvl = 0; lvl < 4; lvl++) {
                    float thr = 4.0f / (float)(1 << lvl);
                    if (mem >= thr) { r += thr; mem -= thr; }
                }
            }
            rw[warp * E_ + e] = r;
        }
    }
}

// -------------------------- build gather lists -------------------------------
__global__ void build_lists_kernel(const float* __restrict__ rw)
{
    int n = blockIdx.x * blockDim.x + threadIdx.x;
    if (n >= N_) return;
    int b = n >> 10;
#pragma unroll
    for (int e = 0; e < E_; e++) {
        if (rw[n * E_ + e] != 0.f) {
            int seg = e * B_ + b;
            int i = atomicAdd(&g_cnt[seg], 1);
            g_idx[seg * S_ + i] = n;
            g_pos[n * E_ + e] = i;
        }
    }
}

// ----------------------------- conversions -----------------------------------
// One launch converts x + all weights. 8 elems/thread. K/V weights packed
// into g_wkvh [e][{k,v}][K][N].
#define U0_ ((long long)N_ * D_ / 8)        // 262144
#define UW_ ((long long)E_ * DD_ / 8)       // 262144
#define UF_ ((long long)E_ * D_ * F_ / 8)   // 1048576
#define UTOT_ (U0_ + 4 * UW_ + 2 * UF_)     // 3407872 (exact multiple of 256)

__global__ void convall_kernel(const float* __restrict__ x,  const float* __restrict__ wq,
                               const float* __restrict__ wk, const float* __restrict__ wv,
                               const float* __restrict__ wo, const float* __restrict__ w1,
                               const float* __restrict__ w2)
{
    long long u = (long long)blockIdx.x * blockDim.x + threadIdx.x;
    const float* src; __half* dst;
    long long so, dofs;
    if (u < U0_)                  { src = x;  dst = g_xh;  so = u;              dofs = so; }
    else if (u < U0_ + UW_)       { src = wq; dst = g_wqh; so = u - U0_;        dofs = so; }
    else if (u < U0_ + 2 * UW_)   { so = u - U0_ - UW_;
                                    long long gi = so * 8;
                                    long long e = gi / DD_, r = gi - e * DD_;
                                    src = wk; dst = g_wkvh;
                                    dofs = (e * 2 * DD_ + r) >> 3; }
    else if (u < U0_ + 3 * UW_)   { so = u - U0_ - 2 * UW_;
                                    long long gi = so * 8;
                                    long long e = gi / DD_, r = gi - e * DD_;
                                    src = wv; dst = g_wkvh;
                                    dofs = (e * 2 * DD_ + DD_ + r) >> 3; }
    else if (u < U0_ + 4 * UW_)   { src = wo; dst = g_woh; so = u - U0_ - 3 * UW_; dofs = so; }
    else if (u < U0_ + 4 * UW_ + UF_) { src = w1; dst = g_w1h; so = u - U0_ - 4 * UW_; dofs = so; }
    else                          { src = w2; dst = g_w2h; so = u - U0_ - 4 * UW_ - UF_; dofs = so; }
    long long si = so * 8, di = dofs * 8;
    float4 a = *(const float4*)(src + si);
    float4 b = *(const float4*)(src + si + 4);
    *(__half2*)(dst + di)     = __floats2half2_rn(a.x, a.y);
    *(__half2*)(dst + di + 2) = __floats2half2_rn(a.z, a.w);
    *(__half2*)(dst + di + 4) = __floats2half2_rn(b.x, b.y);
    *(__half2*)(dst + di + 6) = __floats2half2_rn(b.z, b.w);
}

__global__ void bpack_kernel(const float* __restrict__ bk, const float* __restrict__ bv)
{
    int i = blockIdx.x * blockDim.x + threadIdx.x;
    if (i >= E_ * 2 * D_) return;
    int e = i / (2 * D_);
    int r = i - e * 2 * D_;
    int w = r / D_;
    int d = r - w * D_;
    g_bkv[i] = (w == 0 ? bk : bv)[e * D_ + d];
}

// --------------------------- fp16 tensor GEMM --------------------------------
// C = A[.,K] @ B[K][N] + bias (relu). A fp16 K-major (a-frags via
// ldmatrix.x4); B fp16 untransposed [K][N] (b-frags via ldmatrix.x2.trans).
// BM=BN=128, BK=32, 256 thr, 8 warps of 64x32. 3-stage cp.async pipeline.
#define HAPAD 40
#define BSTR  136
#define HGEMM_SMEM (3 * (128 * HAPAD + 32 * BSTR) * 2)

template <bool RELU>
__global__ __launch_bounds__(256, 2) void hgemm(
    const __half* __restrict__ A, const __half* __restrict__ Bp,
    __half* __restrict__ Ch, float* __restrict__ Cf,
    const float* __restrict__ bias,
    int K, int lda, int ldb, int ldc,
    int div1,
    long long sA0, long long sA1,
    long long sB0, long long sB1,
    long long sC0, long long sC1,
    long long sb0, long long sb1,
    const int* __restrict__ mlim, const int* __restrict__ gidx)
{
    const int z  = blockIdx.z;
    const int bm = blockIdx.y * 128;
    if (mlim && bm >= mlim[z]) return;
    const int z0 = z / div1, z1 = z - z0 * div1;
    A  += z0 * sA0 + z1 * sA1;
    Bp += z0 * sB0 + z1 * sB1;
    const long long coff = z0 * sC0 + z1 * sC1;
    const float* biasp = bias + z0 * sb0 + z1 * sb1;

    extern __shared__ __half hsm[];
    __half* As = hsm;                        // [3][128*HAPAD]
    __half* Bs = hsm + 3 * 128 * HAPAD;      // [3][32*BSTR]

    const int tid  = threadIdx.x;
    const int lane = tid & 31;
    const int wid  = tid >> 5;
    const int warpM = (wid >> 2) * 64;
    const int warpN = (wid & 3) * 32;
    const int bn = blockIdx.x * 128;

    // A staging: 2 x 16B per thread
    const int srow = tid >> 1;
    const int sch  = (tid & 1) * 16;
    long long arow = bm + srow;
    if (gidx) arow = gidx[(long long)z * S_ + arow];
    const __half* gA = A + arow * lda + sch;
    uint32_t sA = (uint32_t)__cvta_generic_to_shared(As + srow * HAPAD + sch);

    // B staging: rows = K, cols = 128 @ bn
    const int brow = tid >> 4;
    const int bc16 = (tid & 15) * 8;
    const __half* gB = Bp + (long long)brow * ldb + bn + bc16;
    uint32_t sB = (uint32_t)__cvta_generic_to_shared(Bs + brow * BSTR + bc16);

    const uint32_t stgA = 128 * HAPAD * 2;
    const uint32_t stgB = 32 * BSTR * 2;
    const long long ldb16 = 16LL * ldb;

    float acc[4][4][4];
#pragma unroll
    for (int i = 0; i < 4; i++)
#pragma unroll
        for (int j = 0; j < 4; j++)
#pragma unroll
            for (int q = 0; q < 4; q++) acc[i][j][q] = 0.f;

    cp_async16(sA,      gA);
    cp_async16(sA + 16, gA + 8);
    cp_async16(sB,                 gB);
    cp_async16(sB + 16 * BSTR * 2, gB + ldb16);
    cp_commit();
    cp_async16(sA + stgA,      gA + 32);
    cp_async16(sA + stgA + 16, gA + 40);
    cp_async16(sB + stgB,                 gB + 2 * ldb16);
    cp_async16(sB + stgB + 16 * BSTR * 2, gB + 3 * ldb16);
    cp_commit();

    const int qq2 = (lane & 3) * 2;
    // ldmatrix.x4 a-frag source lane mapping
    const int aRow = warpM + (lane & 15);
    const int aCol = (lane >> 4) << 3;

    int it = 0;
    for (int k0 = 0; k0 < K; k0 += 32, it++) {
        const int st = it % 3;
        cp_wait1();
        __syncthreads();

        if (k0 + 64 < K) {
            const int sp = (it + 2) % 3;
            const __half* gA2 = gA + k0 + 64;
            const __half* gB2 = gB + (long long)(k0 + 64) * ldb;
            cp_async16(sA + sp * stgA,      gA2);
            cp_async16(sA + sp * stgA + 16, gA2 + 8);
            cp_async16(sB + sp * stgB,                 gB2);
            cp_async16(sB + sp * stgB + 16 * BSTR * 2, gB2 + ldb16);
        }
        cp_commit();

        const __half* As0 = As + st * 128 * HAPAD;
        const __half* Bs0 = Bs + st * 32 * BSTR;
        uint32_t aBase = (uint32_t)__cvta_generic_to_shared(As0 + aRow * HAPAD + aCol);

#pragma unroll
        for (int ks = 0; ks < 2; ks++) {
            const int kb = ks * 16;
            unsigned af[4][4], bf[4][2];
#pragma unroll
            for (int mi = 0; mi < 4; mi++) {
                asm volatile(
                    "ldmatrix.sync.aligned.m8n8.x4.shared.b16 {%0,%1,%2,%3}, [%4];\n"
                    : "=r"(af[mi][0]), "=r"(af[mi][1]), "=r"(af[mi][2]), "=r"(af[mi][3])
                    : "r"(aBase + (mi * 16 * HAPAD + kb) * 2));
            }
            uint32_t bbase = (uint32_t)__cvta_generic_to_shared(
                Bs0 + (kb + (lane & 15)) * BSTR + warpN);
#pragma unroll
            for (int ni = 0; ni < 4; ni++) {
                asm volatile(
                    "ldmatrix.sync.aligned.m8n8.x2.trans.shared.b16 {%0,%1}, [%2];\n"
                    : "=r"(bf[ni][0]), "=r"(bf[ni][1]) : "r"(bbase + ni * 16));
            }
#pragma unroll
            for (int mi = 0; mi < 4; mi++)
#pragma unroll
                for (int ni = 0; ni < 4; ni++)
                    mma_f16(acc[mi][ni], af[mi][0], af[mi][1], af[mi][2], af[mi][3],
                            bf[ni][0], bf[ni][1]);
        }
    }

    // epilogue
#pragma unroll
    for (int mi = 0; mi < 4; mi++) {
        long long row0 = bm + warpM + mi * 16 + (lane >> 2);
#pragma unroll
        for (int ni = 0; ni < 4; ni++) {
            int col = bn + warpN + ni * 8 + qq2;
            float b0 = biasp[col], b1 = biasp[col + 1];
            float v0 = acc[mi][ni][0] + b0;
            float v1 = acc[mi][ni][1] + b1;
            float v2 = acc[mi][ni][2] + b0;
            float v3 = acc[mi][ni][3] + b1;
            if (RELU) {
                v0 = fmaxf(v0, 0.f); v1 = fmaxf(v1, 0.f);
                v2 = fmaxf(v2, 0.f); v3 = fmaxf(v3, 0.f);
            }
            if (Ch) {
                *(__half2*)(Ch + coff + row0 * ldc + col)       = __floats2half2_rn(v0, v1);
                *(__half2*)(Ch + coff + (row0 + 8) * ldc + col) = __floats2half2_rn(v2, v3);
            }
            if (Cf) {
                *(float2*)(Cf + coff + row0 * ldc + col)       = make_float2(v0, v1);
                *(float2*)(Cf + coff + (row0 + 8) * ldc + col) = make_float2(v2, v3);
            }
        }
    }
}

// ------------------------- fused flash attention (fp16) ----------------------
#define BC_   64
#define FSTR  136
#define FLASH_SMEM ((128 * FSTR + 2 * BC_ * FSTR + 2 * BC_ * FSTR) * 2)

__global__ __launch_bounds__(256, 2) void flash_kernel(const __half* __restrict__ qh,
                                                       const __half* __restrict__ kvh,
                                                       const int* __restrict__ cnt,
                                                       __half* __restrict__ ogh)
{
    const int qt  = blockIdx.x;
    const int seg = blockIdx.y >> 2;
    const int h   = blockIdx.y & 3;
    if (qt * 128 >= cnt[seg]) return;
    const int e = seg >> 2;
    const int b = seg & 3;

    extern __shared__ __half fsm[];
    __half* Qs = fsm;
    __half* Ks = fsm + 128 * FSTR;
    __half* Vs = Ks + 2 * BC_ * FSTR;

    const int tid  = threadIdx.x;
    const int lane = tid & 31;
    const int wid  = tid >> 5;
    const float scale = 0.08838834764831845f;

    const __half* qbase = qh + (long long)seg * SD_ + (long long)(qt * 128) * D_ + h * DH_;
    const __half* kbase = kvh + (long long)e * 2 * ND_ + (long long)(b * S_) * D_ + h * DH_;
    const __half* vbase = kbase + ND_;

    {
        int r = tid >> 1, c0 = (tid & 1) * 64;
        const __half* g = qbase + (long long)r * D_ + c0;
        uint32_t s = (uint32_t)__cvta_generic_to_shared(Qs + r * FSTR + c0);
#pragma unroll
        for (int j = 0; j < 8; j++) cp_async16(s + j * 16, g + j * 8);
    }
    {
        int r = tid >> 2, c0 = (tid & 3) * 32;
        const __half* gk = kbase + (long long)r * D_ + c0;
        const __half* gv = vbase + (long long)r * D_ + c0;
        uint32_t sk = (uint32_t)__cvta_generic_to_shared(Ks + r * FSTR + c0);
        uint32_t sv = (uint32_t)__cvta_generic_to_shared(Vs + r * FSTR + c0);
#pragma unroll
        for (int j = 0; j < 4; j++) {
            cp_async16(sk + j * 16, gk + j * 8);
            cp_async16(sv + j * 16, gv + j * 8);
        }
    }
    cp_commit();

    const int r0  = lane >> 2;
    const int qq2 = (lane & 3) * 2;
    const int wrow = wid * 16;

    float oacc[16][4];
#pragma unroll
    for (int i = 0; i < 16; i++)
#pragma unroll
        for (int j = 0; j < 4; j++) oacc[i][j] = 0.f;
    float m0 = -1e30f, m1 = -1e30f, l0 = 0.f, l1 = 0.f;

    // ldmatrix lane mappings
    const int qRow = wrow + (lane & 15);
    const int qCol = (lane >> 4) << 3;
    const int kRow = lane & 7;
    const int kCol = ((lane >> 3) & 1) << 3;

    for (int t = 0; t < 16; t++) {
        const int st = t & 1;
        cp_wait0();
        __syncthreads();

        if (t < 15) {
            int r = tid >> 2, c0 = (tid & 3) * 32;
            int st2 = st ^ 1;
            const __half* gk = kbase + (long long)((t + 1) * BC_ + r) * D_ + c0;
            const __half* gv = vbase + (long long)((t + 1) * BC_ + r) * D_ + c0;
            uint32_t sk = (uint32_t)__cvta_generic_to_shared(Ks + st2 * BC_ * FSTR + r * FSTR + c0);
            uint32_t sv = (uint32_t)__cvta_generic_to_shared(Vs + st2 * BC_ * FSTR + r * FSTR + c0);
#pragma unroll
            for (int j = 0; j < 4; j++) {
                cp_async16(sk + j * 16, gk + j * 8);
                cp_async16(sv + j * 16, gv + j * 8);
            }
            cp_commit();
        }

        float sacc[8][4];
#pragma unroll
        for (int i = 0; i < 8; i++)
#pragma unroll
            for (int j = 0; j < 4; j++) sacc[i][j] = 0.f;

        const __half* Kt = Ks + st * BC_ * FSTR;
        uint32_t qaddr = (uint32_t)__cvta_generic_to_shared(Qs + qRow * FSTR + qCol);
        uint32_t kaddr = (uint32_t)__cvta_generic_to_shared(Kt + kRow * FSTR + kCol);
#pragma unroll
        for (int ks = 0; ks < 8; ks++) {
            const int kbB = ks * 16 * 2;   // byte offset
            unsigned a0, a1, a2, a3;
            asm volatile(
                "ldmatrix.sync.aligned.m8n8.x4.shared.b16 {%0,%1,%2,%3}, [%4];\n"
                : "=r"(a0), "=r"(a1), "=r"(a2), "=r"(a3)
                : "r"(qaddr + kbB));
#pragma unroll
            for (int ni = 0; ni < 8; ni++) {
                unsigned b0, b1;
                asm volatile(
                    "ldmatrix.sync.aligned.m8n8.x2.shared.b16 {%0,%1}, [%2];\n"
                    : "=r"(b0), "=r"(b1)
                    : "r"(kaddr + kbB + ni * 8 * FSTR * 2));
                mma_f16(sacc[ni], a0, a1, a2, a3, b0, b1);
            }
        }

        float rmax0 = -1e30f, rmax1 = -1e30f;
#pragma unroll
        for (int ni = 0; ni < 8; ni++) {
            sacc[ni][0] *= scale; sacc[ni][1] *= scale;
            sacc[ni][2] *= scale; sacc[ni][3] *= scale;
            rmax0 = fmaxf(rmax0, fmaxf(sacc[ni][0], sacc[ni][1]));
            rmax1 = fmaxf(rmax1, fmaxf(sacc[ni][2], sacc[ni][3]));
        }
        rmax0 = fmaxf(rmax0, __shfl_xor_sync(0xffffffffu, rmax0, 1));
        rmax0 = fmaxf(rmax0, __shfl_xor_sync(0xffffffffu, rmax0, 2));
        rmax1 = fmaxf(rmax1, __shfl_xor_sync(0xffffffffu, rmax1, 1));
        rmax1 = fmaxf(rmax1, __shfl_xor_sync(0xffffffffu, rmax1, 2));
        float mn0 = fmaxf(m0, rmax0), mn1 = fmaxf(m1, rmax1);
        float c0 = __expf(m0 - mn0), c1 = __expf(m1 - mn1);
        m0 = mn0; m1 = mn1;
        float rs0 = 0.f, rs1 = 0.f;
#pragma unroll
        for (int ni = 0; ni < 8; ni++) {
            sacc[ni][0] = __expf(sacc[ni][0] - m0);
            sacc[ni][1] = __expf(sacc[ni][1] - m0);
            sacc[ni][2] = __expf(sacc[ni][2] - m1);
            sacc[ni][3] = __expf(sacc[ni][3] - m1);
            rs0 += sacc[ni][0] + sacc[ni][1];
            rs1 += sacc[ni][2] + sacc[ni][3];
        }
        rs0 += __shfl_xor_sync(0xffffffffu, rs0, 1);
        rs0 += __shfl_xor_sync(0xffffffffu, rs0, 2);
        rs1 += __shfl_xor_sync(0xffffffffu, rs1, 1);
        rs1 += __shfl_xor_sync(0xffffffffu, rs1, 2);
        l0 = l0 * c0 + rs0;
        l1 = l1 * c1 + rs1;
#pragma unroll
        for (int ni = 0; ni < 16; ni++) {
            oacc[ni][0] *= c0; oacc[ni][1] *= c0;
            oacc[ni][2] *= c1; oacc[ni][3] *= c1;
        }

        const __half* Vt = Vs + st * BC_ * FSTR;
#pragma unroll
        for (int ks = 0; ks < 4; ks++) {
            unsigned a0 = h2pack(sacc[2 * ks][0],     sacc[2 * ks][1]);
            unsigned a1 = h2pack(sacc[2 * ks][2],     sacc[2 * ks][3]);
            unsigned a2 = h2pack(sacc[2 * ks + 1][0], sacc[2 * ks + 1][1]);
            unsigned a3 = h2pack(sacc[2 * ks + 1][2], sacc[2 * ks + 1][3]);
            uint32_t vrow = (uint32_t)__cvta_generic_to_shared(
                Vt + (16 * ks + (lane & 15)) * FSTR);
#pragma unroll
            for (int ni = 0; ni < 16; ni++) {
                unsigned b0, b1;
                asm volatile(
                    "ldmatrix.sync.aligned.m8n8.x2.trans.shared.b16 {%0,%1}, [%2];\n"
                    : "=r"(b0), "=r"(b1) : "r"(vrow + ni * 16));
                mma_f16(oacc[ni], a0, a1, a2, a3, b0, b1);
            }
        }
    }

    float inv0 = 1.f / l0, inv1 = 1.f / l1;
    long long row0 = (long long)(qt * 128 + wrow + r0);
    __half* ob = ogh + (long long)seg * SD_ + row0 * D_ + h * DH_;
#pragma unroll
    for (int ni = 0; ni < 16; ni++) {
        int col = ni * 8 + qq2;
        *(__half2*)(ob + col)            = __floats2half2_rn(oacc[ni][0] * inv0, oacc[ni][1] * inv0);
        *(__half2*)(ob + 8LL * D_ + col) = __floats2half2_rn(oacc[ni][2] * inv1, oacc[ni][3] * inv1);
    }
}

// --------------------------- LayerNorm kernels ------------------------------
__global__ void ln1g_kernel(const float* __restrict__ x, const float* __restrict__ t1,
                            const int* __restrict__ idx, const int* __restrict__ cnt,
                            const float* __restrict__ s_all, const float* __restrict__ b_all,
                            float* __restrict__ hg, __half* __restrict__ hgh)
{
    int i   = blockIdx.x;
    int seg = blockIdx.y;
    if (i >= cnt[seg]) return;
    int e = seg >> 2;
    int token = idx[seg * S_ + i];
    const float* a    = x  + (size_t)token * D_;
    const float* bsrc = t1 + ((size_t)seg * S_ + i) * D_;
    const float* s    = s_all + (size_t)e * D_;
    const float* bb   = b_all + (size_t)e * D_;
    float*  outf = hg  + ((size_t)seg * S_ + i) * D_;
    __half* outh = hgh + ((size_t)seg * S_ + i) * D_;
    int t = threadIdx.x;
    __shared__ float red4[4];
    float v[4];
#pragma unroll
    for (int q = 0; q < 4; q++) {
        int d = t + q * 128;
        v[q] = a[d] + bsrc[d];
    }
    float mu = blocksum128(v[0] + v[1] + v[2] + v[3], red4, t) * (1.f / D_);
    float sq = 0.f;
#pragma unroll
    for (int q = 0; q < 4; q++) { float d2 = v[q] - mu; sq += d2 * d2; }
    float inv = rsqrtf(blocksum128(sq, red4, t) * (1.f / D_) + LN_EPS);
#pragma unroll
    for (int q = 0; q < 4; q++) {
        int d = t + q * 128;
        float y = (v[q] - mu) * inv * s[d] + bb[d];
        outf[d] = y;
        outh[d] = __float2half_rn(y);
    }
}

__global__ void ln2_scatter_kernel(const float* __restrict__ hg, const float* __restrict__ f2g,
                                   const float* __restrict__ s_all, const float* __restrict__ b_all,
                                   const float* __restrict__ rw, const int* __restrict__ pos,
                                   float* __restrict__ finalOut)
{
    int n = blockIdx.x;
    int t = threadIdx.x;
    int b = n >> 10;
    __shared__ float red4[4];
    float outv[4] = {0.f, 0.f, 0.f, 0.f};
    for (int e = 0; e < E_; e++) {
        float w = rw[n * E_ + e];
        if (w == 0.f) continue;            // uniform across block
        int seg = e * B_ + b;
        int p = pos[n * E_ + e];
        const float* hp = hg  + ((size_t)seg * S_ + p) * D_;
        const float* fp = f2g + ((size_t)seg * S_ + p) * D_;
        const float* s  = s_all + (size_t)e * D_;
        const float* bb = b_all + (size_t)e * D_;
        float v[4];
#pragma unroll
        for (int q = 0; q < 4; q++) {
            int d = t + q * 128;
            v[q] = hp[d] + fp[d];
        }
        float mu = blocksum128(v[0] + v[1] + v[2] + v[3], red4, t) * (1.f / D_);
        float sq = 0.f;
#pragma unroll
        for (int q = 0; q < 4; q++) { float d2 = v[q] - mu; sq += d2 * d2; }
        float inv = rsqrtf(blocksum128(sq, red4, t) * (1.f / D_) + LN_EPS);
#pragma unroll
        for (int q = 0; q < 4; q++) {
            int d = t + q * 128;
            outv[q] += w * ((v[q] - mu) * inv * s[d] + bb[d]);
        }
    }
#pragma unroll
    for (int q = 0; q < 4; q++)
        finalOut[(size_t)n * D_ + t + q * 128] = outv[q];
}

// ------------------------------ host glue -----------------------------------
extern "C" void kernel_launch(void* const* d_in, const int* in_sizes, int n_in,
                              void* d_out, int out_size)
{
    const float* x      = (const float*)d_in[0];
    const float* gate_w = (const float*)d_in[1];
    const float* gate_b = (const float*)d_in[2];
    const float* ln1_s  = (const float*)d_in[3];
    const float* ln1_b  = (const float*)d_in[4];
    const float* ln2_s  = (const float*)d_in[5];
    const float* ln2_b  = (const float*)d_in[6];
    const float* wq     = (const float*)d_in[7];
    const float* wk     = (const float*)d_in[8];
    const float* wv     = (const float*)d_in[9];
    const float* wo     = (const float*)d_in[10];
    const float* bq     = (const float*)d_in[11];
    const float* bk     = (const float*)d_in[12];
    const float* bv     = (const float*)d_in[13];
    const float* bo     = (const float*)d_in[14];
    const float* w1     = (const float*)d_in[15];
    const float* b1     = (const float*)d_in[16];
    const float* w2     = (const float*)d_in[17];
    const float* b2     = (const float*)d_in[18];

    float* out_final  = (float*)d_out;
    float* out_logits = out_final + (size_t)N_ * D_;

    float *rw, *t1, *hg, *f2, *bkv;
    int *cnt, *idx, *pos;
    __half *xh, *wqh, *wkvh, *woh, *w1h, *w2h, *kvh, *qh, *ogh, *hgh, *f1h;
    cudaGetSymbolAddress((void**)&rw,   g_rw);
    cudaGetSymbolAddress((void**)&cnt,  g_cnt);
    cudaGetSymbolAddress((void**)&idx,  g_idx);
    cudaGetSymbolAddress((void**)&pos,  g_pos);
    cudaGetSymbolAddress((void**)&bkv,  g_bkv);
    cudaGetSymbolAddress((void**)&xh,   g_xh);
    cudaGetSymbolAddress((void**)&wqh,  g_wqh);
    cudaGetSymbolAddress((void**)&wkvh, g_wkvh);
    cudaGetSymbolAddress((void**)&woh,  g_woh);
    cudaGetSymbolAddress((void**)&w1h,  g_w1h);
    cudaGetSymbolAddress((void**)&w2h,  g_w2h);
    cudaGetSymbolAddress((void**)&kvh,  g_kvh);
    cudaGetSymbolAddress((void**)&qh,   g_qh);
    cudaGetSymbolAddress((void**)&ogh,  g_ogh);
    cudaGetSymbolAddress((void**)&hgh,  g_hgh);
    cudaGetSymbolAddress((void**)&f1h,  g_f1h);
    cudaGetSymbolAddress((void**)&t1,   g_t1);
    cudaGetSymbolAddress((void**)&hg,   g_hg);
    cudaGetSymbolAddress((void**)&f2,   g_f2);

    cudaFuncSetAttribute(flash_kernel,
                         cudaFuncAttributeMaxDynamicSharedMemorySize, FLASH_SMEM);
    cudaFuncSetAttribute(hgemm<false>,
                         cudaFuncAttributeMaxDynamicSharedMemorySize, HGEMM_SMEM);
    cudaFuncSetAttribute(hgemm<true>,
                         cudaFuncAttributeMaxDynamicSharedMemorySize, HGEMM_SMEM);

    cudaMemsetAsync(cnt, 0, SEGS * sizeof(int));
    cudaMemsetAsync(idx, 0, SEGS * S_ * sizeof(int));

    router_kernel<<<N_ / 8, 256>>>(x, gate_w, gate_b, out_logits, rw);
    build_lists_kernel<<<N_ / 256, 256>>>(rw);

    // one-shot conversion of x + all weights
    convall_kernel<<<(int)(UTOT_ / 256), 256>>>(x, wq, wk, wv, wo, w1, w2);
    bpack_kernel<<<(E_ * 2 * D_ + 255) / 256, 256>>>(bk, bv);

    // K+V projections merged (dense): z = e*2 + {k,v}
    {
        dim3 grid(D_ / 128, N_ / 128, E_ * 2);
        hgemm<false><<<grid, 256, HGEMM_SMEM>>>(
            xh, wkvh, kvh, nullptr, bkv,
            D_, D_, D_, D_,
            2,
            0, 0,
            2LL * DD_, DD_,
            2 * ND_, ND_,
            2LL * D_, D_,
            nullptr, nullptr);
    }
    // Q projection (gathered): z = seg
    {
        dim3 grid(D_ / 128, S_ / 128, SEGS);
        hgemm<false><<<grid, 256, HGEMM_SMEM>>>(
            xh, wqh, qh, nullptr, bq,
            D_, D_, D_, D_,
            B_,
            0, 0,
            DD_, 0,
            (long long)B_ * SD_, SD_,
            D_, 0,
            cnt, idx);
    }

    // fused attention
    {
        dim3 grid(S_ / 128, SEGS * H_);
        flash_kernel<<<grid, 256, FLASH_SMEM>>>(qh, kvh, cnt, ogh);
    }

    // O projection -> t1 (fp32): z = seg
    {
        dim3 grid(D_ / 128, S_ / 128, SEGS);
        hgemm<false><<<grid, 256, HGEMM_SMEM>>>(
            ogh, woh, nullptr, t1, bo,
            D_, D_, D_, D_,
            B_,
            (long long)B_ * SD_, SD_,
            DD_, 0,
            (long long)B_ * SD_, SD_,
            D_, 0,
            cnt, nullptr);
    }

    // LN1 -> hg (fp32) + hgh (fp16)
    {
        dim3 grid(S_, SEGS);
        ln1g_kernel<<<grid, 128>>>(x, t1, idx, cnt, ln1_s, ln1_b, hg, hgh);
    }

    // FFN1 -> f1h (relu): z = seg
    {
        dim3 grid(F_ / 128, S_ / 128, SEGS);
        hgemm<true><<<grid, 256, HGEMM_SMEM>>>(
            hgh, w1h, f1h, nullptr, b1,
            D_, D_, F_, F_,
            B_,
            (long long)B_ * SD_, SD_,
            (long long)D_ * F_, 0,
            (long long)B_ * SF_, SF_,
            F_, 0,
            cnt, nullptr);
    }

    // FFN2 -> f2 (fp32): z = seg
    {
        dim3 grid(D_ / 128, S_ / 128, SEGS);
        hgemm<false><<<grid, 256, HGEMM_SMEM>>>(
            f1h, w2h, nullptr, f2, b2,
            F_, F_, D_, D_,
            B_,
            (long long)B_ * SF_, SF_,
            (long long)F_ * D_, 0,
            (long long)B_ * SD_, SD_,
            D_, 0,
            cnt, nullptr);
    }

    // final = sum_e rw * LN2(hg + f2)
    ln2_scatter_kernel<<<N_, 128>>>(hg, f2, ln2_s, ln2_b, rw, pos, out_final);
}